// round 6
// baseline (speedup 1.0000x reference)
#include <cuda_runtime.h>

#define NN 10000
#define EE 320000
#define NG_ 16

// ---------------- scratch (static device memory; no allocations) ----------------
__device__ float  g_s[NN*64];
__device__ float4 g_v4[NN*32];
__device__ float  g_scs[NN*64];
__device__ float  g_scv[NN*96];
__device__ float  g_accs[NN*64];
__device__ float4 g_accv4[NN*32];            // (x,y,z,pad) per lane
__device__ float  g_ns[NN*64];
__device__ float  g_nv[NN*96];
__device__ float  g_wmlp[(long long)EE*96];
__device__ float  g_P[NN*128];               // s@F1[0:64]   (i-role), lane*4 layout
__device__ float  g_Q[NN*128];               // s@F1[64:128] (j-role)
__device__ float  g_T[NN*384];               // v x F2[0:32]  (i-role), lane*12 layout
__device__ float  g_U[NN*384];               // v x F2[32:64] (j-role)
__device__ float  g_gstat[4*NG_];
__device__ float  g_gout[3*NG_];

__device__ __forceinline__ float sig_(float x){ return 1.f/(1.f+__expf(-x)); }

// ---- f32x2 packed math helpers (sm_103a FFMA2 via PTX) ----
__device__ __forceinline__ unsigned long long pk2(float x){
  unsigned long long r; asm("mov.b64 %0, {%1, %1};" : "=l"(r) : "f"(x)); return r; }
__device__ __forceinline__ unsigned long long pkab(float a, float b){
  unsigned long long r; asm("mov.b64 %0, {%1, %2};" : "=l"(r) : "f"(a), "f"(b)); return r; }
__device__ __forceinline__ void up2(unsigned long long v, float &a, float &b){
  asm("mov.b64 {%0, %1}, %2;" : "=f"(a), "=f"(b) : "l"(v)); }
__device__ __forceinline__ void fma2(unsigned long long &d, unsigned long long a, unsigned long long b){
  asm("fma.rn.f32x2 %0, %1, %2, %3;" : "=l"(d) : "l"(a), "l"(b), "l"(d)); }

// ---------------- zero accumulators ----------------
__global__ void k_zero(){
  int i = blockIdx.x*blockDim.x + threadIdx.x;
  if (i < NN*64) g_accs[i] = 0.f;
  int j = i - NN*64;
  if (j >= 0 && j < NN*128) ((float*)g_accv4)[j] = 0.f;
  int k = i - NN*192;
  if (k >= 0 && k < 4*NG_) g_gstat[k] = 0.f;
}

// ---------------- node pre ----------------
__global__ void __launch_bounds__(512) k_node_pre(const float* __restrict__ nf,
                           const float* __restrict__ oh,
                           const float* __restrict__ lpWs, const float* __restrict__ lpbs,
                           const float* __restrict__ lpWv,
                           const float* __restrict__ scWs, const float* __restrict__ scWv){
  extern __shared__ float sm[];
  float2* WsS  = (float2*)sm;
  float*  WvS  = sm + 4096;
  float2* sWsS = (float2*)(sm + 5120);
  float*  sWvS = sm + 21504;
  float*  bsS  = sm + 25600;
  float*  stage= sm + 25664;

  for (int i=threadIdx.x;i<4096;i+=blockDim.x) sm[i]=lpWs[i];
  for (int i=threadIdx.x;i<1024;i+=blockDim.x) WvS[i]=lpWv[i];
  for (int i=threadIdx.x;i<16384;i+=blockDim.x) sm[5120+i]=scWs[i];
  for (int i=threadIdx.x;i<4096;i+=blockDim.x) sWvS[i]=scWv[i];
  for (int i=threadIdx.x;i<64;i+=blockDim.x) bsS[i]=lpbs[i];
  __syncthreads();

  int warp = threadIdx.x>>5, lane = threadIdx.x&31, wpb = blockDim.x>>5;
  float*  sS  = stage + warp*192;
  float4* vS  = (float4*)(sS + 64);

  for (int n = blockIdx.x*wpb + warp; n < NN; n += gridDim.x*wpb){
    const float* row = nf + n*160;
    sS[lane] = row[lane]; sS[32+lane] = row[32+lane];
    vS[lane] = make_float4(row[64+3*lane], row[65+3*lane], row[66+3*lane], 0.f);
    const float* o4 = oh + n*4;
    int sp = (o4[1]>0.5f)?1:((o4[2]>0.5f)?2:((o4[3]>0.5f)?3:0));
    __syncwarp();

    float a0=0.f,a1=0.f,c0=0.f,c1=0.f;
    #pragma unroll 4
    for (int u=0;u<64;u++){
      float x = sS[u];
      float2 w  = WsS[u*32+lane];
      float2 w2 = sWsS[(u*4+sp)*32+lane];
      a0+=x*w.x; a1+=x*w.y; c0+=x*w2.x; c1+=x*w2.y;
    }
    g_s[n*64+2*lane]   = a0*0.125f + bsS[2*lane];
    g_s[n*64+2*lane+1] = a1*0.125f + bsS[2*lane+1];
    g_scs[n*64+2*lane]   = c0*0.0625f;
    g_scs[n*64+2*lane+1] = c1*0.0625f;

    float vx=0.f,vy=0.f,vz=0.f,cx=0.f,cy=0.f,cz=0.f;
    #pragma unroll 4
    for (int u=0;u<32;u++){
      float4 x = vS[u];
      float w  = WvS[u*32+lane];
      float w2 = sWvS[(u*4+sp)*32+lane];
      vx+=x.x*w;  vy+=x.y*w;  vz+=x.z*w;
      cx+=x.x*w2; cy+=x.y*w2; cz+=x.z*w2;
    }
    g_v4[n*32+lane] = make_float4(vx*0.17677670f, vy*0.17677670f, vz*0.17677670f, 0.f);
    g_scv[n*96+3*lane]   = cx*0.08838835f;
    g_scv[n*96+3*lane+1] = cy*0.08838835f;
    g_scv[n*96+3*lane+2] = cz*0.08838835f;
    __syncwarp();
  }
}

// ---------------- per-node P/Q (phase 1) and T/U (phase 2), merged ----------------
__global__ void __launch_bounds__(512) k_pstv(const float* __restrict__ Wss0,
   const float* __restrict__ Wssg, const float* __restrict__ Wsv1,
   const float* __restrict__ Wvv0, const float* __restrict__ Wvvg,
   const float* __restrict__ Wvs1){
  extern __shared__ float sm[];
  float4* FA = (float4*)sm;            // F1 rows 0..63:  64x32 f4
  float4* FB = (float4*)(sm+8192);     // F1 rows 64..127
  float4* GA = (float4*)(sm+16384);    // F2 rows 0..31
  float4* GB = (float4*)(sm+20480);    // F2 rows 32..63
  float* stage = sm + 24576;           // per warp 1024 f

  for (int i=threadIdx.x;i<2048;i+=blockDim.x){
    int u=i>>5, l=i&31;
    FA[i]=make_float4(Wss0[u*64+2*l], Wss0[u*64+2*l+1], Wssg[u*32+l], Wsv1[u*32+l]);
    int u2=u+64;
    FB[i]=make_float4(Wss0[u2*64+2*l], Wss0[u2*64+2*l+1], Wssg[u2*32+l], Wsv1[u2*32+l]);
  }
  for (int i=threadIdx.x;i<1024;i+=blockDim.x){
    int u=i>>5, l=i&31;
    GA[i]=make_float4(Wvv0[u*64+2*l], Wvv0[u*64+2*l+1], Wvvg[u*32+l], Wvs1[u*32+l]);
    int u2=u+32;
    GB[i]=make_float4(Wvv0[u2*64+2*l], Wvv0[u2*64+2*l+1], Wvvg[u2*32+l], Wvs1[u2*32+l]);
  }
  __syncthreads();

  int warp=threadIdx.x>>5, lane=threadIdx.x&31, wpb=blockDim.x>>5;
  float* sd = stage + warp*1024;

  // ---- phase 1: P/Q, 8 nodes/warp ----
  const int b1 = NN/8;
  for (int p = blockIdx.x*wpb+warp; p<b1; p+=gridDim.x*wpb){
    int n0 = p*8;
    #pragma unroll
    for (int k=0;k<8;k++){
      int n = n0+k;
      float x0 = g_s[n*64+lane];
      float x1 = g_s[n*64+32+lane];
      *(unsigned long long*)(sd + k*128 + 2*lane)      = pkab(x0,x0);
      *(unsigned long long*)(sd + k*128 + 64 + 2*lane) = pkab(x1,x1);
    }
    __syncwarp();

    unsigned long long pa[8], pg[8], qa[8], qg[8];
    #pragma unroll
    for (int k=0;k<8;k++){ pa[k]=0ull; pg[k]=0ull; qa[k]=0ull; qg[k]=0ull; }
    #pragma unroll 2
    for (int u=0;u<64;u+=2){
      ulonglong2 wa0 = *(ulonglong2*)&FA[(u  )*32+lane];
      ulonglong2 wa1 = *(ulonglong2*)&FA[(u+1)*32+lane];
      ulonglong2 wb0 = *(ulonglong2*)&FB[(u  )*32+lane];
      ulonglong2 wb1 = *(ulonglong2*)&FB[(u+1)*32+lane];
      #pragma unroll
      for (int k=0;k<8;k++){
        ulonglong2 xp = *(ulonglong2*)(sd + k*128 + 2*u);
        fma2(pa[k], xp.x, wa0.x); fma2(pg[k], xp.x, wa0.y);
        fma2(qa[k], xp.x, wb0.x); fma2(qg[k], xp.x, wb0.y);
        fma2(pa[k], xp.y, wa1.x); fma2(pg[k], xp.y, wa1.y);
        fma2(qa[k], xp.y, wb1.x); fma2(qg[k], xp.y, wb1.y);
      }
    }
    #pragma unroll
    for (int k=0;k<8;k++){
      int n = n0+k;
      float a0,a1,ag,at;
      up2(pa[k],a0,a1); up2(pg[k],ag,at);
      *(float4*)(g_P + n*128 + lane*4) = make_float4(a0,a1,ag,at);
      up2(qa[k],a0,a1); up2(qg[k],ag,at);
      *(float4*)(g_Q + n*128 + lane*4) = make_float4(a0,a1,ag,at);
    }
    __syncwarp();
  }

  // ---- phase 2: T/U, 4 nodes/warp ----
  float4* vst = (float4*)sd;
  const int b2 = NN/4;
  for (int p = blockIdx.x*wpb+warp; p<b2; p+=gridDim.x*wpb){
    int n0 = p*4;
    #pragma unroll
    for (int k=0;k<4;k++) vst[k*32+lane] = g_v4[(n0+k)*32+lane];
    __syncwarp();

    unsigned long long t01[4][3], tgr[4][3], u01[4][3], ugr[4][3];
    #pragma unroll
    for (int k=0;k<4;k++)
      #pragma unroll
      for (int c=0;c<3;c++){ t01[k][c]=0ull; tgr[k][c]=0ull; u01[k][c]=0ull; ugr[k][c]=0ull; }

    #pragma unroll 2
    for (int u=0;u<32;u++){
      ulonglong2 ga = *(ulonglong2*)&GA[u*32+lane];
      ulonglong2 gb = *(ulonglong2*)&GB[u*32+lane];
      #pragma unroll
      for (int k=0;k<4;k++){
        float4 v = vst[k*32+u];
        unsigned long long vx=pk2(v.x), vy=pk2(v.y), vz=pk2(v.z);
        fma2(t01[k][0], vx, ga.x); fma2(t01[k][1], vy, ga.x); fma2(t01[k][2], vz, ga.x);
        fma2(tgr[k][0], vx, ga.y); fma2(tgr[k][1], vy, ga.y); fma2(tgr[k][2], vz, ga.y);
        fma2(u01[k][0], vx, gb.x); fma2(u01[k][1], vy, gb.x); fma2(u01[k][2], vz, gb.x);
        fma2(ugr[k][0], vx, gb.y); fma2(ugr[k][1], vy, gb.y); fma2(ugr[k][2], vz, gb.y);
      }
    }
    #pragma unroll
    for (int k=0;k<4;k++){
      int n = n0+k;
      float b0x,b1x,b0y,b1y,b0z,b1z,bgx,rx,bgy,ry,bgz,rz;
      up2(t01[k][0],b0x,b1x); up2(t01[k][1],b0y,b1y); up2(t01[k][2],b0z,b1z);
      up2(tgr[k][0],bgx,rx);  up2(tgr[k][1],bgy,ry);  up2(tgr[k][2],bgz,rz);
      float* o = g_T + n*384 + lane*12;
      *(float4*)(o  ) = make_float4(b0x,b0y,b0z,b1x);
      *(float4*)(o+4) = make_float4(b1y,b1z,bgx,bgy);
      *(float4*)(o+8) = make_float4(bgz,rx,ry,rz);
      up2(u01[k][0],b0x,b1x); up2(u01[k][1],b0y,b1y); up2(u01[k][2],b0z,b1z);
      up2(ugr[k][0],bgx,rx);  up2(ugr[k][1],bgy,ry);  up2(ugr[k][2],bgz,rz);
      o = g_U + n*384 + lane*12;
      *(float4*)(o  ) = make_float4(b0x,b0y,b0z,b1x);
      *(float4*)(o+4) = make_float4(b1y,b1z,bgx,bgy);
      *(float4*)(o+8) = make_float4(bgz,rx,ry,rz);
    }
    __syncwarp();
  }
}

// ---------------- per-edge MLP (128->64->64->96), 6 edges/warp, dup L1 input ----------------
__global__ void __launch_bounds__(512) k_mlp(const float* __restrict__ ele,
   const float* __restrict__ W1, const float* __restrict__ b1,
   const float* __restrict__ W2, const float* __restrict__ b2,
   const float* __restrict__ W3, const float* __restrict__ b3){
  extern __shared__ float sm[];
  // W1S ull view: [0,8192)f ; W2S [8192,12288) ; W3p [12288,16384) ; W3s [16384,18432)
  float* b1S = sm+18432; float* b2S = sm+18496; float* b3S = sm+18560;
  float* stage = sm+18656;   // per warp 2304 f : 6 edges x (256 dup-e + 64 h + 64 g)

  for (int i=threadIdx.x;i<8192;i+=blockDim.x) sm[i]=W1[i];
  for (int i=threadIdx.x;i<4096;i+=blockDim.x) sm[8192+i]=W2[i];
  for (int i=threadIdx.x;i<2048;i+=blockDim.x){
    int j=i>>5, l=i&31;
    ((float2*)(sm+12288))[i] = make_float2(W3[j*96+l], W3[j*96+32+l]);
    sm[16384+i] = W3[j*96+64+l];
  }
  for (int i=threadIdx.x;i<64;i+=blockDim.x){ b1S[i]=b1[i]; b2S[i]=b2[i]; }
  for (int i=threadIdx.x;i<96;i+=blockDim.x) b3S[i]=b3[i];
  __syncthreads();

  int warp=threadIdx.x>>5, lane=threadIdx.x&31, wpb=blockDim.x>>5;
  float* st = stage + warp*2304;

  unsigned long long bias1 = pkab(b1S[2*lane], b1S[2*lane+1]);
  unsigned long long bias2 = pkab(b2S[2*lane], b2S[2*lane+1]);
  unsigned long long bias3 = pkab(b3S[lane],   b3S[32+lane]);
  float bias3s = b3S[64+lane];

  const int batches = (EE+5)/6;
  for (int p = blockIdx.x*wpb+warp; p<batches; p+=gridDim.x*wpb){
    long long e0 = 6LL*p;
    #pragma unroll
    for (int k=0;k<6;k++){
      long long e = e0+k;
      float* eE = st + k*384;
      if (e < EE){
        const float* r = ele + e*128;
        #pragma unroll
        for (int c=0;c<4;c++){
          float x = r[c*32+lane];
          *(unsigned long long*)(eE + 2*(c*32+lane)) = pkab(x,x);
        }
      } else {
        #pragma unroll
        for (int c=0;c<4;c++)
          *(unsigned long long*)(eE + 2*(c*32+lane)) = 0ull;
      }
    }
    __syncwarp();

    // ---- layer 1: 128 -> 64 (dup input, zero movs) ----
    unsigned long long acc[6];
    #pragma unroll
    for (int k=0;k<6;k++) acc[k]=bias1;
    #pragma unroll 2
    for (int j=0;j<128;j+=4){
      unsigned long long w0=*(unsigned long long*)(sm+ (j  )*64 + 2*lane);
      unsigned long long w1=*(unsigned long long*)(sm+ (j+1)*64 + 2*lane);
      unsigned long long w2=*(unsigned long long*)(sm+ (j+2)*64 + 2*lane);
      unsigned long long w3=*(unsigned long long*)(sm+ (j+3)*64 + 2*lane);
      #pragma unroll
      for (int k=0;k<6;k++){
        ulonglong2 xa = *(ulonglong2*)(st + k*384 + 2*j);
        ulonglong2 xb = *(ulonglong2*)(st + k*384 + 2*j + 4);
        fma2(acc[k], xa.x, w0);
        fma2(acc[k], xa.y, w1);
        fma2(acc[k], xb.x, w2);
        fma2(acc[k], xb.y, w3);
      }
    }
    #pragma unroll
    for (int k=0;k<6;k++){
      float a0,a1; up2(acc[k],a0,a1);
      float* hE = st + k*384 + 256;
      hE[2*lane]=a0*sig_(a0); hE[2*lane+1]=a1*sig_(a1);
    }
    __syncwarp();

    // ---- layer 2: 64 -> 64 ----
    #pragma unroll
    for (int k=0;k<6;k++) acc[k]=bias2;
    #pragma unroll 2
    for (int j=0;j<64;j+=4){
      unsigned long long w0=*(unsigned long long*)(sm+8192+(j  )*64 + 2*lane);
      unsigned long long w1=*(unsigned long long*)(sm+8192+(j+1)*64 + 2*lane);
      unsigned long long w2=*(unsigned long long*)(sm+8192+(j+2)*64 + 2*lane);
      unsigned long long w3=*(unsigned long long*)(sm+8192+(j+3)*64 + 2*lane);
      #pragma unroll
      for (int k=0;k<6;k++){
        float4 x = *(float4*)(st + k*384 + 256 + j);
        fma2(acc[k], pk2(x.x), w0);
        fma2(acc[k], pk2(x.y), w1);
        fma2(acc[k], pk2(x.z), w2);
        fma2(acc[k], pk2(x.w), w3);
      }
    }
    #pragma unroll
    for (int k=0;k<6;k++){
      float a0,a1; up2(acc[k],a0,a1);
      float* gE = st + k*384 + 320;
      gE[2*lane]=a0*sig_(a0); gE[2*lane+1]=a1*sig_(a1);
    }
    __syncwarp();

    // ---- layer 3: 64 -> 96 ----
    unsigned long long c01[6]; float c2[6];
    #pragma unroll
    for (int k=0;k<6;k++){ c01[k]=bias3; c2[k]=bias3s; }
    #pragma unroll 2
    for (int j=0;j<64;j+=4){
      unsigned long long p0=*(unsigned long long*)(sm+12288+(j  )*64 + 2*lane);
      unsigned long long p1=*(unsigned long long*)(sm+12288+(j+1)*64 + 2*lane);
      unsigned long long p2=*(unsigned long long*)(sm+12288+(j+2)*64 + 2*lane);
      unsigned long long p3=*(unsigned long long*)(sm+12288+(j+3)*64 + 2*lane);
      float s0=sm[16384+(j  )*32+lane];
      float s1=sm[16384+(j+1)*32+lane];
      float s2=sm[16384+(j+2)*32+lane];
      float s3=sm[16384+(j+3)*32+lane];
      #pragma unroll
      for (int k=0;k<6;k++){
        float4 x = *(float4*)(st + k*384 + 320 + j);
        fma2(c01[k], pk2(x.x), p0); c2[k]+=x.x*s0;
        fma2(c01[k], pk2(x.y), p1); c2[k]+=x.y*s1;
        fma2(c01[k], pk2(x.z), p2); c2[k]+=x.z*s2;
        fma2(c01[k], pk2(x.w), p3); c2[k]+=x.w*s3;
      }
    }
    #pragma unroll
    for (int k=0;k<6;k++){
      long long e = e0+k;
      if (e >= EE) continue;
      float a,b; up2(c01[k],a,b);
      float* wo = g_wmlp + e*96;
      wo[lane]=a; wo[32+lane]=b; wo[64+lane]=c2[k];
    }
    __syncwarp();
  }
}

// ---------------- fused edge kernel: es+ev GEMVs + epilogue + scatter, 7 edges/warp ----------------
__global__ void __launch_bounds__(512) k_e12(const int* __restrict__ eidx,
   const float* __restrict__ esh, const float* __restrict__ efea,
   const float* __restrict__ Wss0, const float* __restrict__ Wssg,
   const float* __restrict__ Wsv1,
   const float* __restrict__ Wvv0, const float* __restrict__ Wvvg,
   const float* __restrict__ Wvs1){
  extern __shared__ float sm[];
  float4* FC = (float4*)sm;                               // F1 rows 128..191: 8192 f
  ulonglong2* W2a = (ulonglong2*)(sm+8192);               // F2 rows 64..95: 4096 f
  unsigned long long* W2b = (unsigned long long*)(sm+12288); // 2048 f
  float* stage = sm + 14336;                              // per warp 2720 f

  for (int i=threadIdx.x;i<2048;i+=blockDim.x){
    int u=(i>>5)+128, l=i&31;
    FC[i]=make_float4(Wss0[u*64+2*l], Wss0[u*64+2*l+1], Wssg[u*32+l], Wsv1[u*32+l]);
  }
  for (int i=threadIdx.x;i<1024;i+=blockDim.x){
    int u=(i>>5)+64, l=i&31;
    float w0=Wvv0[u*64+2*l], w1=Wvv0[u*64+2*l+1];
    float wz=Wvvg[u*32+l],   ww=Wvs1[u*32+l];
    W2a[i] = make_ulonglong2(pkab(w0,w1), pkab(wz,ww));
    W2b[i] = pkab(ww,ww);
  }
  __syncthreads();

  int warp=threadIdx.x>>5, lane=threadIdx.x&31, wpb=blockDim.x>>5;
  float* sd0 = stage + warp*2720;        // 7 x 128 dup-es
  float* vd  = sd0 + 896;                // 7 x 256 (8 f/lane)
  float* shS = sd0 + 2688;               // 7 x 4 (+pad)
  const float inv3 = 0.57735027f, invfan = 0.058925565f;
  const int batches = (EE+6)/7;

  for (int p = blockIdx.x*wpb+warp; p<batches; p+=gridDim.x*wpb){
    int e0 = p*7;
    int nid[7], njd[7];
    #pragma unroll
    for (int k=0;k<7;k++){
      int e = e0+k;
      if (e < EE){
        nid[k]=eidx[e]; njd[k]=eidx[EE+e];
        float4 sh = *(const float4*)(esh + (long long)e*4);
        if (lane==0) *(float4*)(shS + k*4) = sh;
        const float* r = efea + (long long)e*160;
        float x0=r[lane], x1=r[32+lane];
        *(unsigned long long*)(sd0 + k*128 + 2*lane)      = pkab(x0,x0);
        *(unsigned long long*)(sd0 + k*128 + 64 + 2*lane) = pkab(x1,x1);
        float ex=r[64+3*lane], ey=r[65+3*lane], ez=r[66+3*lane];
        float dd=(ex*sh.y+ey*sh.z+ez*sh.w)*inv3;
        float* o = vd + k*256 + lane*8;
        *(float4*)o     = make_float4(dd,dd,ex,ey);
        *(float2*)(o+4) = make_float2(dd,ez);
      } else {
        nid[k]=-1; njd[k]=0;
        *(unsigned long long*)(sd0 + k*128 + 2*lane)      = 0ull;
        *(unsigned long long*)(sd0 + k*128 + 64 + 2*lane) = 0ull;
        float* o = vd + k*256 + lane*8;
        *(float4*)o     = make_float4(0.f,0.f,0.f,0.f);
        *(float2*)(o+4) = make_float2(0.f,0.f);
        if (lane==0) *(float4*)(shS + k*4) = make_float4(0.f,0.f,0.f,0.f);
      }
    }
    __syncwarp();

    // ---- GEMV 1: es @ F1[128:192] ----
    unsigned long long a01[7], agt[7];
    #pragma unroll
    for (int k=0;k<7;k++){ a01[k]=0ull; agt[k]=0ull; }
    #pragma unroll 2
    for (int u=0;u<64;u+=2){
      ulonglong2 w0 = *(ulonglong2*)&FC[(u  )*32+lane];
      ulonglong2 w1 = *(ulonglong2*)&FC[(u+1)*32+lane];
      #pragma unroll
      for (int k=0;k<7;k++){
        ulonglong2 xp = *(ulonglong2*)(sd0 + k*128 + 2*u);
        fma2(a01[k], xp.x, w0.x); fma2(agt[k], xp.x, w0.y);
        fma2(a01[k], xp.y, w1.x); fma2(agt[k], xp.y, w1.y);
      }
    }

    // ---- GEMV 2: ev rows @ F2[64:96] ----
    unsigned long long b01[7], r01[7], gz2[7];
    #pragma unroll
    for (int k=0;k<7;k++){ b01[k]=0ull; r01[k]=0ull; gz2[k]=0ull; }
    #pragma unroll 4
    for (int u=0;u<32;u++){
      ulonglong2 wa = W2a[u*32+lane];
      unsigned long long wb = W2b[u*32+lane];
      #pragma unroll
      for (int k=0;k<7;k++){
        ulonglong2 t1 = *(ulonglong2*)(vd + k*256 + u*8);
        unsigned long long t2 = *(unsigned long long*)(vd + k*256 + u*8 + 4);
        fma2(b01[k], t1.x, wa.x);
        fma2(r01[k], t1.y, wb);
        fma2(gz2[k], t2,   wa.y);
      }
    }

    // ---- epilogue + scatter ----
    #pragma unroll
    for (int k=0;k<7;k++){
      if (nid[k] < 0) continue;
      long long e = e0+k;
      float a0,a1,ag,at,b0,b1,r0,r1,bg,r2;
      up2(a01[k],a0,a1); up2(agt[k],ag,at);
      up2(b01[k],b0,b1); up2(r01[k],r0,r1); up2(gz2[k],bg,r2);
      float4 P = *(const float4*)(g_P + nid[k]*128 + lane*4);
      float4 Q = *(const float4*)(g_Q + njd[k]*128 + lane*4);
      a0+=P.x+Q.x; a1+=P.y+Q.y; ag+=P.z+Q.z; at+=P.w+Q.w;

      float4 sh = *(float4*)(shS + k*4);
      const float* tp  = g_T + nid[k]*384 + lane*12;
      const float* upt = g_U + njd[k]*384 + lane*12;
      float4 t0=*(const float4*)tp,  t1=*(const float4*)(tp+4),  t2=*(const float4*)(tp+8);
      float4 u0=*(const float4*)upt, u1=*(const float4*)(upt+4), u2=*(const float4*)(upt+8);
      float s0x=t0.x+u0.x, s0y=t0.y+u0.y, s0z=t0.z+u0.z, s0w=t0.w+u0.w;
      float s1x=t1.x+u1.x, s1y=t1.y+u1.y, s1z=t1.z+u1.z, s1w=t1.w+u1.w;
      float s2x=t2.x+u2.x, s2y=t2.y+u2.y, s2z=t2.z+u2.z, s2w=t2.w+u2.w;
      b0 += inv3*(s0x*sh.y + s0y*sh.z + s0z*sh.w);
      b1 += inv3*(s0w*sh.y + s1x*sh.z + s1y*sh.w);
      bg += inv3*(s1z*sh.y + s1w*sh.z + s2x*sh.w);
      r0 += s2y; r1 += s2z; r2 += s2w;

      float zs0=(sh.x*a0+b0)*invfan, zs1=(sh.x*a1+b1)*invfan;
      float zg =(sh.x*ag+bg)*invfan;
      const float* wm = g_wmlp + e*96;
      float2 wm01 = *(const float2*)(wm+2*lane);
      float wmv = wm[64+lane];
      zs0 = zs0*sig_(zs0)*wm01.x;
      zs1 = zs1*sig_(zs1)*wm01.y;
      float gv = sig_(zg)*wmv*invfan;
      int n = nid[k];
      atomicAdd((float2*)(g_accs + n*64 + 2*lane), make_float2(zs0, zs1));
      atomicAdd(&g_accv4[n*32+lane],
                make_float4((at*sh.y + r0*sh.x)*gv,
                            (at*sh.z + r1*sh.x)*gv,
                            (at*sh.w + r2*sh.x)*gv, 0.f));
    }
    __syncwarp();
  }
}

// ---------------- node post ----------------
__global__ void __launch_bounds__(512) k_node_post(const int* __restrict__ batch,
   const float* __restrict__ ppWs, const float* __restrict__ ppbs,
   const float* __restrict__ ppWv){
  extern __shared__ float sm[];
  float2* WsS = (float2*)sm;
  float* WvS = sm+4096;
  float* bsS = sm+5120;
  float* stage = sm+5184;
  for (int i=threadIdx.x;i<4096;i+=blockDim.x) sm[i]=ppWs[i];
  for (int i=threadIdx.x;i<1024;i+=blockDim.x) WvS[i]=ppWv[i];
  for (int i=threadIdx.x;i<64;i+=blockDim.x) bsS[i]=ppbs[i];
  __syncthreads();
  int warp=threadIdx.x>>5, lane=threadIdx.x&31, wpb=blockDim.x>>5;
  float*  sS  = stage + warp*192;
  float4* vS  = (float4*)(sS+64);
  for (int n=blockIdx.x*wpb+warp; n<NN; n+=gridDim.x*wpb){
    sS[lane]=g_accs[n*64+lane]; sS[32+lane]=g_accs[n*64+32+lane];
    vS[lane]=g_accv4[n*32+lane];
    __syncwarp();
    float a0=0.f,a1=0.f;
    #pragma unroll 4
    for (int u=0;u<64;u++){
      float x=sS[u]; float2 w=WsS[u*32+lane];
      a0+=x*w.x; a1+=x*w.y;
    }
    float ns0 = a0*0.125f + bsS[2*lane]   + g_scs[n*64+2*lane];
    float ns1 = a1*0.125f + bsS[2*lane+1] + g_scs[n*64+2*lane+1];
    g_ns[n*64+2*lane]=ns0; g_ns[n*64+2*lane+1]=ns1;
    float vx=0.f,vy=0.f,vz=0.f;
    #pragma unroll 4
    for (int u=0;u<32;u++){
      float4 x=vS[u]; float w=WvS[u*32+lane];
      vx+=x.x*w; vy+=x.y*w; vz+=x.z*w;
    }
    float nv0 = vx*0.17677670f + g_scv[n*96+3*lane];
    float nv1 = vy*0.17677670f + g_scv[n*96+3*lane+1];
    float nv2 = vz*0.17677670f + g_scv[n*96+3*lane+2];
    g_nv[n*96+3*lane]=nv0; g_nv[n*96+3*lane+1]=nv1; g_nv[n*96+3*lane+2]=nv2;
    float m = ns0+ns1;
    float q = ns0*ns0+ns1*ns1;
    float pw = nv0*nv0+nv1*nv1+nv2*nv2;
    #pragma unroll
    for (int off=16;off>0;off>>=1){
      m += __shfl_down_sync(0xffffffffu, m, off);
      q += __shfl_down_sync(0xffffffffu, q, off);
      pw += __shfl_down_sync(0xffffffffu, pw, off);
    }
    if (lane==0){
      int g = batch[n];
      atomicAdd(&g_gstat[g],        m*(1.f/64.f));
      atomicAdd(&g_gstat[NG_+g],    q*(1.f/64.f));
      atomicAdd(&g_gstat[2*NG_+g],  pw*(1.f/96.f));
      atomicAdd(&g_gstat[3*NG_+g],  1.f);
    }
    __syncwarp();
  }
}

// ---------------- group finalize ----------------
__global__ void k_groups(){
  int t = threadIdx.x;
  if (t < NG_){
    float c  = fmaxf(g_gstat[3*NG_+t], 1.f);
    float mu = g_gstat[t]/c;
    float vs = g_gstat[NG_+t]/c - mu*mu;
    float vv = g_gstat[2*NG_+t]/c;
    g_gout[t]       = mu;
    g_gout[NG_+t]   = rsqrtf(vs+1e-5f);
    g_gout[2*NG_+t] = rsqrtf(vv+1e-5f);
  }
}

// ---------------- apply norm + residual ----------------
__global__ void k_out(const float* __restrict__ nf, const int* __restrict__ batch,
   const float* __restrict__ lnws, const float* __restrict__ lnbs,
   const float* __restrict__ lnwv, float* __restrict__ out){
  int i = blockIdx.x*blockDim.x+threadIdx.x;
  if (i >= NN*160) return;
  int n = i/160, c = i - n*160;
  int g = batch[n];
  float base = nf[i];
  float o;
  if (c < 64){
    float x = (g_ns[n*64+c] - g_gout[g]) * g_gout[NG_+g];
    o = base + x*lnws[c] + lnbs[c];
  } else {
    int cc = c-64;
    o = base + g_nv[n*96+cc]*g_gout[2*NG_+g]*lnwv[cc/3];
  }
  out[i]=o;
}

// ---------------- launcher ----------------
extern "C" void kernel_launch(void* const* d_in, const int* in_sizes, int n_in,
                              void* d_out, int out_size){
  const float* nf   =(const float*)d_in[0];
  const float* oh   =(const float*)d_in[1];
  const float* esh  =(const float*)d_in[2];
  const float* efea =(const float*)d_in[3];
  const float* ele  =(const float*)d_in[4];
  const int*   eidx =(const int*)d_in[5];
  const int*   batch=(const int*)d_in[6];
  const float* lpWs =(const float*)d_in[7];
  const float* lpbs =(const float*)d_in[8];
  const float* lpWv =(const float*)d_in[9];
  const float* ppWs =(const float*)d_in[10];
  const float* ppbs =(const float*)d_in[11];
  const float* ppWv =(const float*)d_in[12];
  const float* scWs =(const float*)d_in[13];
  const float* scWv =(const float*)d_in[14];
  const float* Wss0 =(const float*)d_in[15];
  const float* Wvv0 =(const float*)d_in[16];
  const float* Wssg =(const float*)d_in[17];
  const float* Wvvg =(const float*)d_in[18];
  const float* Wsv1 =(const float*)d_in[19];
  const float* Wvs1 =(const float*)d_in[20];
  const float* fcW1 =(const float*)d_in[21];
  const float* fcb1 =(const float*)d_in[22];
  const float* fcW2 =(const float*)d_in[23];
  const float* fcb2 =(const float*)d_in[24];
  const float* fcW3 =(const float*)d_in[25];
  const float* fcb3 =(const float*)d_in[26];
  const float* lnws =(const float*)d_in[27];
  const float* lnbs =(const float*)d_in[28];
  const float* lnwv =(const float*)d_in[29];
  float* out = (float*)d_out;

  const int SM_PRE  = (25664 + 16*192)*4;    // 114944
  const int SM_PSTV = (24576 + 16*1024)*4;   // 163840
  const int SM_MLP  = (18656 + 16*2304)*4;   // 222080
  const int SM_E12  = (14336 + 16*2720)*4;   // 231424
  const int SM_POST = (5184  + 16*192)*4;    // 33024
  cudaFuncSetAttribute(k_node_pre,  cudaFuncAttributeMaxDynamicSharedMemorySize, SM_PRE);
  cudaFuncSetAttribute(k_pstv,      cudaFuncAttributeMaxDynamicSharedMemorySize, SM_PSTV);
  cudaFuncSetAttribute(k_mlp,       cudaFuncAttributeMaxDynamicSharedMemorySize, SM_MLP);
  cudaFuncSetAttribute(k_e12,       cudaFuncAttributeMaxDynamicSharedMemorySize, SM_E12);
  cudaFuncSetAttribute(k_node_post, cudaFuncAttributeMaxDynamicSharedMemorySize, SM_POST);

  k_zero<<<(NN*192 + 4*NG_ + 255)/256, 256>>>();
  k_node_pre<<<148, 512, SM_PRE>>>(nf, oh, lpWs, lpbs, lpWv, scWs, scWv);
  k_pstv<<<148, 512, SM_PSTV>>>(Wss0, Wssg, Wsv1, Wvv0, Wvvg, Wvs1);
  k_mlp<<<148, 512, SM_MLP>>>(ele, fcW1, fcb1, fcW2, fcb2, fcW3, fcb3);
  k_e12<<<148, 512, SM_E12>>>(eidx, esh, efea, Wss0, Wssg, Wsv1, Wvv0, Wvvg, Wvs1);
  k_node_post<<<148, 512, SM_POST>>>(batch, ppWs, ppbs, ppWv);
  k_groups<<<1, 32>>>();
  k_out<<<(NN*160 + 255)/256, 256>>>(nf, batch, lnws, lnbs, lnwv, out);
}

// round 7
// speedup vs baseline: 1.0476x; 1.0476x over previous
#include <cuda_runtime.h>

#define NN 10000
#define EE 320000
#define NG_ 16

// ---------------- scratch (static device memory; no allocations) ----------------
__device__ float  g_s[NN*64];
__device__ float4 g_v4[NN*32];
__device__ float  g_scs[NN*64];
__device__ float  g_scv[NN*96];
__device__ float  g_accs[NN*64];
__device__ float4 g_accv4[NN*32];            // (x,y,z,pad) per lane
__device__ float  g_ns[NN*64];
__device__ float  g_nv[NN*96];
__device__ float  g_wmlp[(long long)EE*96];
__device__ float  g_P[NN*128];               // s@F1[0:64]   (i-role), lane*4 layout
__device__ float  g_Q[NN*128];               // s@F1[64:128] (j-role)
__device__ float  g_T[NN*384];               // v x F2[0:32]  (i-role), lane*12 layout
__device__ float  g_U[NN*384];               // v x F2[32:64] (j-role)
__device__ float  g_gstat[4*NG_];
__device__ float  g_gout[3*NG_];

__device__ __forceinline__ float sig_(float x){ return 1.f/(1.f+__expf(-x)); }

// ---- f32x2 packed math helpers (sm_103a FFMA2 via PTX) ----
__device__ __forceinline__ unsigned long long pk2(float x){
  unsigned long long r; asm("mov.b64 %0, {%1, %1};" : "=l"(r) : "f"(x)); return r; }
__device__ __forceinline__ unsigned long long pkab(float a, float b){
  unsigned long long r; asm("mov.b64 %0, {%1, %2};" : "=l"(r) : "f"(a), "f"(b)); return r; }
__device__ __forceinline__ void up2(unsigned long long v, float &a, float &b){
  asm("mov.b64 {%0, %1}, %2;" : "=f"(a), "=f"(b) : "l"(v)); }
__device__ __forceinline__ void fma2(unsigned long long &d, unsigned long long a, unsigned long long b){
  asm("fma.rn.f32x2 %0, %1, %2, %3;" : "=l"(d) : "l"(a), "l"(b), "l"(d)); }

// ---------------- zero accumulators ----------------
__global__ void k_zero(){
  int i = blockIdx.x*blockDim.x + threadIdx.x;
  if (i < NN*64) g_accs[i] = 0.f;
  int j = i - NN*64;
  if (j >= 0 && j < NN*128) ((float*)g_accv4)[j] = 0.f;
  int k = i - NN*192;
  if (k >= 0 && k < 4*NG_) g_gstat[k] = 0.f;
}

// ---------------- node pre ----------------
__global__ void __launch_bounds__(512) k_node_pre(const float* __restrict__ nf,
                           const float* __restrict__ oh,
                           const float* __restrict__ lpWs, const float* __restrict__ lpbs,
                           const float* __restrict__ lpWv,
                           const float* __restrict__ scWs, const float* __restrict__ scWv){
  extern __shared__ float sm[];
  float2* WsS  = (float2*)sm;
  float*  WvS  = sm + 4096;
  float2* sWsS = (float2*)(sm + 5120);
  float*  sWvS = sm + 21504;
  float*  bsS  = sm + 25600;
  float*  stage= sm + 25664;

  for (int i=threadIdx.x;i<4096;i+=blockDim.x) sm[i]=lpWs[i];
  for (int i=threadIdx.x;i<1024;i+=blockDim.x) WvS[i]=lpWv[i];
  for (int i=threadIdx.x;i<16384;i+=blockDim.x) sm[5120+i]=scWs[i];
  for (int i=threadIdx.x;i<4096;i+=blockDim.x) sWvS[i]=scWv[i];
  for (int i=threadIdx.x;i<64;i+=blockDim.x) bsS[i]=lpbs[i];
  __syncthreads();

  int warp = threadIdx.x>>5, lane = threadIdx.x&31, wpb = blockDim.x>>5;
  float*  sS  = stage + warp*192;
  float4* vS  = (float4*)(sS + 64);

  for (int n = blockIdx.x*wpb + warp; n < NN; n += gridDim.x*wpb){
    const float* row = nf + n*160;
    sS[lane] = row[lane]; sS[32+lane] = row[32+lane];
    vS[lane] = make_float4(row[64+3*lane], row[65+3*lane], row[66+3*lane], 0.f);
    const float* o4 = oh + n*4;
    int sp = (o4[1]>0.5f)?1:((o4[2]>0.5f)?2:((o4[3]>0.5f)?3:0));
    __syncwarp();

    float a0=0.f,a1=0.f,c0=0.f,c1=0.f;
    #pragma unroll 4
    for (int u=0;u<64;u++){
      float x = sS[u];
      float2 w  = WsS[u*32+lane];
      float2 w2 = sWsS[(u*4+sp)*32+lane];
      a0+=x*w.x; a1+=x*w.y; c0+=x*w2.x; c1+=x*w2.y;
    }
    g_s[n*64+2*lane]   = a0*0.125f + bsS[2*lane];
    g_s[n*64+2*lane+1] = a1*0.125f + bsS[2*lane+1];
    g_scs[n*64+2*lane]   = c0*0.0625f;
    g_scs[n*64+2*lane+1] = c1*0.0625f;

    float vx=0.f,vy=0.f,vz=0.f,cx=0.f,cy=0.f,cz=0.f;
    #pragma unroll 4
    for (int u=0;u<32;u++){
      float4 x = vS[u];
      float w  = WvS[u*32+lane];
      float w2 = sWvS[(u*4+sp)*32+lane];
      vx+=x.x*w;  vy+=x.y*w;  vz+=x.z*w;
      cx+=x.x*w2; cy+=x.y*w2; cz+=x.z*w2;
    }
    g_v4[n*32+lane] = make_float4(vx*0.17677670f, vy*0.17677670f, vz*0.17677670f, 0.f);
    g_scv[n*96+3*lane]   = cx*0.08838835f;
    g_scv[n*96+3*lane+1] = cy*0.08838835f;
    g_scv[n*96+3*lane+2] = cz*0.08838835f;
    __syncwarp();
  }
}

// ---------------- per-node P/Q (phase 1) and T/U (phase 2), merged ----------------
__global__ void __launch_bounds__(512) k_pstv(const float* __restrict__ Wss0,
   const float* __restrict__ Wssg, const float* __restrict__ Wsv1,
   const float* __restrict__ Wvv0, const float* __restrict__ Wvvg,
   const float* __restrict__ Wvs1){
  extern __shared__ float sm[];
  float4* FA = (float4*)sm;            // F1 rows 0..63:  64x32 f4
  float4* FB = (float4*)(sm+8192);     // F1 rows 64..127
  float4* GA = (float4*)(sm+16384);    // F2 rows 0..31
  float4* GB = (float4*)(sm+20480);    // F2 rows 32..63
  float* stage = sm + 24576;           // per warp 1024 f

  for (int i=threadIdx.x;i<2048;i+=blockDim.x){
    int u=i>>5, l=i&31;
    FA[i]=make_float4(Wss0[u*64+2*l], Wss0[u*64+2*l+1], Wssg[u*32+l], Wsv1[u*32+l]);
    int u2=u+64;
    FB[i]=make_float4(Wss0[u2*64+2*l], Wss0[u2*64+2*l+1], Wssg[u2*32+l], Wsv1[u2*32+l]);
  }
  for (int i=threadIdx.x;i<1024;i+=blockDim.x){
    int u=i>>5, l=i&31;
    GA[i]=make_float4(Wvv0[u*64+2*l], Wvv0[u*64+2*l+1], Wvvg[u*32+l], Wvs1[u*32+l]);
    int u2=u+32;
    GB[i]=make_float4(Wvv0[u2*64+2*l], Wvv0[u2*64+2*l+1], Wvvg[u2*32+l], Wvs1[u2*32+l]);
  }
  __syncthreads();

  int warp=threadIdx.x>>5, lane=threadIdx.x&31, wpb=blockDim.x>>5;
  float* sd = stage + warp*1024;

  // ---- phase 1: P/Q, 8 nodes/warp ----
  const int b1 = NN/8;
  for (int p = blockIdx.x*wpb+warp; p<b1; p+=gridDim.x*wpb){
    int n0 = p*8;
    #pragma unroll
    for (int k=0;k<8;k++){
      int n = n0+k;
      float x0 = g_s[n*64+lane];
      float x1 = g_s[n*64+32+lane];
      *(unsigned long long*)(sd + k*128 + 2*lane)      = pkab(x0,x0);
      *(unsigned long long*)(sd + k*128 + 64 + 2*lane) = pkab(x1,x1);
    }
    __syncwarp();

    unsigned long long pa[8], pg[8], qa[8], qg[8];
    #pragma unroll
    for (int k=0;k<8;k++){ pa[k]=0ull; pg[k]=0ull; qa[k]=0ull; qg[k]=0ull; }
    #pragma unroll 2
    for (int u=0;u<64;u+=2){
      ulonglong2 wa0 = *(ulonglong2*)&FA[(u  )*32+lane];
      ulonglong2 wa1 = *(ulonglong2*)&FA[(u+1)*32+lane];
      ulonglong2 wb0 = *(ulonglong2*)&FB[(u  )*32+lane];
      ulonglong2 wb1 = *(ulonglong2*)&FB[(u+1)*32+lane];
      #pragma unroll
      for (int k=0;k<8;k++){
        ulonglong2 xp = *(ulonglong2*)(sd + k*128 + 2*u);
        fma2(pa[k], xp.x, wa0.x); fma2(pg[k], xp.x, wa0.y);
        fma2(qa[k], xp.x, wb0.x); fma2(qg[k], xp.x, wb0.y);
        fma2(pa[k], xp.y, wa1.x); fma2(pg[k], xp.y, wa1.y);
        fma2(qa[k], xp.y, wb1.x); fma2(qg[k], xp.y, wb1.y);
      }
    }
    #pragma unroll
    for (int k=0;k<8;k++){
      int n = n0+k;
      float a0,a1,ag,at;
      up2(pa[k],a0,a1); up2(pg[k],ag,at);
      *(float4*)(g_P + n*128 + lane*4) = make_float4(a0,a1,ag,at);
      up2(qa[k],a0,a1); up2(qg[k],ag,at);
      *(float4*)(g_Q + n*128 + lane*4) = make_float4(a0,a1,ag,at);
    }
    __syncwarp();
  }

  // ---- phase 2: T/U, 4 nodes/warp ----
  float4* vst = (float4*)sd;
  const int b2 = NN/4;
  for (int p = blockIdx.x*wpb+warp; p<b2; p+=gridDim.x*wpb){
    int n0 = p*4;
    #pragma unroll
    for (int k=0;k<4;k++) vst[k*32+lane] = g_v4[(n0+k)*32+lane];
    __syncwarp();

    unsigned long long t01[4][3], tgr[4][3], u01[4][3], ugr[4][3];
    #pragma unroll
    for (int k=0;k<4;k++)
      #pragma unroll
      for (int c=0;c<3;c++){ t01[k][c]=0ull; tgr[k][c]=0ull; u01[k][c]=0ull; ugr[k][c]=0ull; }

    #pragma unroll 2
    for (int u=0;u<32;u++){
      ulonglong2 ga = *(ulonglong2*)&GA[u*32+lane];
      ulonglong2 gb = *(ulonglong2*)&GB[u*32+lane];
      #pragma unroll
      for (int k=0;k<4;k++){
        float4 v = vst[k*32+u];
        unsigned long long vx=pk2(v.x), vy=pk2(v.y), vz=pk2(v.z);
        fma2(t01[k][0], vx, ga.x); fma2(t01[k][1], vy, ga.x); fma2(t01[k][2], vz, ga.x);
        fma2(tgr[k][0], vx, ga.y); fma2(tgr[k][1], vy, ga.y); fma2(tgr[k][2], vz, ga.y);
        fma2(u01[k][0], vx, gb.x); fma2(u01[k][1], vy, gb.x); fma2(u01[k][2], vz, gb.x);
        fma2(ugr[k][0], vx, gb.y); fma2(ugr[k][1], vy, gb.y); fma2(ugr[k][2], vz, gb.y);
      }
    }
    #pragma unroll
    for (int k=0;k<4;k++){
      int n = n0+k;
      float b0x,b1x,b0y,b1y,b0z,b1z,bgx,rx,bgy,ry,bgz,rz;
      up2(t01[k][0],b0x,b1x); up2(t01[k][1],b0y,b1y); up2(t01[k][2],b0z,b1z);
      up2(tgr[k][0],bgx,rx);  up2(tgr[k][1],bgy,ry);  up2(tgr[k][2],bgz,rz);
      float* o = g_T + n*384 + lane*12;
      *(float4*)(o  ) = make_float4(b0x,b0y,b0z,b1x);
      *(float4*)(o+4) = make_float4(b1y,b1z,bgx,bgy);
      *(float4*)(o+8) = make_float4(bgz,rx,ry,rz);
      up2(u01[k][0],b0x,b1x); up2(u01[k][1],b0y,b1y); up2(u01[k][2],b0z,b1z);
      up2(ugr[k][0],bgx,rx);  up2(ugr[k][1],bgy,ry);  up2(ugr[k][2],bgz,rz);
      o = g_U + n*384 + lane*12;
      *(float4*)(o  ) = make_float4(b0x,b0y,b0z,b1x);
      *(float4*)(o+4) = make_float4(b1y,b1z,bgx,bgy);
      *(float4*)(o+8) = make_float4(bgz,rx,ry,rz);
    }
    __syncwarp();
  }
}

// ---------------- per-edge MLP (128->64->64->96), 9 edges/warp, f32x2 ----------------
__global__ void __launch_bounds__(512) k_mlp(const float* __restrict__ ele,
   const float* __restrict__ W1, const float* __restrict__ b1,
   const float* __restrict__ W2, const float* __restrict__ b2,
   const float* __restrict__ W3, const float* __restrict__ b3){
  extern __shared__ float sm[];
  // W1S: [0,8192) ; W2S: [8192,12288) ; W3p: [12288,16384) ; W3s: [16384,18432)
  float* b1S = sm+18432; float* b2S = sm+18496; float* b3S = sm+18560;
  float* stage = sm+18656;   // per warp 2304 f : 9 edges x 256 (e:128, h:64, g:64)

  for (int i=threadIdx.x;i<8192;i+=blockDim.x) sm[i]=W1[i];
  for (int i=threadIdx.x;i<4096;i+=blockDim.x) sm[8192+i]=W2[i];
  for (int i=threadIdx.x;i<2048;i+=blockDim.x){
    int j=i>>5, l=i&31;
    ((float2*)(sm+12288))[i] = make_float2(W3[j*96+l], W3[j*96+32+l]);
    sm[16384+i] = W3[j*96+64+l];
  }
  for (int i=threadIdx.x;i<64;i+=blockDim.x){ b1S[i]=b1[i]; b2S[i]=b2[i]; }
  for (int i=threadIdx.x;i<96;i+=blockDim.x) b3S[i]=b3[i];
  __syncthreads();

  int warp=threadIdx.x>>5, lane=threadIdx.x&31, wpb=blockDim.x>>5;
  float* st = stage + warp*2304;

  unsigned long long bias1 = pkab(b1S[2*lane], b1S[2*lane+1]);
  unsigned long long bias2 = pkab(b2S[2*lane], b2S[2*lane+1]);
  unsigned long long bias3 = pkab(b3S[lane],   b3S[32+lane]);
  float bias3s = b3S[64+lane];

  const int batches = (EE+8)/9;
  for (int p = blockIdx.x*wpb+warp; p<batches; p+=gridDim.x*wpb){
    long long e0 = 9LL*p;
    #pragma unroll
    for (int k=0;k<9;k++){
      long long e = e0+k;
      float* eE = st + k*256;
      if (e < EE){
        const float* r = ele + e*128;
        #pragma unroll
        for (int c=0;c<4;c++) eE[c*32+lane]=r[c*32+lane];
      } else {
        #pragma unroll
        for (int c=0;c<4;c++) eE[c*32+lane]=0.f;
      }
    }
    __syncwarp();

    // ---- layer 1: 128 -> 64 ----
    unsigned long long acc[9];
    #pragma unroll
    for (int k=0;k<9;k++) acc[k]=bias1;
    #pragma unroll 2
    for (int j=0;j<128;j+=4){
      unsigned long long w0=*(unsigned long long*)(sm+ (j  )*64 + 2*lane);
      unsigned long long w1=*(unsigned long long*)(sm+ (j+1)*64 + 2*lane);
      unsigned long long w2=*(unsigned long long*)(sm+ (j+2)*64 + 2*lane);
      unsigned long long w3=*(unsigned long long*)(sm+ (j+3)*64 + 2*lane);
      #pragma unroll
      for (int k=0;k<9;k++){
        float4 x = *(float4*)(st + k*256 + j);
        fma2(acc[k], pk2(x.x), w0);
        fma2(acc[k], pk2(x.y), w1);
        fma2(acc[k], pk2(x.z), w2);
        fma2(acc[k], pk2(x.w), w3);
      }
    }
    #pragma unroll
    for (int k=0;k<9;k++){
      float a0,a1; up2(acc[k],a0,a1);
      float* hE = st + k*256 + 128;
      hE[2*lane]=a0*sig_(a0); hE[2*lane+1]=a1*sig_(a1);
    }
    __syncwarp();

    // ---- layer 2: 64 -> 64 ----
    #pragma unroll
    for (int k=0;k<9;k++) acc[k]=bias2;
    #pragma unroll 2
    for (int j=0;j<64;j+=4){
      unsigned long long w0=*(unsigned long long*)(sm+8192+(j  )*64 + 2*lane);
      unsigned long long w1=*(unsigned long long*)(sm+8192+(j+1)*64 + 2*lane);
      unsigned long long w2=*(unsigned long long*)(sm+8192+(j+2)*64 + 2*lane);
      unsigned long long w3=*(unsigned long long*)(sm+8192+(j+3)*64 + 2*lane);
      #pragma unroll
      for (int k=0;k<9;k++){
        float4 x = *(float4*)(st + k*256 + 128 + j);
        fma2(acc[k], pk2(x.x), w0);
        fma2(acc[k], pk2(x.y), w1);
        fma2(acc[k], pk2(x.z), w2);
        fma2(acc[k], pk2(x.w), w3);
      }
    }
    #pragma unroll
    for (int k=0;k<9;k++){
      float a0,a1; up2(acc[k],a0,a1);
      float* gE = st + k*256 + 192;
      gE[2*lane]=a0*sig_(a0); gE[2*lane+1]=a1*sig_(a1);
    }
    __syncwarp();

    // ---- layer 3: 64 -> 96 ----
    unsigned long long c01[9]; float c2[9];
    #pragma unroll
    for (int k=0;k<9;k++){ c01[k]=bias3; c2[k]=bias3s; }
    #pragma unroll 2
    for (int j=0;j<64;j+=4){
      unsigned long long p0=*(unsigned long long*)(sm+12288+(j  )*64 + 2*lane);
      unsigned long long p1=*(unsigned long long*)(sm+12288+(j+1)*64 + 2*lane);
      unsigned long long p2=*(unsigned long long*)(sm+12288+(j+2)*64 + 2*lane);
      unsigned long long p3=*(unsigned long long*)(sm+12288+(j+3)*64 + 2*lane);
      float s0=sm[16384+(j  )*32+lane];
      float s1=sm[16384+(j+1)*32+lane];
      float s2=sm[16384+(j+2)*32+lane];
      float s3=sm[16384+(j+3)*32+lane];
      #pragma unroll
      for (int k=0;k<9;k++){
        float4 x = *(float4*)(st + k*256 + 192 + j);
        fma2(c01[k], pk2(x.x), p0); c2[k]+=x.x*s0;
        fma2(c01[k], pk2(x.y), p1); c2[k]+=x.y*s1;
        fma2(c01[k], pk2(x.z), p2); c2[k]+=x.z*s2;
        fma2(c01[k], pk2(x.w), p3); c2[k]+=x.w*s3;
      }
    }
    #pragma unroll
    for (int k=0;k<9;k++){
      long long e = e0+k;
      if (e >= EE) continue;
      float a,b; up2(c01[k],a,b);
      float* wo = g_wmlp + e*96;
      wo[lane]=a; wo[32+lane]=b; wo[64+lane]=c2[k];
    }
    __syncwarp();
  }
}

// ---------------- fused edge kernel: es+ev GEMVs + epilogue + scatter, 7 edges/warp ----------------
__global__ void __launch_bounds__(512) k_e12(const int* __restrict__ eidx,
   const float* __restrict__ esh, const float* __restrict__ efea,
   const float* __restrict__ Wss0, const float* __restrict__ Wssg,
   const float* __restrict__ Wsv1,
   const float* __restrict__ Wvv0, const float* __restrict__ Wvvg,
   const float* __restrict__ Wvs1){
  extern __shared__ float sm[];
  float4* FC = (float4*)sm;                               // F1 rows 128..191: 8192 f
  ulonglong2* W2a = (ulonglong2*)(sm+8192);               // F2 rows 64..95: 4096 f
  unsigned long long* W2b = (unsigned long long*)(sm+12288); // 2048 f
  float* stage = sm + 14336;                              // per warp 2720 f

  for (int i=threadIdx.x;i<2048;i+=blockDim.x){
    int u=(i>>5)+128, l=i&31;
    FC[i]=make_float4(Wss0[u*64+2*l], Wss0[u*64+2*l+1], Wssg[u*32+l], Wsv1[u*32+l]);
  }
  for (int i=threadIdx.x;i<1024;i+=blockDim.x){
    int u=(i>>5)+64, l=i&31;
    float w0=Wvv0[u*64+2*l], w1=Wvv0[u*64+2*l+1];
    float wz=Wvvg[u*32+l],   ww=Wvs1[u*32+l];
    W2a[i] = make_ulonglong2(pkab(w0,w1), pkab(wz,ww));
    W2b[i] = pkab(ww,ww);
  }
  __syncthreads();

  int warp=threadIdx.x>>5, lane=threadIdx.x&31, wpb=blockDim.x>>5;
  float* sd0 = stage + warp*2720;        // 7 x 128 dup-es
  float* vd  = sd0 + 896;                // 7 x 256 (8 f/lane)
  float* shS = sd0 + 2688;               // 7 x 4 (+pad)
  const float inv3 = 0.57735027f, invfan = 0.058925565f;
  const int batches = (EE+6)/7;

  for (int p = blockIdx.x*wpb+warp; p<batches; p+=gridDim.x*wpb){
    int e0 = p*7;
    int nid[7], njd[7];
    #pragma unroll
    for (int k=0;k<7;k++){
      int e = e0+k;
      if (e < EE){
        nid[k]=eidx[e]; njd[k]=eidx[EE+e];
        float4 sh = *(const float4*)(esh + (long long)e*4);
        if (lane==0) *(float4*)(shS + k*4) = sh;
        const float* r = efea + (long long)e*160;
        float x0=r[lane], x1=r[32+lane];
        *(unsigned long long*)(sd0 + k*128 + 2*lane)      = pkab(x0,x0);
        *(unsigned long long*)(sd0 + k*128 + 64 + 2*lane) = pkab(x1,x1);
        float ex=r[64+3*lane], ey=r[65+3*lane], ez=r[66+3*lane];
        float dd=(ex*sh.y+ey*sh.z+ez*sh.w)*inv3;
        float* o = vd + k*256 + lane*8;
        *(float4*)o     = make_float4(dd,dd,ex,ey);
        *(float2*)(o+4) = make_float2(dd,ez);
      } else {
        nid[k]=-1; njd[k]=0;
        *(unsigned long long*)(sd0 + k*128 + 2*lane)      = 0ull;
        *(unsigned long long*)(sd0 + k*128 + 64 + 2*lane) = 0ull;
        float* o = vd + k*256 + lane*8;
        *(float4*)o     = make_float4(0.f,0.f,0.f,0.f);
        *(float2*)(o+4) = make_float2(0.f,0.f);
        if (lane==0) *(float4*)(shS + k*4) = make_float4(0.f,0.f,0.f,0.f);
      }
    }
    __syncwarp();

    // ---- GEMV 1: es @ F1[128:192] ----
    unsigned long long a01[7], agt[7];
    #pragma unroll
    for (int k=0;k<7;k++){ a01[k]=0ull; agt[k]=0ull; }
    #pragma unroll 2
    for (int u=0;u<64;u+=2){
      ulonglong2 w0 = *(ulonglong2*)&FC[(u  )*32+lane];
      ulonglong2 w1 = *(ulonglong2*)&FC[(u+1)*32+lane];
      #pragma unroll
      for (int k=0;k<7;k++){
        ulonglong2 xp = *(ulonglong2*)(sd0 + k*128 + 2*u);
        fma2(a01[k], xp.x, w0.x); fma2(agt[k], xp.x, w0.y);
        fma2(a01[k], xp.y, w1.x); fma2(agt[k], xp.y, w1.y);
      }
    }

    // ---- GEMV 2: ev rows @ F2[64:96] ----
    unsigned long long b01[7], r01[7], gz2[7];
    #pragma unroll
    for (int k=0;k<7;k++){ b01[k]=0ull; r01[k]=0ull; gz2[k]=0ull; }
    #pragma unroll 4
    for (int u=0;u<32;u++){
      ulonglong2 wa = W2a[u*32+lane];
      unsigned long long wb = W2b[u*32+lane];
      #pragma unroll
      for (int k=0;k<7;k++){
        ulonglong2 t1 = *(ulonglong2*)(vd + k*256 + u*8);
        unsigned long long t2 = *(unsigned long long*)(vd + k*256 + u*8 + 4);
        fma2(b01[k], t1.x, wa.x);
        fma2(r01[k], t1.y, wb);
        fma2(gz2[k], t2,   wa.y);
      }
    }

    // ---- epilogue + scatter ----
    #pragma unroll
    for (int k=0;k<7;k++){
      if (nid[k] < 0) continue;
      long long e = e0+k;
      float a0,a1,ag,at,b0,b1,r0,r1,bg,r2;
      up2(a01[k],a0,a1); up2(agt[k],ag,at);
      up2(b01[k],b0,b1); up2(r01[k],r0,r1); up2(gz2[k],bg,r2);
      float4 P = *(const float4*)(g_P + nid[k]*128 + lane*4);
      float4 Q = *(const float4*)(g_Q + njd[k]*128 + lane*4);
      a0+=P.x+Q.x; a1+=P.y+Q.y; ag+=P.z+Q.z; at+=P.w+Q.w;

      float4 sh = *(float4*)(shS + k*4);
      const float* tp  = g_T + nid[k]*384 + lane*12;
      const float* upt = g_U + njd[k]*384 + lane*12;
      float4 t0=*(const float4*)tp,  t1=*(const float4*)(tp+4),  t2=*(const float4*)(tp+8);
      float4 u0=*(const float4*)upt, u1=*(const float4*)(upt+4), u2=*(const float4*)(upt+8);
      float s0x=t0.x+u0.x, s0y=t0.y+u0.y, s0z=t0.z+u0.z, s0w=t0.w+u0.w;
      float s1x=t1.x+u1.x, s1y=t1.y+u1.y, s1z=t1.z+u1.z, s1w=t1.w+u1.w;
      float s2x=t2.x+u2.x, s2y=t2.y+u2.y, s2z=t2.z+u2.z, s2w=t2.w+u2.w;
      b0 += inv3*(s0x*sh.y + s0y*sh.z + s0z*sh.w);
      b1 += inv3*(s0w*sh.y + s1x*sh.z + s1y*sh.w);
      bg += inv3*(s1z*sh.y + s1w*sh.z + s2x*sh.w);
      r0 += s2y; r1 += s2z; r2 += s2w;

      float zs0=(sh.x*a0+b0)*invfan, zs1=(sh.x*a1+b1)*invfan;
      float zg =(sh.x*ag+bg)*invfan;
      const float* wm = g_wmlp + e*96;
      float2 wm01 = *(const float2*)(wm+2*lane);
      float wmv = wm[64+lane];
      zs0 = zs0*sig_(zs0)*wm01.x;
      zs1 = zs1*sig_(zs1)*wm01.y;
      float gv = sig_(zg)*wmv*invfan;
      int n = nid[k];
      atomicAdd((float2*)(g_accs + n*64 + 2*lane), make_float2(zs0, zs1));
      atomicAdd(&g_accv4[n*32+lane],
                make_float4((at*sh.y + r0*sh.x)*gv,
                            (at*sh.z + r1*sh.x)*gv,
                            (at*sh.w + r2*sh.x)*gv, 0.f));
    }
    __syncwarp();
  }
}

// ---------------- node post ----------------
__global__ void __launch_bounds__(512) k_node_post(const int* __restrict__ batch,
   const float* __restrict__ ppWs, const float* __restrict__ ppbs,
   const float* __restrict__ ppWv){
  extern __shared__ float sm[];
  float2* WsS = (float2*)sm;
  float* WvS = sm+4096;
  float* bsS = sm+5120;
  float* stage = sm+5184;
  for (int i=threadIdx.x;i<4096;i+=blockDim.x) sm[i]=ppWs[i];
  for (int i=threadIdx.x;i<1024;i+=blockDim.x) WvS[i]=ppWv[i];
  for (int i=threadIdx.x;i<64;i+=blockDim.x) bsS[i]=ppbs[i];
  __syncthreads();
  int warp=threadIdx.x>>5, lane=threadIdx.x&31, wpb=blockDim.x>>5;
  float*  sS  = stage + warp*192;
  float4* vS  = (float4*)(sS+64);
  for (int n=blockIdx.x*wpb+warp; n<NN; n+=gridDim.x*wpb){
    sS[lane]=g_accs[n*64+lane]; sS[32+lane]=g_accs[n*64+32+lane];
    vS[lane]=g_accv4[n*32+lane];
    __syncwarp();
    float a0=0.f,a1=0.f;
    #pragma unroll 4
    for (int u=0;u<64;u++){
      float x=sS[u]; float2 w=WsS[u*32+lane];
      a0+=x*w.x; a1+=x*w.y;
    }
    float ns0 = a0*0.125f + bsS[2*lane]   + g_scs[n*64+2*lane];
    float ns1 = a1*0.125f + bsS[2*lane+1] + g_scs[n*64+2*lane+1];
    g_ns[n*64+2*lane]=ns0; g_ns[n*64+2*lane+1]=ns1;
    float vx=0.f,vy=0.f,vz=0.f;
    #pragma unroll 4
    for (int u=0;u<32;u++){
      float4 x=vS[u]; float w=WvS[u*32+lane];
      vx+=x.x*w; vy+=x.y*w; vz+=x.z*w;
    }
    float nv0 = vx*0.17677670f + g_scv[n*96+3*lane];
    float nv1 = vy*0.17677670f + g_scv[n*96+3*lane+1];
    float nv2 = vz*0.17677670f + g_scv[n*96+3*lane+2];
    g_nv[n*96+3*lane]=nv0; g_nv[n*96+3*lane+1]=nv1; g_nv[n*96+3*lane+2]=nv2;
    float m = ns0+ns1;
    float q = ns0*ns0+ns1*ns1;
    float pw = nv0*nv0+nv1*nv1+nv2*nv2;
    #pragma unroll
    for (int off=16;off>0;off>>=1){
      m += __shfl_down_sync(0xffffffffu, m, off);
      q += __shfl_down_sync(0xffffffffu, q, off);
      pw += __shfl_down_sync(0xffffffffu, pw, off);
    }
    if (lane==0){
      int g = batch[n];
      atomicAdd(&g_gstat[g],        m*(1.f/64.f));
      atomicAdd(&g_gstat[NG_+g],    q*(1.f/64.f));
      atomicAdd(&g_gstat[2*NG_+g],  pw*(1.f/96.f));
      atomicAdd(&g_gstat[3*NG_+g],  1.f);
    }
    __syncwarp();
  }
}

// ---------------- group finalize ----------------
__global__ void k_groups(){
  int t = threadIdx.x;
  if (t < NG_){
    float c  = fmaxf(g_gstat[3*NG_+t], 1.f);
    float mu = g_gstat[t]/c;
    float vs = g_gstat[NG_+t]/c - mu*mu;
    float vv = g_gstat[2*NG_+t]/c;
    g_gout[t]       = mu;
    g_gout[NG_+t]   = rsqrtf(vs+1e-5f);
    g_gout[2*NG_+t] = rsqrtf(vv+1e-5f);
  }
}

// ---------------- apply norm + residual ----------------
__global__ void k_out(const float* __restrict__ nf, const int* __restrict__ batch,
   const float* __restrict__ lnws, const float* __restrict__ lnbs,
   const float* __restrict__ lnwv, float* __restrict__ out){
  int i = blockIdx.x*blockDim.x+threadIdx.x;
  if (i >= NN*160) return;
  int n = i/160, c = i - n*160;
  int g = batch[n];
  float base = nf[i];
  float o;
  if (c < 64){
    float x = (g_ns[n*64+c] - g_gout[g]) * g_gout[NG_+g];
    o = base + x*lnws[c] + lnbs[c];
  } else {
    int cc = c-64;
    o = base + g_nv[n*96+cc]*g_gout[2*NG_+g]*lnwv[cc/3];
  }
  out[i]=o;
}

// ---------------- launcher ----------------
extern "C" void kernel_launch(void* const* d_in, const int* in_sizes, int n_in,
                              void* d_out, int out_size){
  const float* nf   =(const float*)d_in[0];
  const float* oh   =(const float*)d_in[1];
  const float* esh  =(const float*)d_in[2];
  const float* efea =(const float*)d_in[3];
  const float* ele  =(const float*)d_in[4];
  const int*   eidx =(const int*)d_in[5];
  const int*   batch=(const int*)d_in[6];
  const float* lpWs =(const float*)d_in[7];
  const float* lpbs =(const float*)d_in[8];
  const float* lpWv =(const float*)d_in[9];
  const float* ppWs =(const float*)d_in[10];
  const float* ppbs =(const float*)d_in[11];
  const float* ppWv =(const float*)d_in[12];
  const float* scWs =(const float*)d_in[13];
  const float* scWv =(const float*)d_in[14];
  const float* Wss0 =(const float*)d_in[15];
  const float* Wvv0 =(const float*)d_in[16];
  const float* Wssg =(const float*)d_in[17];
  const float* Wvvg =(const float*)d_in[18];
  const float* Wsv1 =(const float*)d_in[19];
  const float* Wvs1 =(const float*)d_in[20];
  const float* fcW1 =(const float*)d_in[21];
  const float* fcb1 =(const float*)d_in[22];
  const float* fcW2 =(const float*)d_in[23];
  const float* fcb2 =(const float*)d_in[24];
  const float* fcW3 =(const float*)d_in[25];
  const float* fcb3 =(const float*)d_in[26];
  const float* lnws =(const float*)d_in[27];
  const float* lnbs =(const float*)d_in[28];
  const float* lnwv =(const float*)d_in[29];
  float* out = (float*)d_out;

  const int SM_PRE  = (25664 + 16*192)*4;    // 114944
  const int SM_PSTV = (24576 + 16*1024)*4;   // 163840
  const int SM_MLP  = (18656 + 16*2304)*4;   // 222080
  const int SM_E12  = (14336 + 16*2720)*4;   // 231424
  const int SM_POST = (5184  + 16*192)*4;    // 33024
  cudaFuncSetAttribute(k_node_pre,  cudaFuncAttributeMaxDynamicSharedMemorySize, SM_PRE);
  cudaFuncSetAttribute(k_pstv,      cudaFuncAttributeMaxDynamicSharedMemorySize, SM_PSTV);
  cudaFuncSetAttribute(k_mlp,       cudaFuncAttributeMaxDynamicSharedMemorySize, SM_MLP);
  cudaFuncSetAttribute(k_e12,       cudaFuncAttributeMaxDynamicSharedMemorySize, SM_E12);
  cudaFuncSetAttribute(k_node_post, cudaFuncAttributeMaxDynamicSharedMemorySize, SM_POST);

  k_zero<<<(NN*192 + 4*NG_ + 255)/256, 256>>>();
  k_node_pre<<<148, 512, SM_PRE>>>(nf, oh, lpWs, lpbs, lpWv, scWs, scWv);
  k_pstv<<<148, 512, SM_PSTV>>>(Wss0, Wssg, Wsv1, Wvv0, Wvvg, Wvs1);
  k_mlp<<<148, 512, SM_MLP>>>(ele, fcW1, fcb1, fcW2, fcb2, fcW3, fcb3);
  k_e12<<<148, 512, SM_E12>>>(eidx, esh, efea, Wss0, Wssg, Wsv1, Wvv0, Wvvg, Wvs1);
  k_node_post<<<148, 512, SM_POST>>>(batch, ppWs, ppbs, ppWv);
  k_groups<<<1, 32>>>();
  k_out<<<(NN*160 + 255)/256, 256>>>(nf, batch, lnws, lnbs, lnwv, out);
}

// round 8
// speedup vs baseline: 1.0527x; 1.0049x over previous
#include <cuda_runtime.h>

#define NN 10000
#define EE 320000
#define NG_ 16

// ---------------- scratch (static device memory; no allocations) ----------------
__device__ float  g_s[NN*64];
__device__ float4 g_v4[NN*32];
__device__ float  g_scs[NN*64];
__device__ float  g_scv[NN*96];
__device__ float  g_accs[NN*64];
__device__ float4 g_accv4[NN*32];            // (x,y,z,pad) per lane
__device__ float  g_ns[NN*64];
__device__ float  g_nv[NN*96];
__device__ float  g_wmlp[(long long)EE*96];
__device__ float  g_P[NN*128];               // s@F1[0:64]   (i-role), lane*4 layout
__device__ float  g_Q[NN*128];               // s@F1[64:128] (j-role)
__device__ float  g_T[NN*384];               // v x F2[0:32]  (i-role), lane*12 layout
__device__ float  g_U[NN*384];               // v x F2[32:64] (j-role)
__device__ float  g_gstat[4*NG_];
__device__ float  g_gout[3*NG_];

__device__ __forceinline__ float sig_(float x){ return 1.f/(1.f+__expf(-x)); }

// ---- f32x2 packed math helpers (sm_103a FFMA2 via PTX) ----
__device__ __forceinline__ unsigned long long pk2(float x){
  unsigned long long r; asm("mov.b64 %0, {%1, %1};" : "=l"(r) : "f"(x)); return r; }
__device__ __forceinline__ unsigned long long pkab(float a, float b){
  unsigned long long r; asm("mov.b64 %0, {%1, %2};" : "=l"(r) : "f"(a), "f"(b)); return r; }
__device__ __forceinline__ void up2(unsigned long long v, float &a, float &b){
  asm("mov.b64 {%0, %1}, %2;" : "=f"(a), "=f"(b) : "l"(v)); }
__device__ __forceinline__ void fma2(unsigned long long &d, unsigned long long a, unsigned long long b){
  asm("fma.rn.f32x2 %0, %1, %2, %3;" : "=l"(d) : "l"(a), "l"(b), "l"(d)); }

// ---------------- zero accumulators ----------------
__global__ void k_zero(){
  int i = blockIdx.x*blockDim.x + threadIdx.x;
  if (i < NN*64) g_accs[i] = 0.f;
  int j = i - NN*64;
  if (j >= 0 && j < NN*128) ((float*)g_accv4)[j] = 0.f;
  int k = i - NN*192;
  if (k >= 0 && k < 4*NG_) g_gstat[k] = 0.f;
}

// ---------------- node pre ----------------
__global__ void __launch_bounds__(512) k_node_pre(const float* __restrict__ nf,
                           const float* __restrict__ oh,
                           const float* __restrict__ lpWs, const float* __restrict__ lpbs,
                           const float* __restrict__ lpWv,
                           const float* __restrict__ scWs, const float* __restrict__ scWv){
  extern __shared__ float sm[];
  float2* WsS  = (float2*)sm;
  float*  WvS  = sm + 4096;
  float2* sWsS = (float2*)(sm + 5120);
  float*  sWvS = sm + 21504;
  float*  bsS  = sm + 25600;
  float*  stage= sm + 25664;

  for (int i=threadIdx.x;i<4096;i+=blockDim.x) sm[i]=lpWs[i];
  for (int i=threadIdx.x;i<1024;i+=blockDim.x) WvS[i]=lpWv[i];
  for (int i=threadIdx.x;i<16384;i+=blockDim.x) sm[5120+i]=scWs[i];
  for (int i=threadIdx.x;i<4096;i+=blockDim.x) sWvS[i]=scWv[i];
  for (int i=threadIdx.x;i<64;i+=blockDim.x) bsS[i]=lpbs[i];
  __syncthreads();

  int warp = threadIdx.x>>5, lane = threadIdx.x&31, wpb = blockDim.x>>5;
  float*  sS  = stage + warp*192;
  float4* vS  = (float4*)(sS + 64);

  for (int n = blockIdx.x*wpb + warp; n < NN; n += gridDim.x*wpb){
    const float* row = nf + n*160;
    sS[lane] = row[lane]; sS[32+lane] = row[32+lane];
    vS[lane] = make_float4(row[64+3*lane], row[65+3*lane], row[66+3*lane], 0.f);
    const float* o4 = oh + n*4;
    int sp = (o4[1]>0.5f)?1:((o4[2]>0.5f)?2:((o4[3]>0.5f)?3:0));
    __syncwarp();

    float a0=0.f,a1=0.f,c0=0.f,c1=0.f;
    #pragma unroll 4
    for (int u=0;u<64;u++){
      float x = sS[u];
      float2 w  = WsS[u*32+lane];
      float2 w2 = sWsS[(u*4+sp)*32+lane];
      a0+=x*w.x; a1+=x*w.y; c0+=x*w2.x; c1+=x*w2.y;
    }
    g_s[n*64+2*lane]   = a0*0.125f + bsS[2*lane];
    g_s[n*64+2*lane+1] = a1*0.125f + bsS[2*lane+1];
    g_scs[n*64+2*lane]   = c0*0.0625f;
    g_scs[n*64+2*lane+1] = c1*0.0625f;

    float vx=0.f,vy=0.f,vz=0.f,cx=0.f,cy=0.f,cz=0.f;
    #pragma unroll 4
    for (int u=0;u<32;u++){
      float4 x = vS[u];
      float w  = WvS[u*32+lane];
      float w2 = sWvS[(u*4+sp)*32+lane];
      vx+=x.x*w;  vy+=x.y*w;  vz+=x.z*w;
      cx+=x.x*w2; cy+=x.y*w2; cz+=x.z*w2;
    }
    g_v4[n*32+lane] = make_float4(vx*0.17677670f, vy*0.17677670f, vz*0.17677670f, 0.f);
    g_scv[n*96+3*lane]   = cx*0.08838835f;
    g_scv[n*96+3*lane+1] = cy*0.08838835f;
    g_scv[n*96+3*lane+2] = cz*0.08838835f;
    __syncwarp();
  }
}

// ---------------- per-node P/Q (phase 1) and T/U (phase 2), merged ----------------
__global__ void __launch_bounds__(512) k_pstv(const float* __restrict__ Wss0,
   const float* __restrict__ Wssg, const float* __restrict__ Wsv1,
   const float* __restrict__ Wvv0, const float* __restrict__ Wvvg,
   const float* __restrict__ Wvs1){
  extern __shared__ float sm[];
  float4* FA = (float4*)sm;            // F1 rows 0..63:  64x32 f4
  float4* FB = (float4*)(sm+8192);     // F1 rows 64..127
  float4* GA = (float4*)(sm+16384);    // F2 rows 0..31
  float4* GB = (float4*)(sm+20480);    // F2 rows 32..63
  float* stage = sm + 24576;           // per warp 1024 f

  for (int i=threadIdx.x;i<2048;i+=blockDim.x){
    int u=i>>5, l=i&31;
    FA[i]=make_float4(Wss0[u*64+2*l], Wss0[u*64+2*l+1], Wssg[u*32+l], Wsv1[u*32+l]);
    int u2=u+64;
    FB[i]=make_float4(Wss0[u2*64+2*l], Wss0[u2*64+2*l+1], Wssg[u2*32+l], Wsv1[u2*32+l]);
  }
  for (int i=threadIdx.x;i<1024;i+=blockDim.x){
    int u=i>>5, l=i&31;
    GA[i]=make_float4(Wvv0[u*64+2*l], Wvv0[u*64+2*l+1], Wvvg[u*32+l], Wvs1[u*32+l]);
    int u2=u+32;
    GB[i]=make_float4(Wvv0[u2*64+2*l], Wvv0[u2*64+2*l+1], Wvvg[u2*32+l], Wvs1[u2*32+l]);
  }
  __syncthreads();

  int warp=threadIdx.x>>5, lane=threadIdx.x&31, wpb=blockDim.x>>5;
  float* sd = stage + warp*1024;

  // ---- phase 1: P/Q, 8 nodes/warp ----
  const int b1 = NN/8;
  for (int p = blockIdx.x*wpb+warp; p<b1; p+=gridDim.x*wpb){
    int n0 = p*8;
    #pragma unroll
    for (int k=0;k<8;k++){
      int n = n0+k;
      float x0 = g_s[n*64+lane];
      float x1 = g_s[n*64+32+lane];
      *(unsigned long long*)(sd + k*128 + 2*lane)      = pkab(x0,x0);
      *(unsigned long long*)(sd + k*128 + 64 + 2*lane) = pkab(x1,x1);
    }
    __syncwarp();

    unsigned long long pa[8], pg[8], qa[8], qg[8];
    #pragma unroll
    for (int k=0;k<8;k++){ pa[k]=0ull; pg[k]=0ull; qa[k]=0ull; qg[k]=0ull; }
    #pragma unroll 2
    for (int u=0;u<64;u+=2){
      ulonglong2 wa0 = *(ulonglong2*)&FA[(u  )*32+lane];
      ulonglong2 wa1 = *(ulonglong2*)&FA[(u+1)*32+lane];
      ulonglong2 wb0 = *(ulonglong2*)&FB[(u  )*32+lane];
      ulonglong2 wb1 = *(ulonglong2*)&FB[(u+1)*32+lane];
      #pragma unroll
      for (int k=0;k<8;k++){
        ulonglong2 xp = *(ulonglong2*)(sd + k*128 + 2*u);
        fma2(pa[k], xp.x, wa0.x); fma2(pg[k], xp.x, wa0.y);
        fma2(qa[k], xp.x, wb0.x); fma2(qg[k], xp.x, wb0.y);
        fma2(pa[k], xp.y, wa1.x); fma2(pg[k], xp.y, wa1.y);
        fma2(qa[k], xp.y, wb1.x); fma2(qg[k], xp.y, wb1.y);
      }
    }
    #pragma unroll
    for (int k=0;k<8;k++){
      int n = n0+k;
      float a0,a1,ag,at;
      up2(pa[k],a0,a1); up2(pg[k],ag,at);
      *(float4*)(g_P + n*128 + lane*4) = make_float4(a0,a1,ag,at);
      up2(qa[k],a0,a1); up2(qg[k],ag,at);
      *(float4*)(g_Q + n*128 + lane*4) = make_float4(a0,a1,ag,at);
    }
    __syncwarp();
  }

  // ---- phase 2: T/U, 4 nodes/warp ----
  float4* vst = (float4*)sd;
  const int b2 = NN/4;
  for (int p = blockIdx.x*wpb+warp; p<b2; p+=gridDim.x*wpb){
    int n0 = p*4;
    #pragma unroll
    for (int k=0;k<4;k++) vst[k*32+lane] = g_v4[(n0+k)*32+lane];
    __syncwarp();

    unsigned long long t01[4][3], tgr[4][3], u01[4][3], ugr[4][3];
    #pragma unroll
    for (int k=0;k<4;k++)
      #pragma unroll
      for (int c=0;c<3;c++){ t01[k][c]=0ull; tgr[k][c]=0ull; u01[k][c]=0ull; ugr[k][c]=0ull; }

    #pragma unroll 2
    for (int u=0;u<32;u++){
      ulonglong2 ga = *(ulonglong2*)&GA[u*32+lane];
      ulonglong2 gb = *(ulonglong2*)&GB[u*32+lane];
      #pragma unroll
      for (int k=0;k<4;k++){
        float4 v = vst[k*32+u];
        unsigned long long vx=pk2(v.x), vy=pk2(v.y), vz=pk2(v.z);
        fma2(t01[k][0], vx, ga.x); fma2(t01[k][1], vy, ga.x); fma2(t01[k][2], vz, ga.x);
        fma2(tgr[k][0], vx, ga.y); fma2(tgr[k][1], vy, ga.y); fma2(tgr[k][2], vz, ga.y);
        fma2(u01[k][0], vx, gb.x); fma2(u01[k][1], vy, gb.x); fma2(u01[k][2], vz, gb.x);
        fma2(ugr[k][0], vx, gb.y); fma2(ugr[k][1], vy, gb.y); fma2(ugr[k][2], vz, gb.y);
      }
    }
    #pragma unroll
    for (int k=0;k<4;k++){
      int n = n0+k;
      float b0x,b1x,b0y,b1y,b0z,b1z,bgx,rx,bgy,ry,bgz,rz;
      up2(t01[k][0],b0x,b1x); up2(t01[k][1],b0y,b1y); up2(t01[k][2],b0z,b1z);
      up2(tgr[k][0],bgx,rx);  up2(tgr[k][1],bgy,ry);  up2(tgr[k][2],bgz,rz);
      float* o = g_T + n*384 + lane*12;
      *(float4*)(o  ) = make_float4(b0x,b0y,b0z,b1x);
      *(float4*)(o+4) = make_float4(b1y,b1z,bgx,bgy);
      *(float4*)(o+8) = make_float4(bgz,rx,ry,rz);
      up2(u01[k][0],b0x,b1x); up2(u01[k][1],b0y,b1y); up2(u01[k][2],b0z,b1z);
      up2(ugr[k][0],bgx,rx);  up2(ugr[k][1],bgy,ry);  up2(ugr[k][2],bgz,rz);
      o = g_U + n*384 + lane*12;
      *(float4*)(o  ) = make_float4(b0x,b0y,b0z,b1x);
      *(float4*)(o+4) = make_float4(b1y,b1z,bgx,bgy);
      *(float4*)(o+8) = make_float4(bgz,rx,ry,rz);
    }
    __syncwarp();
  }
}

// ---------------- per-edge MLP (128->64->64->96), 9 edges/warp, f32x2 ----------------
__global__ void __launch_bounds__(512) k_mlp(const float* __restrict__ ele,
   const float* __restrict__ W1, const float* __restrict__ b1,
   const float* __restrict__ W2, const float* __restrict__ b2,
   const float* __restrict__ W3, const float* __restrict__ b3){
  extern __shared__ float sm[];
  // W1S: [0,8192) ; W2S: [8192,12288) ; W3p: [12288,16384) ; W3s: [16384,18432)
  float* b1S = sm+18432; float* b2S = sm+18496; float* b3S = sm+18560;
  float* stage = sm+18656;   // per warp 2304 f : 9 edges x 256 (e:128, h:64, g:64)

  for (int i=threadIdx.x;i<8192;i+=blockDim.x) sm[i]=W1[i];
  for (int i=threadIdx.x;i<4096;i+=blockDim.x) sm[8192+i]=W2[i];
  for (int i=threadIdx.x;i<2048;i+=blockDim.x){
    int j=i>>5, l=i&31;
    ((float2*)(sm+12288))[i] = make_float2(W3[j*96+l], W3[j*96+32+l]);
    sm[16384+i] = W3[j*96+64+l];
  }
  for (int i=threadIdx.x;i<64;i+=blockDim.x){ b1S[i]=b1[i]; b2S[i]=b2[i]; }
  for (int i=threadIdx.x;i<96;i+=blockDim.x) b3S[i]=b3[i];
  __syncthreads();

  int warp=threadIdx.x>>5, lane=threadIdx.x&31, wpb=blockDim.x>>5;
  float* st = stage + warp*2304;

  unsigned long long bias1 = pkab(b1S[2*lane], b1S[2*lane+1]);
  unsigned long long bias2 = pkab(b2S[2*lane], b2S[2*lane+1]);
  unsigned long long bias3 = pkab(b3S[lane],   b3S[32+lane]);
  float bias3s = b3S[64+lane];

  const int batches = (EE+8)/9;
  for (int p = blockIdx.x*wpb+warp; p<batches; p+=gridDim.x*wpb){
    long long e0 = 9LL*p;
    #pragma unroll
    for (int k=0;k<9;k++){
      long long e = e0+k;
      float* eE = st + k*256;
      if (e < EE){
        const float* r = ele + e*128;
        #pragma unroll
        for (int c=0;c<4;c++) eE[c*32+lane]=r[c*32+lane];
      } else {
        #pragma unroll
        for (int c=0;c<4;c++) eE[c*32+lane]=0.f;
      }
    }
    __syncwarp();

    // ---- layer 1: 128 -> 64 ----
    unsigned long long acc[9];
    #pragma unroll
    for (int k=0;k<9;k++) acc[k]=bias1;
    #pragma unroll 2
    for (int j=0;j<128;j+=4){
      unsigned long long w0=*(unsigned long long*)(sm+ (j  )*64 + 2*lane);
      unsigned long long w1=*(unsigned long long*)(sm+ (j+1)*64 + 2*lane);
      unsigned long long w2=*(unsigned long long*)(sm+ (j+2)*64 + 2*lane);
      unsigned long long w3=*(unsigned long long*)(sm+ (j+3)*64 + 2*lane);
      #pragma unroll
      for (int k=0;k<9;k++){
        float4 x = *(float4*)(st + k*256 + j);
        fma2(acc[k], pk2(x.x), w0);
        fma2(acc[k], pk2(x.y), w1);
        fma2(acc[k], pk2(x.z), w2);
        fma2(acc[k], pk2(x.w), w3);
      }
    }
    #pragma unroll
    for (int k=0;k<9;k++){
      float a0,a1; up2(acc[k],a0,a1);
      float* hE = st + k*256 + 128;
      hE[2*lane]=a0*sig_(a0); hE[2*lane+1]=a1*sig_(a1);
    }
    __syncwarp();

    // ---- layer 2: 64 -> 64 ----
    #pragma unroll
    for (int k=0;k<9;k++) acc[k]=bias2;
    #pragma unroll 2
    for (int j=0;j<64;j+=4){
      unsigned long long w0=*(unsigned long long*)(sm+8192+(j  )*64 + 2*lane);
      unsigned long long w1=*(unsigned long long*)(sm+8192+(j+1)*64 + 2*lane);
      unsigned long long w2=*(unsigned long long*)(sm+8192+(j+2)*64 + 2*lane);
      unsigned long long w3=*(unsigned long long*)(sm+8192+(j+3)*64 + 2*lane);
      #pragma unroll
      for (int k=0;k<9;k++){
        float4 x = *(float4*)(st + k*256 + 128 + j);
        fma2(acc[k], pk2(x.x), w0);
        fma2(acc[k], pk2(x.y), w1);
        fma2(acc[k], pk2(x.z), w2);
        fma2(acc[k], pk2(x.w), w3);
      }
    }
    #pragma unroll
    for (int k=0;k<9;k++){
      float a0,a1; up2(acc[k],a0,a1);
      float* gE = st + k*256 + 192;
      gE[2*lane]=a0*sig_(a0); gE[2*lane+1]=a1*sig_(a1);
    }
    __syncwarp();

    // ---- layer 3: 64 -> 96 ----
    unsigned long long c01[9]; float c2[9];
    #pragma unroll
    for (int k=0;k<9;k++){ c01[k]=bias3; c2[k]=bias3s; }
    #pragma unroll 2
    for (int j=0;j<64;j+=4){
      unsigned long long p0=*(unsigned long long*)(sm+12288+(j  )*64 + 2*lane);
      unsigned long long p1=*(unsigned long long*)(sm+12288+(j+1)*64 + 2*lane);
      unsigned long long p2=*(unsigned long long*)(sm+12288+(j+2)*64 + 2*lane);
      unsigned long long p3=*(unsigned long long*)(sm+12288+(j+3)*64 + 2*lane);
      float s0=sm[16384+(j  )*32+lane];
      float s1=sm[16384+(j+1)*32+lane];
      float s2=sm[16384+(j+2)*32+lane];
      float s3=sm[16384+(j+3)*32+lane];
      #pragma unroll
      for (int k=0;k<9;k++){
        float4 x = *(float4*)(st + k*256 + 192 + j);
        fma2(c01[k], pk2(x.x), p0); c2[k]+=x.x*s0;
        fma2(c01[k], pk2(x.y), p1); c2[k]+=x.y*s1;
        fma2(c01[k], pk2(x.z), p2); c2[k]+=x.z*s2;
        fma2(c01[k], pk2(x.w), p3); c2[k]+=x.w*s3;
      }
    }
    #pragma unroll
    for (int k=0;k<9;k++){
      long long e = e0+k;
      if (e >= EE) continue;
      float a,b; up2(c01[k],a,b);
      float* wo = g_wmlp + e*96;
      wo[lane]=a; wo[32+lane]=b; wo[64+lane]=c2[k];
    }
    __syncwarp();
  }
}

// ---------------- fused edge kernel: es+ev GEMVs + epilogue + scatter, 7 edges/warp ----------------
__global__ void __launch_bounds__(512) k_e12(const int* __restrict__ eidx,
   const float* __restrict__ esh, const float* __restrict__ efea,
   const float* __restrict__ Wss0, const float* __restrict__ Wssg,
   const float* __restrict__ Wsv1,
   const float* __restrict__ Wvv0, const float* __restrict__ Wvvg,
   const float* __restrict__ Wvs1){
  extern __shared__ float sm[];
  float4* FC = (float4*)sm;                               // F1 rows 128..191: 8192 f
  ulonglong2* W2a = (ulonglong2*)(sm+8192);               // F2 rows 64..95: 4096 f
  unsigned long long* W2b = (unsigned long long*)(sm+12288); // 2048 f
  float* stage = sm + 14336;                              // per warp 2720 f

  for (int i=threadIdx.x;i<2048;i+=blockDim.x){
    int u=(i>>5)+128, l=i&31;
    FC[i]=make_float4(Wss0[u*64+2*l], Wss0[u*64+2*l+1], Wssg[u*32+l], Wsv1[u*32+l]);
  }
  for (int i=threadIdx.x;i<1024;i+=blockDim.x){
    int u=(i>>5)+64, l=i&31;
    float w0=Wvv0[u*64+2*l], w1=Wvv0[u*64+2*l+1];
    float wz=Wvvg[u*32+l],   ww=Wvs1[u*32+l];
    W2a[i] = make_ulonglong2(pkab(w0,w1), pkab(wz,ww));
    W2b[i] = pkab(ww,ww);
  }
  __syncthreads();

  int warp=threadIdx.x>>5, lane=threadIdx.x&31, wpb=blockDim.x>>5;
  float* sd0 = stage + warp*2720;        // 7 x 128 dup-es
  float* vd  = sd0 + 896;                // 7 x 256 (8 f/lane)
  float* shS = sd0 + 2688;               // 7 x 4 (+pad)
  const float inv3 = 0.57735027f, invfan = 0.058925565f;
  const int batches = (EE+6)/7;

  for (int p = blockIdx.x*wpb+warp; p<batches; p+=gridDim.x*wpb){
    int e0 = p*7;
    int nid[7], njd[7];
    #pragma unroll
    for (int k=0;k<7;k++){
      int e = e0+k;
      if (e < EE){
        nid[k]=eidx[e]; njd[k]=eidx[EE+e];
        float4 sh = *(const float4*)(esh + (long long)e*4);
        if (lane==0) *(float4*)(shS + k*4) = sh;
        const float* r = efea + (long long)e*160;
        float x0=r[lane], x1=r[32+lane];
        *(unsigned long long*)(sd0 + k*128 + 2*lane)      = pkab(x0,x0);
        *(unsigned long long*)(sd0 + k*128 + 64 + 2*lane) = pkab(x1,x1);
        float ex=r[64+3*lane], ey=r[65+3*lane], ez=r[66+3*lane];
        float dd=(ex*sh.y+ey*sh.z+ez*sh.w)*inv3;
        float* o = vd + k*256 + lane*8;
        *(float4*)o     = make_float4(dd,dd,ex,ey);
        *(float2*)(o+4) = make_float2(dd,ez);
      } else {
        nid[k]=-1; njd[k]=0;
        *(unsigned long long*)(sd0 + k*128 + 2*lane)      = 0ull;
        *(unsigned long long*)(sd0 + k*128 + 64 + 2*lane) = 0ull;
        float* o = vd + k*256 + lane*8;
        *(float4*)o     = make_float4(0.f,0.f,0.f,0.f);
        *(float2*)(o+4) = make_float2(0.f,0.f);
        if (lane==0) *(float4*)(shS + k*4) = make_float4(0.f,0.f,0.f,0.f);
      }
    }
    __syncwarp();

    // ---- GEMV 1: es @ F1[128:192] ----
    unsigned long long a01[7], agt[7];
    #pragma unroll
    for (int k=0;k<7;k++){ a01[k]=0ull; agt[k]=0ull; }
    #pragma unroll 2
    for (int u=0;u<64;u+=2){
      ulonglong2 w0 = *(ulonglong2*)&FC[(u  )*32+lane];
      ulonglong2 w1 = *(ulonglong2*)&FC[(u+1)*32+lane];
      #pragma unroll
      for (int k=0;k<7;k++){
        ulonglong2 xp = *(ulonglong2*)(sd0 + k*128 + 2*u);
        fma2(a01[k], xp.x, w0.x); fma2(agt[k], xp.x, w0.y);
        fma2(a01[k], xp.y, w1.x); fma2(agt[k], xp.y, w1.y);
      }
    }

    // ---- GEMV 2: ev rows @ F2[64:96] ----
    unsigned long long b01[7], r01[7], gz2[7];
    #pragma unroll
    for (int k=0;k<7;k++){ b01[k]=0ull; r01[k]=0ull; gz2[k]=0ull; }
    #pragma unroll 4
    for (int u=0;u<32;u++){
      ulonglong2 wa = W2a[u*32+lane];
      unsigned long long wb = W2b[u*32+lane];
      #pragma unroll
      for (int k=0;k<7;k++){
        ulonglong2 t1 = *(ulonglong2*)(vd + k*256 + u*8);
        unsigned long long t2 = *(unsigned long long*)(vd + k*256 + u*8 + 4);
        fma2(b01[k], t1.x, wa.x);
        fma2(r01[k], t1.y, wb);
        fma2(gz2[k], t2,   wa.y);
      }
    }

    // ---- epilogue + scatter ----
    #pragma unroll
    for (int k=0;k<7;k++){
      if (nid[k] < 0) continue;
      long long e = e0+k;
      float a0,a1,ag,at,b0,b1,r0,r1,bg,r2;
      up2(a01[k],a0,a1); up2(agt[k],ag,at);
      up2(b01[k],b0,b1); up2(r01[k],r0,r1); up2(gz2[k],bg,r2);
      float4 P = *(const float4*)(g_P + nid[k]*128 + lane*4);
      float4 Q = *(const float4*)(g_Q + njd[k]*128 + lane*4);
      a0+=P.x+Q.x; a1+=P.y+Q.y; ag+=P.z+Q.z; at+=P.w+Q.w;

      float4 sh = *(float4*)(shS + k*4);
      const float* tp  = g_T + nid[k]*384 + lane*12;
      const float* upt = g_U + njd[k]*384 + lane*12;
      float4 t0=*(const float4*)tp,  t1=*(const float4*)(tp+4),  t2=*(const float4*)(tp+8);
      float4 u0=*(const float4*)upt, u1=*(const float4*)(upt+4), u2=*(const float4*)(upt+8);
      float s0x=t0.x+u0.x, s0y=t0.y+u0.y, s0z=t0.z+u0.z, s0w=t0.w+u0.w;
      float s1x=t1.x+u1.x, s1y=t1.y+u1.y, s1z=t1.z+u1.z, s1w=t1.w+u1.w;
      float s2x=t2.x+u2.x, s2y=t2.y+u2.y, s2z=t2.z+u2.z, s2w=t2.w+u2.w;
      b0 += inv3*(s0x*sh.y + s0y*sh.z + s0z*sh.w);
      b1 += inv3*(s0w*sh.y + s1x*sh.z + s1y*sh.w);
      bg += inv3*(s1z*sh.y + s1w*sh.z + s2x*sh.w);
      r0 += s2y; r1 += s2z; r2 += s2w;

      float zs0=(sh.x*a0+b0)*invfan, zs1=(sh.x*a1+b1)*invfan;
      float zg =(sh.x*ag+bg)*invfan;
      const float* wm = g_wmlp + e*96;
      float2 wm01 = *(const float2*)(wm+2*lane);
      float wmv = wm[64+lane];
      zs0 = zs0*sig_(zs0)*wm01.x;
      zs1 = zs1*sig_(zs1)*wm01.y;
      float gv = sig_(zg)*wmv*invfan;
      int n = nid[k];
      atomicAdd((float2*)(g_accs + n*64 + 2*lane), make_float2(zs0, zs1));
      atomicAdd(&g_accv4[n*32+lane],
                make_float4((at*sh.y + r0*sh.x)*gv,
                            (at*sh.z + r1*sh.x)*gv,
                            (at*sh.w + r2*sh.x)*gv, 0.f));
    }
    __syncwarp();
  }
}

// ---------------- node post ----------------
__global__ void __launch_bounds__(512) k_node_post(const int* __restrict__ batch,
   const float* __restrict__ ppWs, const float* __restrict__ ppbs,
   const float* __restrict__ ppWv){
  extern __shared__ float sm[];
  float2* WsS = (float2*)sm;
  float* WvS = sm+4096;
  float* bsS = sm+5120;
  float* stage = sm+5184;
  for (int i=threadIdx.x;i<4096;i+=blockDim.x) sm[i]=ppWs[i];
  for (int i=threadIdx.x;i<1024;i+=blockDim.x) WvS[i]=ppWv[i];
  for (int i=threadIdx.x;i<64;i+=blockDim.x) bsS[i]=ppbs[i];
  __syncthreads();
  int warp=threadIdx.x>>5, lane=threadIdx.x&31, wpb=blockDim.x>>5;
  float*  sS  = stage + warp*192;
  float4* vS  = (float4*)(sS+64);
  for (int n=blockIdx.x*wpb+warp; n<NN; n+=gridDim.x*wpb){
    sS[lane]=g_accs[n*64+lane]; sS[32+lane]=g_accs[n*64+32+lane];
    vS[lane]=g_accv4[n*32+lane];
    __syncwarp();
    float a0=0.f,a1=0.f;
    #pragma unroll 4
    for (int u=0;u<64;u++){
      float x=sS[u]; float2 w=WsS[u*32+lane];
      a0+=x*w.x; a1+=x*w.y;
    }
    float ns0 = a0*0.125f + bsS[2*lane]   + g_scs[n*64+2*lane];
    float ns1 = a1*0.125f + bsS[2*lane+1] + g_scs[n*64+2*lane+1];
    g_ns[n*64+2*lane]=ns0; g_ns[n*64+2*lane+1]=ns1;
    float vx=0.f,vy=0.f,vz=0.f;
    #pragma unroll 4
    for (int u=0;u<32;u++){
      float4 x=vS[u]; float w=WvS[u*32+lane];
      vx+=x.x*w; vy+=x.y*w; vz+=x.z*w;
    }
    float nv0 = vx*0.17677670f + g_scv[n*96+3*lane];
    float nv1 = vy*0.17677670f + g_scv[n*96+3*lane+1];
    float nv2 = vz*0.17677670f + g_scv[n*96+3*lane+2];
    g_nv[n*96+3*lane]=nv0; g_nv[n*96+3*lane+1]=nv1; g_nv[n*96+3*lane+2]=nv2;
    float m = ns0+ns1;
    float q = ns0*ns0+ns1*ns1;
    float pw = nv0*nv0+nv1*nv1+nv2*nv2;
    #pragma unroll
    for (int off=16;off>0;off>>=1){
      m += __shfl_down_sync(0xffffffffu, m, off);
      q += __shfl_down_sync(0xffffffffu, q, off);
      pw += __shfl_down_sync(0xffffffffu, pw, off);
    }
    if (lane==0){
      int g = batch[n];
      atomicAdd(&g_gstat[g],        m*(1.f/64.f));
      atomicAdd(&g_gstat[NG_+g],    q*(1.f/64.f));
      atomicAdd(&g_gstat[2*NG_+g],  pw*(1.f/96.f));
      atomicAdd(&g_gstat[3*NG_+g],  1.f);
    }
    __syncwarp();
  }
}

// ---------------- group finalize ----------------
__global__ void k_groups(){
  int t = threadIdx.x;
  if (t < NG_){
    float c  = fmaxf(g_gstat[3*NG_+t], 1.f);
    float mu = g_gstat[t]/c;
    float vs = g_gstat[NG_+t]/c - mu*mu;
    float vv = g_gstat[2*NG_+t]/c;
    g_gout[t]       = mu;
    g_gout[NG_+t]   = rsqrtf(vs+1e-5f);
    g_gout[2*NG_+t] = rsqrtf(vv+1e-5f);
  }
}

// ---------------- apply norm + residual ----------------
__global__ void k_out(const float* __restrict__ nf, const int* __restrict__ batch,
   const float* __restrict__ lnws, const float* __restrict__ lnbs,
   const float* __restrict__ lnwv, float* __restrict__ out){
  int i = blockIdx.x*blockDim.x+threadIdx.x;
  if (i >= NN*160) return;
  int n = i/160, c = i - n*160;
  int g = batch[n];
  float base = nf[i];
  float o;
  if (c < 64){
    float x = (g_ns[n*64+c] - g_gout[g]) * g_gout[NG_+g];
    o = base + x*lnws[c] + lnbs[c];
  } else {
    int cc = c-64;
    o = base + g_nv[n*96+cc]*g_gout[2*NG_+g]*lnwv[cc/3];
  }
  out[i]=o;
}

// ---------------- launcher ----------------
extern "C" void kernel_launch(void* const* d_in, const int* in_sizes, int n_in,
                              void* d_out, int out_size){
  const float* nf   =(const float*)d_in[0];
  const float* oh   =(const float*)d_in[1];
  const float* esh  =(const float*)d_in[2];
  const float* efea =(const float*)d_in[3];
  const float* ele  =(const float*)d_in[4];
  const int*   eidx =(const int*)d_in[5];
  const int*   batch=(const int*)d_in[6];
  const float* lpWs =(const float*)d_in[7];
  const float* lpbs =(const float*)d_in[8];
  const float* lpWv =(const float*)d_in[9];
  const float* ppWs =(const float*)d_in[10];
  const float* ppbs =(const float*)d_in[11];
  const float* ppWv =(const float*)d_in[12];
  const float* scWs =(const float*)d_in[13];
  const float* scWv =(const float*)d_in[14];
  const float* Wss0 =(const float*)d_in[15];
  const float* Wvv0 =(const float*)d_in[16];
  const float* Wssg =(const float*)d_in[17];
  const float* Wvvg =(const float*)d_in[18];
  const float* Wsv1 =(const float*)d_in[19];
  const float* Wvs1 =(const float*)d_in[20];
  const float* fcW1 =(const float*)d_in[21];
  const float* fcb1 =(const float*)d_in[22];
  const float* fcW2 =(const float*)d_in[23];
  const float* fcb2 =(const float*)d_in[24];
  const float* fcW3 =(const float*)d_in[25];
  const float* fcb3 =(const float*)d_in[26];
  const float* lnws =(const float*)d_in[27];
  const float* lnbs =(const float*)d_in[28];
  const float* lnwv =(const float*)d_in[29];
  float* out = (float*)d_out;

  const int SM_PRE  = (25664 + 16*192)*4;    // 114944
  const int SM_PSTV = (24576 + 16*1024)*4;   // 163840
  const int SM_MLP  = (18656 + 16*2304)*4;   // 222080
  const int SM_E12  = (14336 + 16*2720)*4;   // 231424
  const int SM_POST = (5184  + 16*192)*4;    // 33024
  cudaFuncSetAttribute(k_node_pre,  cudaFuncAttributeMaxDynamicSharedMemorySize, SM_PRE);
  cudaFuncSetAttribute(k_pstv,      cudaFuncAttributeMaxDynamicSharedMemorySize, SM_PSTV);
  cudaFuncSetAttribute(k_mlp,       cudaFuncAttributeMaxDynamicSharedMemorySize, SM_MLP);
  cudaFuncSetAttribute(k_e12,       cudaFuncAttributeMaxDynamicSharedMemorySize, SM_E12);
  cudaFuncSetAttribute(k_node_post, cudaFuncAttributeMaxDynamicSharedMemorySize, SM_POST);

  k_zero<<<(NN*192 + 4*NG_ + 255)/256, 256>>>();
  k_node_pre<<<148, 512, SM_PRE>>>(nf, oh, lpWs, lpbs, lpWv, scWs, scWv);
  k_pstv<<<148, 512, SM_PSTV>>>(Wss0, Wssg, Wsv1, Wvv0, Wvvg, Wvs1);
  k_mlp<<<148, 512, SM_MLP>>>(ele, fcW1, fcb1, fcW2, fcb2, fcW3, fcb3);
  k_e12<<<148, 512, SM_E12>>>(eidx, esh, efea, Wss0, Wssg, Wsv1, Wvv0, Wvvg, Wvs1);
  k_node_post<<<148, 512, SM_POST>>>(batch, ppWs, ppbs, ppWv);
  k_groups<<<1, 32>>>();
  k_out<<<(NN*160 + 255)/256, 256>>>(nf, batch, lnws, lnbs, lnwv, out);
}

// round 11
// speedup vs baseline: 1.1178x; 1.0618x over previous
#include <cuda_runtime.h>
#include <cuda_bf16.h>
#include <cstdint>

#define NN 10000
#define EE 320000
#define NG_ 16

__device__ float  g_s[NN*64];
__device__ float4 g_v4[NN*32];
__device__ float  g_scs[NN*64];
__device__ float  g_scv[NN*96];
__device__ float  g_accs[NN*64];
__device__ float4 g_accv4[NN*32];
__device__ float  g_ns[NN*64];
__device__ float  g_nv[NN*96];
__device__ float  g_wmlp[(long long)EE*96];
__device__ float  g_P[NN*128];
__device__ float  g_Q[NN*128];
__device__ float  g_T[NN*384];
__device__ float  g_U[NN*384];
__device__ float  g_gstat[4*NG_];
__device__ float  g_gout[3*NG_];

__device__ __forceinline__ float sig_(float x){ return 1.f/(1.f+__expf(-x)); }
__device__ __forceinline__ unsigned long long pk2(float x){
  unsigned long long r; asm("mov.b64 %0, {%1, %1};" : "=l"(r) : "f"(x)); return r; }
__device__ __forceinline__ unsigned long long pkab(float a, float b){
  unsigned long long r; asm("mov.b64 %0, {%1, %2};" : "=l"(r) : "f"(a), "f"(b)); return r; }
__device__ __forceinline__ void up2(unsigned long long v, float &a, float &b){
  asm("mov.b64 {%0, %1}, %2;" : "=f"(a), "=f"(b) : "l"(v)); }
__device__ __forceinline__ void fma2(unsigned long long &d, unsigned long long a, unsigned long long b){
  asm("fma.rn.f32x2 %0, %1, %2, %3;" : "=l"(d) : "l"(a), "l"(b), "l"(d)); }
__device__ __forceinline__ unsigned int s2u_(const void* p){
  unsigned int a; asm("{ .reg .u64 t; cvta.to.shared.u64 t, %1; cvt.u32.u64 %0, t; }" : "=r"(a) : "l"(p)); return a; }

// ---- mma.sync helpers (base sm_80+ features, valid on plain sm_103 PTX target) ----
__device__ __forceinline__ void ldsm4(unsigned &r0,unsigned &r1,unsigned &r2,unsigned &r3, unsigned a){
  asm volatile("ldmatrix.sync.aligned.m8n8.x4.shared.b16 {%0,%1,%2,%3}, [%4];"
    : "=r"(r0),"=r"(r1),"=r"(r2),"=r"(r3) : "r"(a)); }
__device__ __forceinline__ void ldsm2(unsigned &r0,unsigned &r1, unsigned a){
  asm volatile("ldmatrix.sync.aligned.m8n8.x2.shared.b16 {%0,%1}, [%2];"
    : "=r"(r0),"=r"(r1) : "r"(a)); }
__device__ __forceinline__ void mma16816(float* c, const unsigned* a, const unsigned* b){
  asm volatile("mma.sync.aligned.m16n8k16.row.col.f32.bf16.bf16.f32 "
    "{%0,%1,%2,%3}, {%4,%5,%6,%7}, {%8,%9}, {%0,%1,%2,%3};"
    : "+f"(c[0]),"+f"(c[1]),"+f"(c[2]),"+f"(c[3])
    : "r"(a[0]),"r"(a[1]),"r"(a[2]),"r"(a[3]), "r"(b[0]),"r"(b[1])); }
__device__ __forceinline__ void split2(float a, float b, unsigned &h, unsigned &l){
  __nv_bfloat16 ha=__float2bfloat16(a), hb=__float2bfloat16(b);
  float la=a-__bfloat162float(ha), lb=b-__bfloat162float(hb);
  __nv_bfloat162 hh=__halves2bfloat162(ha,hb);
  __nv_bfloat162 ll=__halves2bfloat162(__float2bfloat16(la),__float2bfloat16(lb));
  h=*(unsigned*)&hh; l=*(unsigned*)&ll; }

__global__ void k_zero(){
  int i = blockIdx.x*blockDim.x + threadIdx.x;
  if (i < NN*64) g_accs[i] = 0.f;
  int j = i - NN*64;
  if (j >= 0 && j < NN*128) ((float*)g_accv4)[j] = 0.f;
  int k = i - NN*192;
  if (k >= 0 && k < 4*NG_) g_gstat[k] = 0.f;
}

__global__ void __launch_bounds__(512) k_node_pre(const float* __restrict__ nf,
   const float* __restrict__ oh, const float* __restrict__ lpWs, const float* __restrict__ lpbs,
   const float* __restrict__ lpWv, const float* __restrict__ scWs, const float* __restrict__ scWv){
  extern __shared__ float sm[];
  float2* WsS  = (float2*)sm;
  float*  WvS  = sm + 4096;
  float2* sWsS = (float2*)(sm + 5120);
  float*  sWvS = sm + 21504;
  float*  bsS  = sm + 25600;
  float*  stage= sm + 25664;
  for (int i=threadIdx.x;i<4096;i+=blockDim.x) sm[i]=lpWs[i];
  for (int i=threadIdx.x;i<1024;i+=blockDim.x) WvS[i]=lpWv[i];
  for (int i=threadIdx.x;i<16384;i+=blockDim.x) sm[5120+i]=scWs[i];
  for (int i=threadIdx.x;i<4096;i+=blockDim.x) sWvS[i]=scWv[i];
  for (int i=threadIdx.x;i<64;i+=blockDim.x) bsS[i]=lpbs[i];
  __syncthreads();
  int warp = threadIdx.x>>5, lane = threadIdx.x&31, wpb = blockDim.x>>5;
  float*  sS  = stage + warp*192;
  float4* vS  = (float4*)(sS + 64);
  for (int n = blockIdx.x*wpb + warp; n < NN; n += gridDim.x*wpb){
    const float* row = nf + n*160;
    sS[lane] = row[lane]; sS[32+lane] = row[32+lane];
    vS[lane] = make_float4(row[64+3*lane], row[65+3*lane], row[66+3*lane], 0.f);
    const float* o4 = oh + n*4;
    int sp = (o4[1]>0.5f)?1:((o4[2]>0.5f)?2:((o4[3]>0.5f)?3:0));
    __syncwarp();
    float a0=0.f,a1=0.f,c0=0.f,c1=0.f;
    #pragma unroll 4
    for (int u=0;u<64;u++){
      float x = sS[u];
      float2 w  = WsS[u*32+lane];
      float2 w2 = sWsS[(u*4+sp)*32+lane];
      a0+=x*w.x; a1+=x*w.y; c0+=x*w2.x; c1+=x*w2.y;
    }
    g_s[n*64+2*lane]   = a0*0.125f + bsS[2*lane];
    g_s[n*64+2*lane+1] = a1*0.125f + bsS[2*lane+1];
    g_scs[n*64+2*lane]   = c0*0.0625f;
    g_scs[n*64+2*lane+1] = c1*0.0625f;
    float vx=0.f,vy=0.f,vz=0.f,cx=0.f,cy=0.f,cz=0.f;
    #pragma unroll 4
    for (int u=0;u<32;u++){
      float4 x = vS[u];
      float w  = WvS[u*32+lane];
      float w2 = sWvS[(u*4+sp)*32+lane];
      vx+=x.x*w;  vy+=x.y*w;  vz+=x.z*w;
      cx+=x.x*w2; cy+=x.y*w2; cz+=x.z*w2;
    }
    g_v4[n*32+lane] = make_float4(vx*0.17677670f, vy*0.17677670f, vz*0.17677670f, 0.f);
    g_scv[n*96+3*lane]   = cx*0.08838835f;
    g_scv[n*96+3*lane+1] = cy*0.08838835f;
    g_scv[n*96+3*lane+2] = cz*0.08838835f;
    __syncwarp();
  }
}

__global__ void __launch_bounds__(512) k_pstv(const float* __restrict__ Wss0,
   const float* __restrict__ Wssg, const float* __restrict__ Wsv1,
   const float* __restrict__ Wvv0, const float* __restrict__ Wvvg, const float* __restrict__ Wvs1){
  extern __shared__ float sm[];
  float4* FA = (float4*)sm;
  float4* FB = (float4*)(sm+8192);
  float4* GA = (float4*)(sm+16384);
  float4* GB = (float4*)(sm+20480);
  float* stage = sm + 24576;
  for (int i=threadIdx.x;i<2048;i+=blockDim.x){
    int u=i>>5, l=i&31;
    FA[i]=make_float4(Wss0[u*64+2*l], Wss0[u*64+2*l+1], Wssg[u*32+l], Wsv1[u*32+l]);
    int u2=u+64;
    FB[i]=make_float4(Wss0[u2*64+2*l], Wss0[u2*64+2*l+1], Wssg[u2*32+l], Wsv1[u2*32+l]);
  }
  for (int i=threadIdx.x;i<1024;i+=blockDim.x){
    int u=i>>5, l=i&31;
    GA[i]=make_float4(Wvv0[u*64+2*l], Wvv0[u*64+2*l+1], Wvvg[u*32+l], Wvs1[u*32+l]);
    int u2=u+32;
    GB[i]=make_float4(Wvv0[u2*64+2*l], Wvv0[u2*64+2*l+1], Wvvg[u2*32+l], Wvs1[u2*32+l]);
  }
  __syncthreads();
  int warp=threadIdx.x>>5, lane=threadIdx.x&31, wpb=blockDim.x>>5;
  float* sd = stage + warp*1024;
  const int b1 = NN/8;
  for (int p = blockIdx.x*wpb+warp; p<b1; p+=gridDim.x*wpb){
    int n0 = p*8;
    #pragma unroll
    for (int k=0;k<8;k++){
      int n = n0+k;
      float x0 = g_s[n*64+lane];
      float x1 = g_s[n*64+32+lane];
      *(unsigned long long*)(sd + k*128 + 2*lane)      = pkab(x0,x0);
      *(unsigned long long*)(sd + k*128 + 64 + 2*lane) = pkab(x1,x1);
    }
    __syncwarp();
    unsigned long long pa[8], pg[8], qa[8], qg[8];
    #pragma unroll
    for (int k=0;k<8;k++){ pa[k]=0ull; pg[k]=0ull; qa[k]=0ull; qg[k]=0ull; }
    #pragma unroll 2
    for (int u=0;u<64;u+=2){
      ulonglong2 wa0 = *(ulonglong2*)&FA[(u  )*32+lane];
      ulonglong2 wa1 = *(ulonglong2*)&FA[(u+1)*32+lane];
      ulonglong2 wb0 = *(ulonglong2*)&FB[(u  )*32+lane];
      ulonglong2 wb1 = *(ulonglong2*)&FB[(u+1)*32+lane];
      #pragma unroll
      for (int k=0;k<8;k++){
        ulonglong2 xp = *(ulonglong2*)(sd + k*128 + 2*u);
        fma2(pa[k], xp.x, wa0.x); fma2(pg[k], xp.x, wa0.y);
        fma2(qa[k], xp.x, wb0.x); fma2(qg[k], xp.x, wb0.y);
        fma2(pa[k], xp.y, wa1.x); fma2(pg[k], xp.y, wa1.y);
        fma2(qa[k], xp.y, wb1.x); fma2(qg[k], xp.y, wb1.y);
      }
    }
    #pragma unroll
    for (int k=0;k<8;k++){
      int n = n0+k;
      float a0,a1,ag,at;
      up2(pa[k],a0,a1); up2(pg[k],ag,at);
      *(float4*)(g_P + n*128 + lane*4) = make_float4(a0,a1,ag,at);
      up2(qa[k],a0,a1); up2(qg[k],ag,at);
      *(float4*)(g_Q + n*128 + lane*4) = make_float4(a0,a1,ag,at);
    }
    __syncwarp();
  }
  float4* vst = (float4*)sd;
  const int b2 = NN/4;
  for (int p = blockIdx.x*wpb+warp; p<b2; p+=gridDim.x*wpb){
    int n0 = p*4;
    #pragma unroll
    for (int k=0;k<4;k++) vst[k*32+lane] = g_v4[(n0+k)*32+lane];
    __syncwarp();
    unsigned long long t01[4][3], tgr[4][3], u01[4][3], ugr[4][3];
    #pragma unroll
    for (int k=0;k<4;k++)
      #pragma unroll
      for (int c=0;c<3;c++){ t01[k][c]=0ull; tgr[k][c]=0ull; u01[k][c]=0ull; ugr[k][c]=0ull; }
    #pragma unroll 2
    for (int u=0;u<32;u++){
      ulonglong2 ga = *(ulonglong2*)&GA[u*32+lane];
      ulonglong2 gb = *(ulonglong2*)&GB[u*32+lane];
      #pragma unroll
      for (int k=0;k<4;k++){
        float4 v = vst[k*32+u];
        unsigned long long vx=pk2(v.x), vy=pk2(v.y), vz=pk2(v.z);
        fma2(t01[k][0], vx, ga.x); fma2(t01[k][1], vy, ga.x); fma2(t01[k][2], vz, ga.x);
        fma2(tgr[k][0], vx, ga.y); fma2(tgr[k][1], vy, ga.y); fma2(tgr[k][2], vz, ga.y);
        fma2(u01[k][0], vx, gb.x); fma2(u01[k][1], vy, gb.x); fma2(u01[k][2], vz, gb.x);
        fma2(ugr[k][0], vx, gb.y); fma2(ugr[k][1], vy, gb.y); fma2(ugr[k][2], vz, gb.y);
      }
    }
    #pragma unroll
    for (int k=0;k<4;k++){
      int n = n0+k;
      float b0x,b1x,b0y,b1y,b0z,b1z,bgx,rx,bgy,ry,bgz,rz;
      up2(t01[k][0],b0x,b1x); up2(t01[k][1],b0y,b1y); up2(t01[k][2],b0z,b1z);
      up2(tgr[k][0],bgx,rx);  up2(tgr[k][1],bgy,ry);  up2(tgr[k][2],bgz,rz);
      float* o = g_T + n*384 + lane*12;
      *(float4*)(o  ) = make_float4(b0x,b0y,b0z,b1x);
      *(float4*)(o+4) = make_float4(b1y,b1z,bgx,bgy);
      *(float4*)(o+8) = make_float4(bgz,rx,ry,rz);
      up2(u01[k][0],b0x,b1x); up2(u01[k][1],b0y,b1y); up2(u01[k][2],b0z,b1z);
      up2(ugr[k][0],bgx,rx);  up2(ugr[k][1],bgy,ry);  up2(ugr[k][2],bgz,rz);
      o = g_U + n*384 + lane*12;
      *(float4*)(o  ) = make_float4(b0x,b0y,b0z,b1x);
      *(float4*)(o+4) = make_float4(b1y,b1z,bgx,bgy);
      *(float4*)(o+8) = make_float4(bgz,rx,ry,rz);
    }
    __syncwarp();
  }
}

// ---------------- HMMA MLP: 2500 tiles of 128 edges, bf16 hi/lo ----------------
#define LD1 136
#define LD2 72
#define LDO 98
#define MB_XH  0
#define MB_XL  34816
#define MB_W1H 69632
#define MB_W1L 87040
#define MB_W2H 104448
#define MB_W2L 113664
#define MB_W3H 122880
#define MB_W3L 136704
#define MB_HH  150528
#define MB_HL  168960
#define MB_GH  0
#define MB_GL  18432
#define MB_OUT 150528
#define MB_B1  200704
#define MB_B2  200960
#define MB_B3  201216
#define MB_TOT 201600

__global__ void __launch_bounds__(256) k_mlp_hmma(const float* __restrict__ ele,
   const float* __restrict__ W1, const float* __restrict__ b1,
   const float* __restrict__ W2, const float* __restrict__ b2,
   const float* __restrict__ W3, const float* __restrict__ b3){
  extern __shared__ char smc[];
  unsigned int sb = s2u_(smc);
  int tid=threadIdx.x, wid=tid>>5, lane=tid&31;
  for (int i=tid;i<64*128;i+=256){
    int n=i>>7,k=i&127; float w=W1[k*64+n];
    __nv_bfloat16 h=__float2bfloat16(w);
    *(__nv_bfloat16*)(smc+MB_W1H+(n*LD1+k)*2)=h;
    *(__nv_bfloat16*)(smc+MB_W1L+(n*LD1+k)*2)=__float2bfloat16(w-__bfloat162float(h));
  }
  for (int i=tid;i<64*64;i+=256){
    int n=i>>6,k=i&63; float w=W2[k*64+n];
    __nv_bfloat16 h=__float2bfloat16(w);
    *(__nv_bfloat16*)(smc+MB_W2H+(n*LD2+k)*2)=h;
    *(__nv_bfloat16*)(smc+MB_W2L+(n*LD2+k)*2)=__float2bfloat16(w-__bfloat162float(h));
  }
  for (int i=tid;i<96*64;i+=256){
    int n=i>>6,k=i&63; float w=W3[k*96+n];
    __nv_bfloat16 h=__float2bfloat16(w);
    *(__nv_bfloat16*)(smc+MB_W3H+(n*LD2+k)*2)=h;
    *(__nv_bfloat16*)(smc+MB_W3L+(n*LD2+k)*2)=__float2bfloat16(w-__bfloat162float(h));
  }
  float* b1S=(float*)(smc+MB_B1); float* b2S=(float*)(smc+MB_B2); float* b3S=(float*)(smc+MB_B3);
  if (tid<64){ b1S[tid]=b1[tid]; b2S[tid]=b2[tid]; }
  if (tid<96) b3S[tid]=b3[tid];
  __syncthreads();

  int r0 = wid*16;
  int arow = r0 + (lane&15);
  int koff = (lane>>4)<<3;
  int brow = lane&7;
  int bk   = ((lane>>3)&1)<<3;
  int er = r0+(lane>>2), ec2=(lane&3)*2;

  for (int t=blockIdx.x; t<EE/128; t+=gridDim.x){
    const float4* xp=(const float4*)(ele+(long long)t*16384);
    for (int i=tid;i<4096;i+=256){
      float4 v=xp[i];
      int r=(i*4)>>7, c=(i*4)&127;
      unsigned h0,l0,h1,l1;
      split2(v.x,v.y,h0,l0); split2(v.z,v.w,h1,l1);
      unsigned off=(unsigned)(r*LD1+c)*2u;
      *(uint2*)(smc+MB_XH+off)=make_uint2(h0,h1);
      *(uint2*)(smc+MB_XL+off)=make_uint2(l0,l1);
    }
    __syncthreads();

    // layer 1: K=128, N=64
    float acc[8][4];
    #pragma unroll
    for(int nt=0;nt<8;nt++){acc[nt][0]=0.f;acc[nt][1]=0.f;acc[nt][2]=0.f;acc[nt][3]=0.f;}
    #pragma unroll
    for(int kk=0;kk<8;kk++){
      unsigned ah[4],al[4];
      ldsm4(ah[0],ah[1],ah[2],ah[3], sb+MB_XH+(unsigned)(arow*LD1+kk*16+koff)*2u);
      ldsm4(al[0],al[1],al[2],al[3], sb+MB_XL+(unsigned)(arow*LD1+kk*16+koff)*2u);
      #pragma unroll
      for(int nt=0;nt<8;nt++){
        unsigned bh[2],bl[2];
        ldsm2(bh[0],bh[1], sb+MB_W1H+(unsigned)((nt*8+brow)*LD1+kk*16+bk)*2u);
        ldsm2(bl[0],bl[1], sb+MB_W1L+(unsigned)((nt*8+brow)*LD1+kk*16+bk)*2u);
        mma16816(acc[nt], ah, bh);
        mma16816(acc[nt], ah, bl);
        mma16816(acc[nt], al, bh);
      }
    }
    #pragma unroll
    for(int nt=0;nt<8;nt++){
      int c=nt*8+ec2;
      float f0=acc[nt][0]+b1S[c], f1=acc[nt][1]+b1S[c+1];
      float f2=acc[nt][2]+b1S[c], f3=acc[nt][3]+b1S[c+1];
      f0*=sig_(f0); f1*=sig_(f1); f2*=sig_(f2); f3*=sig_(f3);
      unsigned h,l;
      split2(f0,f1,h,l);
      *(unsigned*)(smc+MB_HH+(er*LD2+c)*2)=h;
      *(unsigned*)(smc+MB_HL+(er*LD2+c)*2)=l;
      split2(f2,f3,h,l);
      *(unsigned*)(smc+MB_HH+((er+8)*LD2+c)*2)=h;
      *(unsigned*)(smc+MB_HL+((er+8)*LD2+c)*2)=l;
    }
    __syncthreads();

    // layer 2: K=64, N=64 -> G (overlays X)
    #pragma unroll
    for(int nt=0;nt<8;nt++){acc[nt][0]=0.f;acc[nt][1]=0.f;acc[nt][2]=0.f;acc[nt][3]=0.f;}
    #pragma unroll
    for(int kk=0;kk<4;kk++){
      unsigned ah[4],al[4];
      ldsm4(ah[0],ah[1],ah[2],ah[3], sb+MB_HH+(unsigned)(arow*LD2+kk*16+koff)*2u);
      ldsm4(al[0],al[1],al[2],al[3], sb+MB_HL+(unsigned)(arow*LD2+kk*16+koff)*2u);
      #pragma unroll
      for(int nt=0;nt<8;nt++){
        unsigned bh[2],bl[2];
        ldsm2(bh[0],bh[1], sb+MB_W2H+(unsigned)((nt*8+brow)*LD2+kk*16+bk)*2u);
        ldsm2(bl[0],bl[1], sb+MB_W2L+(unsigned)((nt*8+brow)*LD2+kk*16+bk)*2u);
        mma16816(acc[nt], ah, bh);
        mma16816(acc[nt], ah, bl);
        mma16816(acc[nt], al, bh);
      }
    }
    #pragma unroll
    for(int nt=0;nt<8;nt++){
      int c=nt*8+ec2;
      float f0=acc[nt][0]+b2S[c], f1=acc[nt][1]+b2S[c+1];
      float f2=acc[nt][2]+b2S[c], f3=acc[nt][3]+b2S[c+1];
      f0*=sig_(f0); f1*=sig_(f1); f2*=sig_(f2); f3*=sig_(f3);
      unsigned h,l;
      split2(f0,f1,h,l);
      *(unsigned*)(smc+MB_GH+(er*LD2+c)*2)=h;
      *(unsigned*)(smc+MB_GL+(er*LD2+c)*2)=l;
      split2(f2,f3,h,l);
      *(unsigned*)(smc+MB_GH+((er+8)*LD2+c)*2)=h;
      *(unsigned*)(smc+MB_GL+((er+8)*LD2+c)*2)=l;
    }
    __syncthreads();

    // layer 3: K=64, N=96 -> OUT (overlays H)
    float a3[12][4];
    #pragma unroll
    for(int nt=0;nt<12;nt++){a3[nt][0]=0.f;a3[nt][1]=0.f;a3[nt][2]=0.f;a3[nt][3]=0.f;}
    #pragma unroll
    for(int kk=0;kk<4;kk++){
      unsigned ah[4],al[4];
      ldsm4(ah[0],ah[1],ah[2],ah[3], sb+MB_GH+(unsigned)(arow*LD2+kk*16+koff)*2u);
      ldsm4(al[0],al[1],al[2],al[3], sb+MB_GL+(unsigned)(arow*LD2+kk*16+koff)*2u);
      #pragma unroll
      for(int nt=0;nt<12;nt++){
        unsigned bh[2],bl[2];
        ldsm2(bh[0],bh[1], sb+MB_W3H+(unsigned)((nt*8+brow)*LD2+kk*16+bk)*2u);
        ldsm2(bl[0],bl[1], sb+MB_W3L+(unsigned)((nt*8+brow)*LD2+kk*16+bk)*2u);
        mma16816(a3[nt], ah, bh);
        mma16816(a3[nt], ah, bl);
        mma16816(a3[nt], al, bh);
      }
    }
    {
      float* outS=(float*)(smc+MB_OUT);
      #pragma unroll
      for(int nt=0;nt<12;nt++){
        int c=nt*8+ec2;
        *(float2*)(outS+er*LDO+c)     = make_float2(a3[nt][0]+b3S[c], a3[nt][1]+b3S[c+1]);
        *(float2*)(outS+(er+8)*LDO+c) = make_float2(a3[nt][2]+b3S[c], a3[nt][3]+b3S[c+1]);
      }
    }
    __syncthreads();
    {
      const float* outS=(const float*)(smc+MB_OUT);
      long long base=(long long)t*12288;
      for(int i=tid;i<12288;i+=256){
        int r=i/96, c=i-r*96;
        g_wmlp[base+i]=outS[r*LDO+c];
      }
    }
    __syncthreads();
  }
}

__global__ void __launch_bounds__(512) k_e12(const int* __restrict__ eidx,
   const float* __restrict__ esh, const float* __restrict__ efea,
   const float* __restrict__ Wss0, const float* __restrict__ Wssg, const float* __restrict__ Wsv1,
   const float* __restrict__ Wvv0, const float* __restrict__ Wvvg, const float* __restrict__ Wvs1){
  extern __shared__ float sm[];
  float4* FC = (float4*)sm;
  ulonglong2* W2a = (ulonglong2*)(sm+8192);
  unsigned long long* W2b = (unsigned long long*)(sm+12288);
  float* stage = sm + 14336;
  for (int i=threadIdx.x;i<2048;i+=blockDim.x){
    int u=(i>>5)+128, l=i&31;
    FC[i]=make_float4(Wss0[u*64+2*l], Wss0[u*64+2*l+1], Wssg[u*32+l], Wsv1[u*32+l]);
  }
  for (int i=threadIdx.x;i<1024;i+=blockDim.x){
    int u=(i>>5)+64, l=i&31;
    float w0=Wvv0[u*64+2*l], w1=Wvv0[u*64+2*l+1];
    float wz=Wvvg[u*32+l],   ww=Wvs1[u*32+l];
    W2a[i] = make_ulonglong2(pkab(w0,w1), pkab(wz,ww));
    W2b[i] = pkab(ww,ww);
  }
  __syncthreads();
  int warp=threadIdx.x>>5, lane=threadIdx.x&31, wpb=blockDim.x>>5;
  float* sd0 = stage + warp*2720;
  float* vd  = sd0 + 896;
  float* shS = sd0 + 2688;
  const float inv3 = 0.57735027f, invfan = 0.058925565f;
  const int batches = (EE+6)/7;
  for (int p = blockIdx.x*wpb+warp; p<batches; p+=gridDim.x*wpb){
    int e0 = p*7;
    int nid[7], njd[7];
    #pragma unroll
    for (int k=0;k<7;k++){
      int e = e0+k;
      if (e < EE){
        nid[k]=eidx[e]; njd[k]=eidx[EE+e];
        float4 sh = *(const float4*)(esh + (long long)e*4);
        if (lane==0) *(float4*)(shS + k*4) = sh;
        const float* r = efea + (long long)e*160;
        float x0=r[lane], x1=r[32+lane];
        *(unsigned long long*)(sd0 + k*128 + 2*lane)      = pkab(x0,x0);
        *(unsigned long long*)(sd0 + k*128 + 64 + 2*lane) = pkab(x1,x1);
        float ex=r[64+3*lane], ey=r[65+3*lane], ez=r[66+3*lane];
        float dd=(ex*sh.y+ey*sh.z+ez*sh.w)*inv3;
        float* o = vd + k*256 + lane*8;
        *(float4*)o     = make_float4(dd,dd,ex,ey);
        *(float2*)(o+4) = make_float2(dd,ez);
      } else {
        nid[k]=-1; njd[k]=0;
        *(unsigned long long*)(sd0 + k*128 + 2*lane)      = 0ull;
        *(unsigned long long*)(sd0 + k*128 + 64 + 2*lane) = 0ull;
        float* o = vd + k*256 + lane*8;
        *(float4*)o     = make_float4(0.f,0.f,0.f,0.f);
        *(float2*)(o+4) = make_float2(0.f,0.f);
        if (lane==0) *(float4*)(shS + k*4) = make_float4(0.f,0.f,0.f,0.f);
      }
    }
    __syncwarp();
    unsigned long long a01[7], agt[7];
    #pragma unroll
    for (int k=0;k<7;k++){ a01[k]=0ull; agt[k]=0ull; }
    #pragma unroll 2
    for (int u=0;u<64;u+=2){
      ulonglong2 w0 = *(ulonglong2*)&FC[(u  )*32+lane];
      ulonglong2 w1 = *(ulonglong2*)&FC[(u+1)*32+lane];
      #pragma unroll
      for (int k=0;k<7;k++){
        ulonglong2 xp = *(ulonglong2*)(sd0 + k*128 + 2*u);
        fma2(a01[k], xp.x, w0.x); fma2(agt[k], xp.x, w0.y);
        fma2(a01[k], xp.y, w1.x); fma2(agt[k], xp.y, w1.y);
      }
    }
    unsigned long long b01[7], r01[7], gz2[7];
    #pragma unroll
    for (int k=0;k<7;k++){ b01[k]=0ull; r01[k]=0ull; gz2[k]=0ull; }
    #pragma unroll 4
    for (int u=0;u<32;u++){
      ulonglong2 wa = W2a[u*32+lane];
      unsigned long long wb = W2b[u*32+lane];
      #pragma unroll
      for (int k=0;k<7;k++){
        ulonglong2 t1 = *(ulonglong2*)(vd + k*256 + u*8);
        unsigned long long t2 = *(unsigned long long*)(vd + k*256 + u*8 + 4);
        fma2(b01[k], t1.x, wa.x);
        fma2(r01[k], t1.y, wb);
        fma2(gz2[k], t2,   wa.y);
      }
    }
    #pragma unroll
    for (int k=0;k<7;k++){
      if (nid[k] < 0) continue;
      long long e = e0+k;
      float a0,a1,ag,at,b0,b1,r0,r1,bg,r2;
      up2(a01[k],a0,a1); up2(agt[k],ag,at);
      up2(b01[k],b0,b1); up2(r01[k],r0,r1); up2(gz2[k],bg,r2);
      float4 P = *(const float4*)(g_P + nid[k]*128 + lane*4);
      float4 Q = *(const float4*)(g_Q + njd[k]*128 + lane*4);
      a0+=P.x+Q.x; a1+=P.y+Q.y; ag+=P.z+Q.z; at+=P.w+Q.w;
      float4 sh = *(float4*)(shS + k*4);
      const float* tp  = g_T + nid[k]*384 + lane*12;
      const float* upt = g_U + njd[k]*384 + lane*12;
      float4 t0=*(const float4*)tp,  t1=*(const float4*)(tp+4),  t2=*(const float4*)(tp+8);
      float4 u0=*(const float4*)upt, u1=*(const float4*)(upt+4), u2=*(const float4*)(upt+8);
      float s0x=t0.x+u0.x, s0y=t0.y+u0.y, s0z=t0.z+u0.z, s0w=t0.w+u0.w;
      float s1x=t1.x+u1.x, s1y=t1.y+u1.y, s1z=t1.z+u1.z, s1w=t1.w+u1.w;
      float s2x=t2.x+u2.x, s2y=t2.y+u2.y, s2z=t2.z+u2.z, s2w=t2.w+u2.w;
      b0 += inv3*(s0x*sh.y + s0y*sh.z + s0z*sh.w);
      b1 += inv3*(s0w*sh.y + s1x*sh.z + s1y*sh.w);
      bg += inv3*(s1z*sh.y + s1w*sh.z + s2x*sh.w);
      r0 += s2y; r1 += s2z; r2 += s2w;
      float zs0=(sh.x*a0+b0)*invfan, zs1=(sh.x*a1+b1)*invfan;
      float zg =(sh.x*ag+bg)*invfan;
      const float* wm = g_wmlp + e*96;
      float2 wm01 = *(const float2*)(wm+2*lane);
      float wmv = wm[64+lane];
      zs0 = zs0*sig_(zs0)*wm01.x;
      zs1 = zs1*sig_(zs1)*wm01.y;
      float gv = sig_(zg)*wmv*invfan;
      int n = nid[k];
      atomicAdd((float2*)(g_accs + n*64 + 2*lane), make_float2(zs0, zs1));
      atomicAdd(&g_accv4[n*32+lane],
                make_float4((at*sh.y + r0*sh.x)*gv, (at*sh.z + r1*sh.x)*gv,
                            (at*sh.w + r2*sh.x)*gv, 0.f));
    }
    __syncwarp();
  }
}

__global__ void __launch_bounds__(512) k_node_post(const int* __restrict__ batch,
   const float* __restrict__ ppWs, const float* __restrict__ ppbs, const float* __restrict__ ppWv){
  extern __shared__ float sm[];
  float2* WsS = (float2*)sm;
  float* WvS = sm+4096;
  float* bsS = sm+5120;
  float* stage = sm+5184;
  for (int i=threadIdx.x;i<4096;i+=blockDim.x) sm[i]=ppWs[i];
  for (int i=threadIdx.x;i<1024;i+=blockDim.x) WvS[i]=ppWv[i];
  for (int i=threadIdx.x;i<64;i+=blockDim.x) bsS[i]=ppbs[i];
  __syncthreads();
  int warp=threadIdx.x>>5, lane=threadIdx.x&31, wpb=blockDim.x>>5;
  float*  sS  = stage + warp*192;
  float4* vS  = (float4*)(sS+64);
  for (int n=blockIdx.x*wpb+warp; n<NN; n+=gridDim.x*wpb){
    sS[lane]=g_accs[n*64+lane]; sS[32+lane]=g_accs[n*64+32+lane];
    vS[lane]=g_accv4[n*32+lane];
    __syncwarp();
    float a0=0.f,a1=0.f;
    #pragma unroll 4
    for (int u=0;u<64;u++){
      float x=sS[u]; float2 w=WsS[u*32+lane];
      a0+=x*w.x; a1+=x*w.y;
    }
    float ns0 = a0*0.125f + bsS[2*lane]   + g_scs[n*64+2*lane];
    float ns1 = a1*0.125f + bsS[2*lane+1] + g_scs[n*64+2*lane+1];
    g_ns[n*64+2*lane]=ns0; g_ns[n*64+2*lane+1]=ns1;
    float vx=0.f,vy=0.f,vz=0.f;
    #pragma unroll 4
    for (int u=0;u<32;u++){
      float4 x=vS[u]; float w=WvS[u*32+lane];
      vx+=x.x*w; vy+=x.y*w; vz+=x.z*w;
    }
    float nv0 = vx*0.17677670f + g_scv[n*96+3*lane];
    float nv1 = vy*0.17677670f + g_scv[n*96+3*lane+1];
    float nv2 = vz*0.17677670f + g_scv[n*96+3*lane+2];
    g_nv[n*96+3*lane]=nv0; g_nv[n*96+3*lane+1]=nv1; g_nv[n*96+3*lane+2]=nv2;
    float m = ns0+ns1;
    float q = ns0*ns0+ns1*ns1;
    float pw = nv0*nv0+nv1*nv1+nv2*nv2;
    #pragma unroll
    for (int off=16;off>0;off>>=1){
      m += __shfl_down_sync(0xffffffffu, m, off);
      q += __shfl_down_sync(0xffffffffu, q, off);
      pw += __shfl_down_sync(0xffffffffu, pw, off);
    }
    if (lane==0){
      int g = batch[n];
      atomicAdd(&g_gstat[g],        m*(1.f/64.f));
      atomicAdd(&g_gstat[NG_+g],    q*(1.f/64.f));
      atomicAdd(&g_gstat[2*NG_+g],  pw*(1.f/96.f));
      atomicAdd(&g_gstat[3*NG_+g],  1.f);
    }
    __syncwarp();
  }
}

__global__ void k_groups(){
  int t = threadIdx.x;
  if (t < NG_){
    float c  = fmaxf(g_gstat[3*NG_+t], 1.f);
    float mu = g_gstat[t]/c;
    float vs = g_gstat[NG_+t]/c - mu*mu;
    float vv = g_gstat[2*NG_+t]/c;
    g_gout[t]       = mu;
    g_gout[NG_+t]   = rsqrtf(vs+1e-5f);
    g_gout[2*NG_+t] = rsqrtf(vv+1e-5f);
  }
}

__global__ void k_out(const float* __restrict__ nf, const int* __restrict__ batch,
   const float* __restrict__ lnws, const float* __restrict__ lnbs,
   const float* __restrict__ lnwv, float* __restrict__ out){
  int i = blockIdx.x*blockDim.x+threadIdx.x;
  if (i >= NN*160) return;
  int n = i/160, c = i - n*160;
  int g = batch[n];
  float base = nf[i];
  float o;
  if (c < 64){
    float x = (g_ns[n*64+c] - g_gout[g]) * g_gout[NG_+g];
    o = base + x*lnws[c] + lnbs[c];
  } else {
    int cc = c-64;
    o = base + g_nv[n*96+cc]*g_gout[2*NG_+g]*lnwv[cc/3];
  }
  out[i]=o;
}

extern "C" void kernel_launch(void* const* d_in, const int* in_sizes, int n_in,
                              void* d_out, int out_size){
  const float* nf   =(const float*)d_in[0];
  const float* oh   =(const float*)d_in[1];
  const float* esh  =(const float*)d_in[2];
  const float* efea =(const float*)d_in[3];
  const float* ele  =(const float*)d_in[4];
  const int*   eidx =(const int*)d_in[5];
  const int*   batch=(const int*)d_in[6];
  const float* lpWs =(const float*)d_in[7];
  const float* lpbs =(const float*)d_in[8];
  const float* lpWv =(const float*)d_in[9];
  const float* ppWs =(const float*)d_in[10];
  const float* ppbs =(const float*)d_in[11];
  const float* ppWv =(const float*)d_in[12];
  const float* scWs =(const float*)d_in[13];
  const float* scWv =(const float*)d_in[14];
  const float* Wss0 =(const float*)d_in[15];
  const float* Wvv0 =(const float*)d_in[16];
  const float* Wssg =(const float*)d_in[17];
  const float* Wvvg =(const float*)d_in[18];
  const float* Wsv1 =(const float*)d_in[19];
  const float* Wvs1 =(const float*)d_in[20];
  const float* fcW1 =(const float*)d_in[21];
  const float* fcb1 =(const float*)d_in[22];
  const float* fcW2 =(const float*)d_in[23];
  const float* fcb2 =(const float*)d_in[24];
  const float* fcW3 =(const float*)d_in[25];
  const float* fcb3 =(const float*)d_in[26];
  const float* lnws =(const float*)d_in[27];
  const float* lnbs =(const float*)d_in[28];
  const float* lnwv =(const float*)d_in[29];
  float* out = (float*)d_out;

  const int SM_PRE  = (25664 + 16*192)*4;
  const int SM_PSTV = (24576 + 16*1024)*4;
  const int SM_E12  = (14336 + 16*2720)*4;
  const int SM_POST = (5184  + 16*192)*4;
  cudaFuncSetAttribute(k_node_pre,  cudaFuncAttributeMaxDynamicSharedMemorySize, SM_PRE);
  cudaFuncSetAttribute(k_pstv,      cudaFuncAttributeMaxDynamicSharedMemorySize, SM_PSTV);
  cudaFuncSetAttribute(k_mlp_hmma,  cudaFuncAttributeMaxDynamicSharedMemorySize, MB_TOT);
  cudaFuncSetAttribute(k_e12,       cudaFuncAttributeMaxDynamicSharedMemorySize, SM_E12);
  cudaFuncSetAttribute(k_node_post, cudaFuncAttributeMaxDynamicSharedMemorySize, SM_POST);

  k_zero<<<(NN*192 + 4*NG_ + 255)/256, 256>>>();
  k_node_pre<<<148, 512, SM_PRE>>>(nf, oh, lpWs, lpbs, lpWv, scWs, scWv);
  k_pstv<<<148, 512, SM_PSTV>>>(Wss0, Wssg, Wsv1, Wvv0, Wvvg, Wvs1);
  k_mlp_hmma<<<148, 256, MB_TOT>>>(ele, fcW1, fcb1, fcW2, fcb2, fcW3, fcb3);
  k_e12<<<148, 512, SM_E12>>>(eidx, esh, efea, Wss0, Wssg, Wsv1, Wvv0, Wvvg, Wvs1);
  k_node_post<<<148, 512, SM_POST>>>(batch, ppWs, ppbs, ppWv);
  k_groups<<<1, 32>>>();
  k_out<<<(NN*160 + 255)/256, 256>>>(nf, batch, lnws, lnbs, lnwv, out);
}

// round 12
// speedup vs baseline: 1.1311x; 1.0118x over previous
#include <cuda_runtime.h>
#include <cuda_bf16.h>
#include <cstdint>

#define NN 10000
#define EE 320000
#define NG_ 16

__device__ float  g_s[NN*64];
__device__ float4 g_v4[NN*32];
__device__ float  g_scs[NN*64];
__device__ float  g_scv[NN*96];
__device__ float  g_accs[NN*64];
__device__ float4 g_accv4[NN*32];
__device__ float  g_ns[NN*64];
__device__ float  g_nv[NN*96];
__device__ float  g_wmlp[(long long)EE*96];
__device__ float  g_P[NN*128];
__device__ float  g_Q[NN*128];
__device__ float  g_T[NN*384];
__device__ float  g_U[NN*384];
__device__ float  g_gstat[4*NG_];
__device__ float  g_gout[3*NG_];

__device__ __forceinline__ float sig_(float x){ return 1.f/(1.f+__expf(-x)); }
__device__ __forceinline__ unsigned long long pk2(float x){
  unsigned long long r; asm("mov.b64 %0, {%1, %1};" : "=l"(r) : "f"(x)); return r; }
__device__ __forceinline__ unsigned long long pkab(float a, float b){
  unsigned long long r; asm("mov.b64 %0, {%1, %2};" : "=l"(r) : "f"(a), "f"(b)); return r; }
__device__ __forceinline__ void up2(unsigned long long v, float &a, float &b){
  asm("mov.b64 {%0, %1}, %2;" : "=f"(a), "=f"(b) : "l"(v)); }
__device__ __forceinline__ void fma2(unsigned long long &d, unsigned long long a, unsigned long long b){
  asm("fma.rn.f32x2 %0, %1, %2, %3;" : "=l"(d) : "l"(a), "l"(b), "l"(d)); }
__device__ __forceinline__ unsigned int s2u_(const void* p){
  unsigned int a; asm("{ .reg .u64 t; cvta.to.shared.u64 t, %1; cvt.u32.u64 %0, t; }" : "=r"(a) : "l"(p)); return a; }

__device__ __forceinline__ void ldsm4(unsigned &r0,unsigned &r1,unsigned &r2,unsigned &r3, unsigned a){
  asm volatile("ldmatrix.sync.aligned.m8n8.x4.shared.b16 {%0,%1,%2,%3}, [%4];"
    : "=r"(r0),"=r"(r1),"=r"(r2),"=r"(r3) : "r"(a)); }
__device__ __forceinline__ void mma16816(float* c, const unsigned* a, const unsigned* b){
  asm volatile("mma.sync.aligned.m16n8k16.row.col.f32.bf16.bf16.f32 "
    "{%0,%1,%2,%3}, {%4,%5,%6,%7}, {%8,%9}, {%0,%1,%2,%3};"
    : "+f"(c[0]),"+f"(c[1]),"+f"(c[2]),"+f"(c[3])
    : "r"(a[0]),"r"(a[1]),"r"(a[2]),"r"(a[3]), "r"(b[0]),"r"(b[1])); }
__device__ __forceinline__ void split2(float a, float b, unsigned &h, unsigned &l){
  __nv_bfloat16 ha=__float2bfloat16(a), hb=__float2bfloat16(b);
  float la=a-__bfloat162float(ha), lb=b-__bfloat162float(hb);
  __nv_bfloat162 hh=__halves2bfloat162(ha,hb);
  __nv_bfloat162 ll=__halves2bfloat162(__float2bfloat16(la),__float2bfloat16(lb));
  h=*(unsigned*)&hh; l=*(unsigned*)&ll; }

__global__ void k_zero(){
  int i = blockIdx.x*blockDim.x + threadIdx.x;
  if (i < NN*64) g_accs[i] = 0.f;
  int j = i - NN*64;
  if (j >= 0 && j < NN*128) ((float*)g_accv4)[j] = 0.f;
  int k = i - NN*192;
  if (k >= 0 && k < 4*NG_) g_gstat[k] = 0.f;
}

__global__ void __launch_bounds__(512) k_node_pre(const float* __restrict__ nf,
   const float* __restrict__ oh, const float* __restrict__ lpWs, const float* __restrict__ lpbs,
   const float* __restrict__ lpWv, const float* __restrict__ scWs, const float* __restrict__ scWv){
  extern __shared__ float sm[];
  float2* WsS  = (float2*)sm;
  float*  WvS  = sm + 4096;
  float2* sWsS = (float2*)(sm + 5120);
  float*  sWvS = sm + 21504;
  float*  bsS  = sm + 25600;
  float*  stage= sm + 25664;
  for (int i=threadIdx.x;i<4096;i+=blockDim.x) sm[i]=lpWs[i];
  for (int i=threadIdx.x;i<1024;i+=blockDim.x) WvS[i]=lpWv[i];
  for (int i=threadIdx.x;i<16384;i+=blockDim.x) sm[5120+i]=scWs[i];
  for (int i=threadIdx.x;i<4096;i+=blockDim.x) sWvS[i]=scWv[i];
  for (int i=threadIdx.x;i<64;i+=blockDim.x) bsS[i]=lpbs[i];
  __syncthreads();
  int warp = threadIdx.x>>5, lane = threadIdx.x&31, wpb = blockDim.x>>5;
  float*  sS  = stage + warp*192;
  float4* vS  = (float4*)(sS + 64);
  for (int n = blockIdx.x*wpb + warp; n < NN; n += gridDim.x*wpb){
    const float* row = nf + n*160;
    sS[lane] = row[lane]; sS[32+lane] = row[32+lane];
    vS[lane] = make_float4(row[64+3*lane], row[65+3*lane], row[66+3*lane], 0.f);
    const float* o4 = oh + n*4;
    int sp = (o4[1]>0.5f)?1:((o4[2]>0.5f)?2:((o4[3]>0.5f)?3:0));
    __syncwarp();
    float a0=0.f,a1=0.f,c0=0.f,c1=0.f;
    #pragma unroll 4
    for (int u=0;u<64;u++){
      float x = sS[u];
      float2 w  = WsS[u*32+lane];
      float2 w2 = sWsS[(u*4+sp)*32+lane];
      a0+=x*w.x; a1+=x*w.y; c0+=x*w2.x; c1+=x*w2.y;
    }
    g_s[n*64+2*lane]   = a0*0.125f + bsS[2*lane];
    g_s[n*64+2*lane+1] = a1*0.125f + bsS[2*lane+1];
    g_scs[n*64+2*lane]   = c0*0.0625f;
    g_scs[n*64+2*lane+1] = c1*0.0625f;
    float vx=0.f,vy=0.f,vz=0.f,cx=0.f,cy=0.f,cz=0.f;
    #pragma unroll 4
    for (int u=0;u<32;u++){
      float4 x = vS[u];
      float w  = WvS[u*32+lane];
      float w2 = sWvS[(u*4+sp)*32+lane];
      vx+=x.x*w;  vy+=x.y*w;  vz+=x.z*w;
      cx+=x.x*w2; cy+=x.y*w2; cz+=x.z*w2;
    }
    g_v4[n*32+lane] = make_float4(vx*0.17677670f, vy*0.17677670f, vz*0.17677670f, 0.f);
    g_scv[n*96+3*lane]   = cx*0.08838835f;
    g_scv[n*96+3*lane+1] = cy*0.08838835f;
    g_scv[n*96+3*lane+2] = cz*0.08838835f;
    __syncwarp();
  }
}

__global__ void __launch_bounds__(512) k_pstv(const float* __restrict__ Wss0,
   const float* __restrict__ Wssg, const float* __restrict__ Wsv1,
   const float* __restrict__ Wvv0, const float* __restrict__ Wvvg, const float* __restrict__ Wvs1){
  extern __shared__ float sm[];
  float4* FA = (float4*)sm;
  float4* FB = (float4*)(sm+8192);
  float4* GA = (float4*)(sm+16384);
  float4* GB = (float4*)(sm+20480);
  float* stage = sm + 24576;
  for (int i=threadIdx.x;i<2048;i+=blockDim.x){
    int u=i>>5, l=i&31;
    FA[i]=make_float4(Wss0[u*64+2*l], Wss0[u*64+2*l+1], Wssg[u*32+l], Wsv1[u*32+l]);
    int u2=u+64;
    FB[i]=make_float4(Wss0[u2*64+2*l], Wss0[u2*64+2*l+1], Wssg[u2*32+l], Wsv1[u2*32+l]);
  }
  for (int i=threadIdx.x;i<1024;i+=blockDim.x){
    int u=i>>5, l=i&31;
    GA[i]=make_float4(Wvv0[u*64+2*l], Wvv0[u*64+2*l+1], Wvvg[u*32+l], Wvs1[u*32+l]);
    int u2=u+32;
    GB[i]=make_float4(Wvv0[u2*64+2*l], Wvv0[u2*64+2*l+1], Wvvg[u2*32+l], Wvs1[u2*32+l]);
  }
  __syncthreads();
  int warp=threadIdx.x>>5, lane=threadIdx.x&31, wpb=blockDim.x>>5;
  float* sd = stage + warp*1024;
  const int b1 = NN/8;
  for (int p = blockIdx.x*wpb+warp; p<b1; p+=gridDim.x*wpb){
    int n0 = p*8;
    #pragma unroll
    for (int k=0;k<8;k++){
      int n = n0+k;
      float x0 = g_s[n*64+lane];
      float x1 = g_s[n*64+32+lane];
      *(unsigned long long*)(sd + k*128 + 2*lane)      = pkab(x0,x0);
      *(unsigned long long*)(sd + k*128 + 64 + 2*lane) = pkab(x1,x1);
    }
    __syncwarp();
    unsigned long long pa[8], pg[8], qa[8], qg[8];
    #pragma unroll
    for (int k=0;k<8;k++){ pa[k]=0ull; pg[k]=0ull; qa[k]=0ull; qg[k]=0ull; }
    #pragma unroll 2
    for (int u=0;u<64;u+=2){
      ulonglong2 wa0 = *(ulonglong2*)&FA[(u  )*32+lane];
      ulonglong2 wa1 = *(ulonglong2*)&FA[(u+1)*32+lane];
      ulonglong2 wb0 = *(ulonglong2*)&FB[(u  )*32+lane];
      ulonglong2 wb1 = *(ulonglong2*)&FB[(u+1)*32+lane];
      #pragma unroll
      for (int k=0;k<8;k++){
        ulonglong2 xp = *(ulonglong2*)(sd + k*128 + 2*u);
        fma2(pa[k], xp.x, wa0.x); fma2(pg[k], xp.x, wa0.y);
        fma2(qa[k], xp.x, wb0.x); fma2(qg[k], xp.x, wb0.y);
        fma2(pa[k], xp.y, wa1.x); fma2(pg[k], xp.y, wa1.y);
        fma2(qa[k], xp.y, wb1.x); fma2(qg[k], xp.y, wb1.y);
      }
    }
    #pragma unroll
    for (int k=0;k<8;k++){
      int n = n0+k;
      float a0,a1,ag,at;
      up2(pa[k],a0,a1); up2(pg[k],ag,at);
      *(float4*)(g_P + n*128 + lane*4) = make_float4(a0,a1,ag,at);
      up2(qa[k],a0,a1); up2(qg[k],ag,at);
      *(float4*)(g_Q + n*128 + lane*4) = make_float4(a0,a1,ag,at);
    }
    __syncwarp();
  }
  float4* vst = (float4*)sd;
  const int b2 = NN/4;
  for (int p = blockIdx.x*wpb+warp; p<b2; p+=gridDim.x*wpb){
    int n0 = p*4;
    #pragma unroll
    for (int k=0;k<4;k++) vst[k*32+lane] = g_v4[(n0+k)*32+lane];
    __syncwarp();
    unsigned long long t01[4][3], tgr[4][3], u01[4][3], ugr[4][3];
    #pragma unroll
    for (int k=0;k<4;k++)
      #pragma unroll
      for (int c=0;c<3;c++){ t01[k][c]=0ull; tgr[k][c]=0ull; u01[k][c]=0ull; ugr[k][c]=0ull; }
    #pragma unroll 2
    for (int u=0;u<32;u++){
      ulonglong2 ga = *(ulonglong2*)&GA[u*32+lane];
      ulonglong2 gb = *(ulonglong2*)&GB[u*32+lane];
      #pragma unroll
      for (int k=0;k<4;k++){
        float4 v = vst[k*32+u];
        unsigned long long vx=pk2(v.x), vy=pk2(v.y), vz=pk2(v.z);
        fma2(t01[k][0], vx, ga.x); fma2(t01[k][1], vy, ga.x); fma2(t01[k][2], vz, ga.x);
        fma2(tgr[k][0], vx, ga.y); fma2(tgr[k][1], vy, ga.y); fma2(tgr[k][2], vz, ga.y);
        fma2(u01[k][0], vx, gb.x); fma2(u01[k][1], vy, gb.x); fma2(u01[k][2], vz, gb.x);
        fma2(ugr[k][0], vx, gb.y); fma2(ugr[k][1], vy, gb.y); fma2(ugr[k][2], vz, gb.y);
      }
    }
    #pragma unroll
    for (int k=0;k<4;k++){
      int n = n0+k;
      float b0x,b1x,b0y,b1y,b0z,b1z,bgx,rx,bgy,ry,bgz,rz;
      up2(t01[k][0],b0x,b1x); up2(t01[k][1],b0y,b1y); up2(t01[k][2],b0z,b1z);
      up2(tgr[k][0],bgx,rx);  up2(tgr[k][1],bgy,ry);  up2(tgr[k][2],bgz,rz);
      float* o = g_T + n*384 + lane*12;
      *(float4*)(o  ) = make_float4(b0x,b0y,b0z,b1x);
      *(float4*)(o+4) = make_float4(b1y,b1z,bgx,bgy);
      *(float4*)(o+8) = make_float4(bgz,rx,ry,rz);
      up2(u01[k][0],b0x,b1x); up2(u01[k][1],b0y,b1y); up2(u01[k][2],b0z,b1z);
      up2(ugr[k][0],bgx,rx);  up2(ugr[k][1],bgy,ry);  up2(ugr[k][2],bgz,rz);
      o = g_U + n*384 + lane*12;
      *(float4*)(o  ) = make_float4(b0x,b0y,b0z,b1x);
      *(float4*)(o+4) = make_float4(b1y,b1z,bgx,bgy);
      *(float4*)(o+8) = make_float4(bgz,rx,ry,rz);
    }
    __syncwarp();
  }
}

// ---------------- HMMA MLP: 1250 pairs of 128-edge tiles, bf16 hi/lo ----------------
#define LD1 136
#define LD2 72
#define LDO 98
#define W1Hb 139264
#define W1Lb 156672
#define W2Hb 174080
#define W2Lb 183296
#define W3Hb 192512
#define W3Lb 206336
#define B1b  220160
#define B2b  220416
#define B3b  220672
#define MBTOT 221056

__global__ void __launch_bounds__(256) k_mlp_hmma(const float* __restrict__ ele,
   const float* __restrict__ W1, const float* __restrict__ b1,
   const float* __restrict__ W2, const float* __restrict__ b2,
   const float* __restrict__ W3, const float* __restrict__ b3){
  extern __shared__ char smc[];
  unsigned int sb = s2u_(smc);
  int tid=threadIdx.x, wid=tid>>5, lane=tid&31;
  for (int i=tid;i<64*128;i+=256){
    int n=i>>7,k=i&127; float w=W1[k*64+n];
    __nv_bfloat16 h=__float2bfloat16(w);
    *(__nv_bfloat16*)(smc+W1Hb+(n*LD1+k)*2)=h;
    *(__nv_bfloat16*)(smc+W1Lb+(n*LD1+k)*2)=__float2bfloat16(w-__bfloat162float(h));
  }
  for (int i=tid;i<64*64;i+=256){
    int n=i>>6,k=i&63; float w=W2[k*64+n];
    __nv_bfloat16 h=__float2bfloat16(w);
    *(__nv_bfloat16*)(smc+W2Hb+(n*LD2+k)*2)=h;
    *(__nv_bfloat16*)(smc+W2Lb+(n*LD2+k)*2)=__float2bfloat16(w-__bfloat162float(h));
  }
  for (int i=tid;i<96*64;i+=256){
    int n=i>>6,k=i&63; float w=W3[k*96+n];
    __nv_bfloat16 h=__float2bfloat16(w);
    *(__nv_bfloat16*)(smc+W3Hb+(n*LD2+k)*2)=h;
    *(__nv_bfloat16*)(smc+W3Lb+(n*LD2+k)*2)=__float2bfloat16(w-__bfloat162float(h));
  }
  float* b1S=(float*)(smc+B1b); float* b2S=(float*)(smc+B2b); float* b3S=(float*)(smc+B3b);
  if (tid<64){ b1S[tid]=b1[tid]; b2S[tid]=b2[tid]; }
  if (tid<96) b3S[tid]=b3[tid];
  __syncthreads();

  int r0 = wid*16;
  int arow = r0 + (lane&15);
  int koff = (lane>>4)<<3;
  int b4r  = (lane&7) + ((lane>>4)<<3);
  int b4k  = ((lane>>3)&1)<<3;
  int er = r0+(lane>>2), ec2=(lane&3)*2;

  for (int tp=blockIdx.x; tp<EE/256; tp+=gridDim.x){
    // ---- stage 2 X tiles (bf16 hi/lo) ----
    #pragma unroll
    for (int tt=0;tt<2;tt++){
      const float4* xp=(const float4*)(ele+(long long)(2*tp+tt)*16384);
      for (int i=tid;i<4096;i+=256){
        float4 v=xp[i];
        int r=(i*4)>>7, c=(i*4)&127;
        unsigned h0,l0,h1,l1;
        split2(v.x,v.y,h0,l0); split2(v.z,v.w,h1,l1);
        unsigned off=(unsigned)(r*LD1+c)*2u;
        *(uint2*)(smc+tt*34816+off)=make_uint2(h0,h1);
        *(uint2*)(smc+69632+tt*34816+off)=make_uint2(l0,l1);
      }
    }
    __syncthreads();

    // ---- layer 1: K=128, N=64, 2 tiles ----
    float acc[2][8][4];
    #pragma unroll
    for(int tt=0;tt<2;tt++)
      #pragma unroll
      for(int nt=0;nt<8;nt++){acc[tt][nt][0]=0.f;acc[tt][nt][1]=0.f;acc[tt][nt][2]=0.f;acc[tt][nt][3]=0.f;}
    #pragma unroll
    for(int kk=0;kk<8;kk++){
      unsigned ah[2][4], al[2][4];
      #pragma unroll
      for(int tt=0;tt<2;tt++){
        ldsm4(ah[tt][0],ah[tt][1],ah[tt][2],ah[tt][3], sb+tt*34816u+(unsigned)(arow*LD1+kk*16+koff)*2u);
        ldsm4(al[tt][0],al[tt][1],al[tt][2],al[tt][3], sb+69632u+tt*34816u+(unsigned)(arow*LD1+kk*16+koff)*2u);
      }
      #pragma unroll
      for(int p=0;p<4;p++){
        unsigned bh[4],bl[4];
        ldsm4(bh[0],bh[1],bh[2],bh[3], sb+W1Hb+(unsigned)((p*16+b4r)*LD1+kk*16+b4k)*2u);
        ldsm4(bl[0],bl[1],bl[2],bl[3], sb+W1Lb+(unsigned)((p*16+b4r)*LD1+kk*16+b4k)*2u);
        #pragma unroll
        for(int tt=0;tt<2;tt++){
          mma16816(acc[tt][2*p],   ah[tt], bh);
          mma16816(acc[tt][2*p],   ah[tt], bl);
          mma16816(acc[tt][2*p],   al[tt], bh);
          mma16816(acc[tt][2*p+1], ah[tt], bh+2);
          mma16816(acc[tt][2*p+1], ah[tt], bl+2);
          mma16816(acc[tt][2*p+1], al[tt], bh+2);
        }
      }
    }
    __syncthreads();   // all warps finished reading X; H may overlay X
    #pragma unroll
    for(int tt=0;tt<2;tt++)
      #pragma unroll
      for(int nt=0;nt<8;nt++){
        int c=nt*8+ec2;
        float f0=acc[tt][nt][0]+b1S[c], f1=acc[tt][nt][1]+b1S[c+1];
        float f2=acc[tt][nt][2]+b1S[c], f3=acc[tt][nt][3]+b1S[c+1];
        f0*=sig_(f0); f1*=sig_(f1); f2*=sig_(f2); f3*=sig_(f3);
        unsigned h,l;
        split2(f0,f1,h,l);
        *(unsigned*)(smc+tt*18432+(er*LD2+c)*2)=h;
        *(unsigned*)(smc+36864+tt*18432+(er*LD2+c)*2)=l;
        split2(f2,f3,h,l);
        *(unsigned*)(smc+tt*18432+((er+8)*LD2+c)*2)=h;
        *(unsigned*)(smc+36864+tt*18432+((er+8)*LD2+c)*2)=l;
      }
    __syncwarp();

    // ---- layer 2: K=64, N=64; G overlays H in place (row-local per warp) ----
    #pragma unroll
    for(int tt=0;tt<2;tt++)
      #pragma unroll
      for(int nt=0;nt<8;nt++){acc[tt][nt][0]=0.f;acc[tt][nt][1]=0.f;acc[tt][nt][2]=0.f;acc[tt][nt][3]=0.f;}
    #pragma unroll
    for(int kk=0;kk<4;kk++){
      unsigned ah[2][4], al[2][4];
      #pragma unroll
      for(int tt=0;tt<2;tt++){
        ldsm4(ah[tt][0],ah[tt][1],ah[tt][2],ah[tt][3], sb+tt*18432u+(unsigned)(arow*LD2+kk*16+koff)*2u);
        ldsm4(al[tt][0],al[tt][1],al[tt][2],al[tt][3], sb+36864u+tt*18432u+(unsigned)(arow*LD2+kk*16+koff)*2u);
      }
      #pragma unroll
      for(int p=0;p<4;p++){
        unsigned bh[4],bl[4];
        ldsm4(bh[0],bh[1],bh[2],bh[3], sb+W2Hb+(unsigned)((p*16+b4r)*LD2+kk*16+b4k)*2u);
        ldsm4(bl[0],bl[1],bl[2],bl[3], sb+W2Lb+(unsigned)((p*16+b4r)*LD2+kk*16+b4k)*2u);
        #pragma unroll
        for(int tt=0;tt<2;tt++){
          mma16816(acc[tt][2*p],   ah[tt], bh);
          mma16816(acc[tt][2*p],   ah[tt], bl);
          mma16816(acc[tt][2*p],   al[tt], bh);
          mma16816(acc[tt][2*p+1], ah[tt], bh+2);
          mma16816(acc[tt][2*p+1], ah[tt], bl+2);
          mma16816(acc[tt][2*p+1], al[tt], bh+2);
        }
      }
    }
    #pragma unroll
    for(int tt=0;tt<2;tt++)
      #pragma unroll
      for(int nt=0;nt<8;nt++){
        int c=nt*8+ec2;
        float f0=acc[tt][nt][0]+b2S[c], f1=acc[tt][nt][1]+b2S[c+1];
        float f2=acc[tt][nt][2]+b2S[c], f3=acc[tt][nt][3]+b2S[c+1];
        f0*=sig_(f0); f1*=sig_(f1); f2*=sig_(f2); f3*=sig_(f3);
        unsigned h,l;
        split2(f0,f1,h,l);
        *(unsigned*)(smc+tt*18432+(er*LD2+c)*2)=h;
        *(unsigned*)(smc+36864+tt*18432+(er*LD2+c)*2)=l;
        split2(f2,f3,h,l);
        *(unsigned*)(smc+tt*18432+((er+8)*LD2+c)*2)=h;
        *(unsigned*)(smc+36864+tt*18432+((er+8)*LD2+c)*2)=l;
      }
    __syncwarp();

    // ---- layer 3: K=64, N=96 ----
    float a3[2][12][4];
    #pragma unroll
    for(int tt=0;tt<2;tt++)
      #pragma unroll
      for(int nt=0;nt<12;nt++){a3[tt][nt][0]=0.f;a3[tt][nt][1]=0.f;a3[tt][nt][2]=0.f;a3[tt][nt][3]=0.f;}
    #pragma unroll
    for(int kk=0;kk<4;kk++){
      unsigned ah[2][4], al[2][4];
      #pragma unroll
      for(int tt=0;tt<2;tt++){
        ldsm4(ah[tt][0],ah[tt][1],ah[tt][2],ah[tt][3], sb+tt*18432u+(unsigned)(arow*LD2+kk*16+koff)*2u);
        ldsm4(al[tt][0],al[tt][1],al[tt][2],al[tt][3], sb+36864u+tt*18432u+(unsigned)(arow*LD2+kk*16+koff)*2u);
      }
      #pragma unroll
      for(int p=0;p<6;p++){
        unsigned bh[4],bl[4];
        ldsm4(bh[0],bh[1],bh[2],bh[3], sb+W3Hb+(unsigned)((p*16+b4r)*LD2+kk*16+b4k)*2u);
        ldsm4(bl[0],bl[1],bl[2],bl[3], sb+W3Lb+(unsigned)((p*16+b4r)*LD2+kk*16+b4k)*2u);
        #pragma unroll
        for(int tt=0;tt<2;tt++){
          mma16816(a3[tt][2*p],   ah[tt], bh);
          mma16816(a3[tt][2*p],   ah[tt], bl);
          mma16816(a3[tt][2*p],   al[tt], bh);
          mma16816(a3[tt][2*p+1], ah[tt], bh+2);
          mma16816(a3[tt][2*p+1], ah[tt], bl+2);
          mma16816(a3[tt][2*p+1], al[tt], bh+2);
        }
      }
    }
    __syncthreads();   // all warps finished reading G; OUT may overlay
    #pragma unroll
    for(int tt=0;tt<2;tt++){
      float* outS=(float*)(smc+tt*50176);
      #pragma unroll
      for(int nt=0;nt<12;nt++){
        int c=nt*8+ec2;
        *(float2*)(outS+er*LDO+c)     = make_float2(a3[tt][nt][0]+b3S[c], a3[tt][nt][1]+b3S[c+1]);
        *(float2*)(outS+(er+8)*LDO+c) = make_float2(a3[tt][nt][2]+b3S[c], a3[tt][nt][3]+b3S[c+1]);
      }
    }
    __syncthreads();
    #pragma unroll
    for(int tt=0;tt<2;tt++){
      const float* outS=(const float*)(smc+tt*50176);
      long long base=(long long)(2*tp+tt)*12288;
      for(int i=tid;i<12288;i+=256){
        int r=i/96, c=i-r*96;
        g_wmlp[base+i]=outS[r*LDO+c];
      }
    }
    __syncthreads();
  }
}

__global__ void __launch_bounds__(512) k_e12(const int* __restrict__ eidx,
   const float* __restrict__ esh, const float* __restrict__ efea,
   const float* __restrict__ Wss0, const float* __restrict__ Wssg, const float* __restrict__ Wsv1,
   const float* __restrict__ Wvv0, const float* __restrict__ Wvvg, const float* __restrict__ Wvs1){
  extern __shared__ float sm[];
  float4* FC = (float4*)sm;
  ulonglong2* W2a = (ulonglong2*)(sm+8192);
  unsigned long long* W2b = (unsigned long long*)(sm+12288);
  float* stage = sm + 14336;
  for (int i=threadIdx.x;i<2048;i+=blockDim.x){
    int u=(i>>5)+128, l=i&31;
    FC[i]=make_float4(Wss0[u*64+2*l], Wss0[u*64+2*l+1], Wssg[u*32+l], Wsv1[u*32+l]);
  }
  for (int i=threadIdx.x;i<1024;i+=blockDim.x){
    int u=(i>>5)+64, l=i&31;
    float w0=Wvv0[u*64+2*l], w1=Wvv0[u*64+2*l+1];
    float wz=Wvvg[u*32+l],   ww=Wvs1[u*32+l];
    W2a[i] = make_ulonglong2(pkab(w0,w1), pkab(wz,ww));
    W2b[i] = pkab(ww,ww);
  }
  __syncthreads();
  int warp=threadIdx.x>>5, lane=threadIdx.x&31, wpb=blockDim.x>>5;
  float* sd0 = stage + warp*2720;
  float* vd  = sd0 + 896;
  float* shS = sd0 + 2688;
  const float inv3 = 0.57735027f, invfan = 0.058925565f;
  const int batches = (EE+6)/7;
  for (int p = blockIdx.x*wpb+warp; p<batches; p+=gridDim.x*wpb){
    int e0 = p*7;
    int nid[7], njd[7];
    #pragma unroll
    for (int k=0;k<7;k++){
      int e = e0+k;
      if (e < EE){
        nid[k]=eidx[e]; njd[k]=eidx[EE+e];
        float4 sh = *(const float4*)(esh + (long long)e*4);
        if (lane==0) *(float4*)(shS + k*4) = sh;
        const float* r = efea + (long long)e*160;
        float x0=r[lane], x1=r[32+lane];
        *(unsigned long long*)(sd0 + k*128 + 2*lane)      = pkab(x0,x0);
        *(unsigned long long*)(sd0 + k*128 + 64 + 2*lane) = pkab(x1,x1);
        float ex=r[64+3*lane], ey=r[65+3*lane], ez=r[66+3*lane];
        float dd=(ex*sh.y+ey*sh.z+ez*sh.w)*inv3;
        float* o = vd + k*256 + lane*8;
        *(float4*)o     = make_float4(dd,dd,ex,ey);
        *(float2*)(o+4) = make_float2(dd,ez);
      } else {
        nid[k]=-1; njd[k]=0;
        *(unsigned long long*)(sd0 + k*128 + 2*lane)      = 0ull;
        *(unsigned long long*)(sd0 + k*128 + 64 + 2*lane) = 0ull;
        float* o = vd + k*256 + lane*8;
        *(float4*)o     = make_float4(0.f,0.f,0.f,0.f);
        *(float2*)(o+4) = make_float2(0.f,0.f);
        if (lane==0) *(float4*)(shS + k*4) = make_float4(0.f,0.f,0.f,0.f);
      }
    }
    __syncwarp();
    unsigned long long a01[7], agt[7];
    #pragma unroll
    for (int k=0;k<7;k++){ a01[k]=0ull; agt[k]=0ull; }
    #pragma unroll 2
    for (int u=0;u<64;u+=2){
      ulonglong2 w0 = *(ulonglong2*)&FC[(u  )*32+lane];
      ulonglong2 w1 = *(ulonglong2*)&FC[(u+1)*32+lane];
      #pragma unroll
      for (int k=0;k<7;k++){
        ulonglong2 xp = *(ulonglong2*)(sd0 + k*128 + 2*u);
        fma2(a01[k], xp.x, w0.x); fma2(agt[k], xp.x, w0.y);
        fma2(a01[k], xp.y, w1.x); fma2(agt[k], xp.y, w1.y);
      }
    }
    unsigned long long b01[7], r01[7], gz2[7];
    #pragma unroll
    for (int k=0;k<7;k++){ b01[k]=0ull; r01[k]=0ull; gz2[k]=0ull; }
    #pragma unroll 4
    for (int u=0;u<32;u++){
      ulonglong2 wa = W2a[u*32+lane];
      unsigned long long wb = W2b[u*32+lane];
      #pragma unroll
      for (int k=0;k<7;k++){
        ulonglong2 t1 = *(ulonglong2*)(vd + k*256 + u*8);
        unsigned long long t2 = *(unsigned long long*)(vd + k*256 + u*8 + 4);
        fma2(b01[k], t1.x, wa.x);
        fma2(r01[k], t1.y, wb);
        fma2(gz2[k], t2,   wa.y);
      }
    }
    #pragma unroll
    for (int k=0;k<7;k++){
      if (nid[k] < 0) continue;
      long long e = e0+k;
      float a0,a1,ag,at,b0,b1,r0,r1,bg,r2;
      up2(a01[k],a0,a1); up2(agt[k],ag,at);
      up2(b01[k],b0,b1); up2(r01[k],r0,r1); up2(gz2[k],bg,r2);
      float4 P = *(const float4*)(g_P + nid[k]*128 + lane*4);
      float4 Q = *(const float4*)(g_Q + njd[k]*128 + lane*4);
      a0+=P.x+Q.x; a1+=P.y+Q.y; ag+=P.z+Q.z; at+=P.w+Q.w;
      float4 sh = *(float4*)(shS + k*4);
      const float* tp  = g_T + nid[k]*384 + lane*12;
      const float* upt = g_U + njd[k]*384 + lane*12;
      float4 t0=*(const float4*)tp,  t1=*(const float4*)(tp+4),  t2=*(const float4*)(tp+8);
      float4 u0=*(const float4*)upt, u1=*(const float4*)(upt+4), u2=*(const float4*)(upt+8);
      float s0x=t0.x+u0.x, s0y=t0.y+u0.y, s0z=t0.z+u0.z, s0w=t0.w+u0.w;
      float s1x=t1.x+u1.x, s1y=t1.y+u1.y, s1z=t1.z+u1.z, s1w=t1.w+u1.w;
      float s2x=t2.x+u2.x, s2y=t2.y+u2.y, s2z=t2.z+u2.z, s2w=t2.w+u2.w;
      b0 += inv3*(s0x*sh.y + s0y*sh.z + s0z*sh.w);
      b1 += inv3*(s0w*sh.y + s1x*sh.z + s1y*sh.w);
      bg += inv3*(s1z*sh.y + s1w*sh.z + s2x*sh.w);
      r0 += s2y; r1 += s2z; r2 += s2w;
      float zs0=(sh.x*a0+b0)*invfan, zs1=(sh.x*a1+b1)*invfan;
      float zg =(sh.x*ag+bg)*invfan;
      const float* wm = g_wmlp + e*96;
      float2 wm01 = *(const float2*)(wm+2*lane);
      float wmv = wm[64+lane];
      zs0 = zs0*sig_(zs0)*wm01.x;
      zs1 = zs1*sig_(zs1)*wm01.y;
      float gv = sig_(zg)*wmv*invfan;
      int n = nid[k];
      atomicAdd((float2*)(g_accs + n*64 + 2*lane), make_float2(zs0, zs1));
      atomicAdd(&g_accv4[n*32+lane],
                make_float4((at*sh.y + r0*sh.x)*gv, (at*sh.z + r1*sh.x)*gv,
                            (at*sh.w + r2*sh.x)*gv, 0.f));
    }
    __syncwarp();
  }
}

__global__ void __launch_bounds__(512) k_node_post(const int* __restrict__ batch,
   const float* __restrict__ ppWs, const float* __restrict__ ppbs, const float* __restrict__ ppWv){
  extern __shared__ float sm[];
  float2* WsS = (float2*)sm;
  float* WvS = sm+4096;
  float* bsS = sm+5120;
  float* stage = sm+5184;
  for (int i=threadIdx.x;i<4096;i+=blockDim.x) sm[i]=ppWs[i];
  for (int i=threadIdx.x;i<1024;i+=blockDim.x) WvS[i]=ppWv[i];
  for (int i=threadIdx.x;i<64;i+=blockDim.x) bsS[i]=ppbs[i];
  __syncthreads();
  int warp=threadIdx.x>>5, lane=threadIdx.x&31, wpb=blockDim.x>>5;
  float*  sS  = stage + warp*192;
  float4* vS  = (float4*)(sS+64);
  for (int n=blockIdx.x*wpb+warp; n<NN; n+=gridDim.x*wpb){
    sS[lane]=g_accs[n*64+lane]; sS[32+lane]=g_accs[n*64+32+lane];
    vS[lane]=g_accv4[n*32+lane];
    __syncwarp();
    float a0=0.f,a1=0.f;
    #pragma unroll 4
    for (int u=0;u<64;u++){
      float x=sS[u]; float2 w=WsS[u*32+lane];
      a0+=x*w.x; a1+=x*w.y;
    }
    float ns0 = a0*0.125f + bsS[2*lane]   + g_scs[n*64+2*lane];
    float ns1 = a1*0.125f + bsS[2*lane+1] + g_scs[n*64+2*lane+1];
    g_ns[n*64+2*lane]=ns0; g_ns[n*64+2*lane+1]=ns1;
    float vx=0.f,vy=0.f,vz=0.f;
    #pragma unroll 4
    for (int u=0;u<32;u++){
      float4 x=vS[u]; float w=WvS[u*32+lane];
      vx+=x.x*w; vy+=x.y*w; vz+=x.z*w;
    }
    float nv0 = vx*0.17677670f + g_scv[n*96+3*lane];
    float nv1 = vy*0.17677670f + g_scv[n*96+3*lane+1];
    float nv2 = vz*0.17677670f + g_scv[n*96+3*lane+2];
    g_nv[n*96+3*lane]=nv0; g_nv[n*96+3*lane+1]=nv1; g_nv[n*96+3*lane+2]=nv2;
    float m = ns0+ns1;
    float q = ns0*ns0+ns1*ns1;
    float pw = nv0*nv0+nv1*nv1+nv2*nv2;
    #pragma unroll
    for (int off=16;off>0;off>>=1){
      m += __shfl_down_sync(0xffffffffu, m, off);
      q += __shfl_down_sync(0xffffffffu, q, off);
      pw += __shfl_down_sync(0xffffffffu, pw, off);
    }
    if (lane==0){
      int g = batch[n];
      atomicAdd(&g_gstat[g],        m*(1.f/64.f));
      atomicAdd(&g_gstat[NG_+g],    q*(1.f/64.f));
      atomicAdd(&g_gstat[2*NG_+g],  pw*(1.f/96.f));
      atomicAdd(&g_gstat[3*NG_+g],  1.f);
    }
    __syncwarp();
  }
}

__global__ void k_groups(){
  int t = threadIdx.x;
  if (t < NG_){
    float c  = fmaxf(g_gstat[3*NG_+t], 1.f);
    float mu = g_gstat[t]/c;
    float vs = g_gstat[NG_+t]/c - mu*mu;
    float vv = g_gstat[2*NG_+t]/c;
    g_gout[t]       = mu;
    g_gout[NG_+t]   = rsqrtf(vs+1e-5f);
    g_gout[2*NG_+t] = rsqrtf(vv+1e-5f);
  }
}

__global__ void k_out(const float* __restrict__ nf, const int* __restrict__ batch,
   const float* __restrict__ lnws, const float* __restrict__ lnbs,
   const float* __restrict__ lnwv, float* __restrict__ out){
  int i = blockIdx.x*blockDim.x+threadIdx.x;
  if (i >= NN*160) return;
  int n = i/160, c = i - n*160;
  int g = batch[n];
  float base = nf[i];
  float o;
  if (c < 64){
    float x = (g_ns[n*64+c] - g_gout[g]) * g_gout[NG_+g];
    o = base + x*lnws[c] + lnbs[c];
  } else {
    int cc = c-64;
    o = base + g_nv[n*96+cc]*g_gout[2*NG_+g]*lnwv[cc/3];
  }
  out[i]=o;
}

extern "C" void kernel_launch(void* const* d_in, const int* in_sizes, int n_in,
                              void* d_out, int out_size){
  const float* nf   =(const float*)d_in[0];
  const float* oh   =(const float*)d_in[1];
  const float* esh  =(const float*)d_in[2];
  const float* efea =(const float*)d_in[3];
  const float* ele  =(const float*)d_in[4];
  const int*   eidx =(const int*)d_in[5];
  const int*   batch=(const int*)d_in[6];
  const float* lpWs =(const float*)d_in[7];
  const float* lpbs =(const float*)d_in[8];
  const float* lpWv =(const float*)d_in[9];
  const float* ppWs =(const float*)d_in[10];
  const float* ppbs =(const float*)d_in[11];
  const float* ppWv =(const float*)d_in[12];
  const float* scWs =(const float*)d_in[13];
  const float* scWv =(const float*)d_in[14];
  const float* Wss0 =(const float*)d_in[15];
  const float* Wvv0 =(const float*)d_in[16];
  const float* Wssg =(const float*)d_in[17];
  const float* Wvvg =(const float*)d_in[18];
  const float* Wsv1 =(const float*)d_in[19];
  const float* Wvs1 =(const float*)d_in[20];
  const float* fcW1 =(const float*)d_in[21];
  const float* fcb1 =(const float*)d_in[22];
  const float* fcW2 =(const float*)d_in[23];
  const float* fcb2 =(const float*)d_in[24];
  const float* fcW3 =(const float*)d_in[25];
  const float* fcb3 =(const float*)d_in[26];
  const float* lnws =(const float*)d_in[27];
  const float* lnbs =(const float*)d_in[28];
  const float* lnwv =(const float*)d_in[29];
  float* out = (float*)d_out;

  const int SM_PRE  = (25664 + 16*192)*4;
  const int SM_PSTV = (24576 + 16*1024)*4;
  const int SM_E12  = (14336 + 16*2720)*4;
  const int SM_POST = (5184  + 16*192)*4;
  cudaFuncSetAttribute(k_node_pre,  cudaFuncAttributeMaxDynamicSharedMemorySize, SM_PRE);
  cudaFuncSetAttribute(k_pstv,      cudaFuncAttributeMaxDynamicSharedMemorySize, SM_PSTV);
  cudaFuncSetAttribute(k_mlp_hmma,  cudaFuncAttributeMaxDynamicSharedMemorySize, MBTOT);
  cudaFuncSetAttribute(k_e12,       cudaFuncAttributeMaxDynamicSharedMemorySize, SM_E12);
  cudaFuncSetAttribute(k_node_post, cudaFuncAttributeMaxDynamicSharedMemorySize, SM_POST);

  k_zero<<<(NN*192 + 4*NG_ + 255)/256, 256>>>();
  k_node_pre<<<148, 512, SM_PRE>>>(nf, oh, lpWs, lpbs, lpWv, scWs, scWv);
  k_pstv<<<148, 512, SM_PSTV>>>(Wss0, Wssg, Wsv1, Wvv0, Wvvg, Wvs1);
  k_mlp_hmma<<<148, 256, MBTOT>>>(ele, fcW1, fcb1, fcW2, fcb2, fcW3, fcb3);
  k_e12<<<148, 512, SM_E12>>>(eidx, esh, efea, Wss0, Wssg, Wsv1, Wvv0, Wvvg, Wvs1);
  k_node_post<<<148, 512, SM_POST>>>(batch, ppWs, ppbs, ppWv);
  k_groups<<<1, 32>>>();
  k_out<<<(NN*160 + 255)/256, 256>>>(nf, batch, lnws, lnbs, lnwv, out);
}

// round 13
// speedup vs baseline: 1.2021x; 1.0628x over previous
#include <cuda_runtime.h>
#include <cuda_bf16.h>
#include <cstdint>

#define NN 10000
#define EE 320000
#define NG_ 16

__device__ float  g_s[NN*64];
__device__ float4 g_v4[NN*32];
__device__ float  g_scs[NN*64];
__device__ float  g_scv[NN*96];
__device__ float  g_accs[NN*64];
__device__ float4 g_accv4[NN*32];
__device__ float  g_ns[NN*64];
__device__ float  g_nv[NN*96];
__device__ float  g_wmlp[(long long)EE*96];
__device__ float  g_P[NN*128];
__device__ float  g_Q[NN*128];
__device__ float  g_T[NN*384];
__device__ float  g_U[NN*384];
__device__ float  g_gstat[4*NG_];
__device__ float  g_gout[3*NG_];

__device__ __forceinline__ float sig_(float x){ return 1.f/(1.f+__expf(-x)); }
__device__ __forceinline__ unsigned long long pk2(float x){
  unsigned long long r; asm("mov.b64 %0, {%1, %1};" : "=l"(r) : "f"(x)); return r; }
__device__ __forceinline__ unsigned long long pkab(float a, float b){
  unsigned long long r; asm("mov.b64 %0, {%1, %2};" : "=l"(r) : "f"(a), "f"(b)); return r; }
__device__ __forceinline__ void up2(unsigned long long v, float &a, float &b){
  asm("mov.b64 {%0, %1}, %2;" : "=f"(a), "=f"(b) : "l"(v)); }
__device__ __forceinline__ void fma2(unsigned long long &d, unsigned long long a, unsigned long long b){
  asm("fma.rn.f32x2 %0, %1, %2, %3;" : "=l"(d) : "l"(a), "l"(b), "l"(d)); }
__device__ __forceinline__ unsigned int s2u_(const void* p){
  unsigned int a; asm("{ .reg .u64 t; cvta.to.shared.u64 t, %1; cvt.u32.u64 %0, t; }" : "=r"(a) : "l"(p)); return a; }

__device__ __forceinline__ void ldsm4(unsigned &r0,unsigned &r1,unsigned &r2,unsigned &r3, unsigned a){
  asm volatile("ldmatrix.sync.aligned.m8n8.x4.shared.b16 {%0,%1,%2,%3}, [%4];"
    : "=r"(r0),"=r"(r1),"=r"(r2),"=r"(r3) : "r"(a)); }
__device__ __forceinline__ void mma16816(float* c, const unsigned* a, const unsigned* b){
  asm volatile("mma.sync.aligned.m16n8k16.row.col.f32.bf16.bf16.f32 "
    "{%0,%1,%2,%3}, {%4,%5,%6,%7}, {%8,%9}, {%0,%1,%2,%3};"
    : "+f"(c[0]),"+f"(c[1]),"+f"(c[2]),"+f"(c[3])
    : "r"(a[0]),"r"(a[1]),"r"(a[2]),"r"(a[3]), "r"(b[0]),"r"(b[1])); }
__device__ __forceinline__ void split2(float a, float b, unsigned &h, unsigned &l){
  __nv_bfloat16 ha=__float2bfloat16(a), hb=__float2bfloat16(b);
  float la=a-__bfloat162float(ha), lb=b-__bfloat162float(hb);
  __nv_bfloat162 hh=__halves2bfloat162(ha,hb);
  __nv_bfloat162 ll=__halves2bfloat162(__float2bfloat16(la),__float2bfloat16(lb));
  h=*(unsigned*)&hh; l=*(unsigned*)&ll; }

__global__ void k_zero(){
  int i = blockIdx.x*blockDim.x + threadIdx.x;
  if (i < NN*64) g_accs[i] = 0.f;
  int j = i - NN*64;
  if (j >= 0 && j < NN*128) ((float*)g_accv4)[j] = 0.f;
  int k = i - NN*192;
  if (k >= 0 && k < 4*NG_) g_gstat[k] = 0.f;
}

__global__ void __launch_bounds__(512) k_node_pre(const float* __restrict__ nf,
   const float* __restrict__ oh, const float* __restrict__ lpWs, const float* __restrict__ lpbs,
   const float* __restrict__ lpWv, const float* __restrict__ scWs, const float* __restrict__ scWv){
  extern __shared__ float sm[];
  float2* WsS  = (float2*)sm;
  float*  WvS  = sm + 4096;
  float2* sWsS = (float2*)(sm + 5120);
  float*  sWvS = sm + 21504;
  float*  bsS  = sm + 25600;
  float*  stage= sm + 25664;
  for (int i=threadIdx.x;i<4096;i+=blockDim.x) sm[i]=lpWs[i];
  for (int i=threadIdx.x;i<1024;i+=blockDim.x) WvS[i]=lpWv[i];
  for (int i=threadIdx.x;i<16384;i+=blockDim.x) sm[5120+i]=scWs[i];
  for (int i=threadIdx.x;i<4096;i+=blockDim.x) sWvS[i]=scWv[i];
  for (int i=threadIdx.x;i<64;i+=blockDim.x) bsS[i]=lpbs[i];
  __syncthreads();
  int warp = threadIdx.x>>5, lane = threadIdx.x&31, wpb = blockDim.x>>5;
  float*  sS  = stage + warp*192;
  float4* vS  = (float4*)(sS + 64);
  for (int n = blockIdx.x*wpb + warp; n < NN; n += gridDim.x*wpb){
    const float* row = nf + n*160;
    sS[lane] = row[lane]; sS[32+lane] = row[32+lane];
    vS[lane] = make_float4(row[64+3*lane], row[65+3*lane], row[66+3*lane], 0.f);
    const float* o4 = oh + n*4;
    int sp = (o4[1]>0.5f)?1:((o4[2]>0.5f)?2:((o4[3]>0.5f)?3:0));
    __syncwarp();
    float a0=0.f,a1=0.f,c0=0.f,c1=0.f;
    #pragma unroll 4
    for (int u=0;u<64;u++){
      float x = sS[u];
      float2 w  = WsS[u*32+lane];
      float2 w2 = sWsS[(u*4+sp)*32+lane];
      a0+=x*w.x; a1+=x*w.y; c0+=x*w2.x; c1+=x*w2.y;
    }
    g_s[n*64+2*lane]   = a0*0.125f + bsS[2*lane];
    g_s[n*64+2*lane+1] = a1*0.125f + bsS[2*lane+1];
    g_scs[n*64+2*lane]   = c0*0.0625f;
    g_scs[n*64+2*lane+1] = c1*0.0625f;
    float vx=0.f,vy=0.f,vz=0.f,cx=0.f,cy=0.f,cz=0.f;
    #pragma unroll 4
    for (int u=0;u<32;u++){
      float4 x = vS[u];
      float w  = WvS[u*32+lane];
      float w2 = sWvS[(u*4+sp)*32+lane];
      vx+=x.x*w;  vy+=x.y*w;  vz+=x.z*w;
      cx+=x.x*w2; cy+=x.y*w2; cz+=x.z*w2;
    }
    g_v4[n*32+lane] = make_float4(vx*0.17677670f, vy*0.17677670f, vz*0.17677670f, 0.f);
    g_scv[n*96+3*lane]   = cx*0.08838835f;
    g_scv[n*96+3*lane+1] = cy*0.08838835f;
    g_scv[n*96+3*lane+2] = cz*0.08838835f;
    __syncwarp();
  }
}

__global__ void __launch_bounds__(512) k_pstv(const float* __restrict__ Wss0,
   const float* __restrict__ Wssg, const float* __restrict__ Wsv1,
   const float* __restrict__ Wvv0, const float* __restrict__ Wvvg, const float* __restrict__ Wvs1){
  extern __shared__ float sm[];
  float4* FA = (float4*)sm;
  float4* FB = (float4*)(sm+8192);
  float4* GA = (float4*)(sm+16384);
  float4* GB = (float4*)(sm+20480);
  float* stage = sm + 24576;
  for (int i=threadIdx.x;i<2048;i+=blockDim.x){
    int u=i>>5, l=i&31;
    FA[i]=make_float4(Wss0[u*64+2*l], Wss0[u*64+2*l+1], Wssg[u*32+l], Wsv1[u*32+l]);
    int u2=u+64;
    FB[i]=make_float4(Wss0[u2*64+2*l], Wss0[u2*64+2*l+1], Wssg[u2*32+l], Wsv1[u2*32+l]);
  }
  for (int i=threadIdx.x;i<1024;i+=blockDim.x){
    int u=i>>5, l=i&31;
    GA[i]=make_float4(Wvv0[u*64+2*l], Wvv0[u*64+2*l+1], Wvvg[u*32+l], Wvs1[u*32+l]);
    int u2=u+32;
    GB[i]=make_float4(Wvv0[u2*64+2*l], Wvv0[u2*64+2*l+1], Wvvg[u2*32+l], Wvs1[u2*32+l]);
  }
  __syncthreads();
  int warp=threadIdx.x>>5, lane=threadIdx.x&31, wpb=blockDim.x>>5;
  float* sd = stage + warp*1024;
  const int b1 = NN/8;
  for (int p = blockIdx.x*wpb+warp; p<b1; p+=gridDim.x*wpb){
    int n0 = p*8;
    #pragma unroll
    for (int k=0;k<8;k++){
      int n = n0+k;
      float x0 = g_s[n*64+lane];
      float x1 = g_s[n*64+32+lane];
      *(unsigned long long*)(sd + k*128 + 2*lane)      = pkab(x0,x0);
      *(unsigned long long*)(sd + k*128 + 64 + 2*lane) = pkab(x1,x1);
    }
    __syncwarp();
    unsigned long long pa[8], pg[8], qa[8], qg[8];
    #pragma unroll
    for (int k=0;k<8;k++){ pa[k]=0ull; pg[k]=0ull; qa[k]=0ull; qg[k]=0ull; }
    #pragma unroll 2
    for (int u=0;u<64;u+=2){
      ulonglong2 wa0 = *(ulonglong2*)&FA[(u  )*32+lane];
      ulonglong2 wa1 = *(ulonglong2*)&FA[(u+1)*32+lane];
      ulonglong2 wb0 = *(ulonglong2*)&FB[(u  )*32+lane];
      ulonglong2 wb1 = *(ulonglong2*)&FB[(u+1)*32+lane];
      #pragma unroll
      for (int k=0;k<8;k++){
        ulonglong2 xp = *(ulonglong2*)(sd + k*128 + 2*u);
        fma2(pa[k], xp.x, wa0.x); fma2(pg[k], xp.x, wa0.y);
        fma2(qa[k], xp.x, wb0.x); fma2(qg[k], xp.x, wb0.y);
        fma2(pa[k], xp.y, wa1.x); fma2(pg[k], xp.y, wa1.y);
        fma2(qa[k], xp.y, wb1.x); fma2(qg[k], xp.y, wb1.y);
      }
    }
    #pragma unroll
    for (int k=0;k<8;k++){
      int n = n0+k;
      float a0,a1,ag,at;
      up2(pa[k],a0,a1); up2(pg[k],ag,at);
      *(float4*)(g_P + n*128 + lane*4) = make_float4(a0,a1,ag,at);
      up2(qa[k],a0,a1); up2(qg[k],ag,at);
      *(float4*)(g_Q + n*128 + lane*4) = make_float4(a0,a1,ag,at);
    }
    __syncwarp();
  }
  float4* vst = (float4*)sd;
  const int b2 = NN/4;
  for (int p = blockIdx.x*wpb+warp; p<b2; p+=gridDim.x*wpb){
    int n0 = p*4;
    #pragma unroll
    for (int k=0;k<4;k++) vst[k*32+lane] = g_v4[(n0+k)*32+lane];
    __syncwarp();
    unsigned long long t01[4][3], tgr[4][3], u01[4][3], ugr[4][3];
    #pragma unroll
    for (int k=0;k<4;k++)
      #pragma unroll
      for (int c=0;c<3;c++){ t01[k][c]=0ull; tgr[k][c]=0ull; u01[k][c]=0ull; ugr[k][c]=0ull; }
    #pragma unroll 2
    for (int u=0;u<32;u++){
      ulonglong2 ga = *(ulonglong2*)&GA[u*32+lane];
      ulonglong2 gb = *(ulonglong2*)&GB[u*32+lane];
      #pragma unroll
      for (int k=0;k<4;k++){
        float4 v = vst[k*32+u];
        unsigned long long vx=pk2(v.x), vy=pk2(v.y), vz=pk2(v.z);
        fma2(t01[k][0], vx, ga.x); fma2(t01[k][1], vy, ga.x); fma2(t01[k][2], vz, ga.x);
        fma2(tgr[k][0], vx, ga.y); fma2(tgr[k][1], vy, ga.y); fma2(tgr[k][2], vz, ga.y);
        fma2(u01[k][0], vx, gb.x); fma2(u01[k][1], vy, gb.x); fma2(u01[k][2], vz, gb.x);
        fma2(ugr[k][0], vx, gb.y); fma2(ugr[k][1], vy, gb.y); fma2(ugr[k][2], vz, gb.y);
      }
    }
    #pragma unroll
    for (int k=0;k<4;k++){
      int n = n0+k;
      float b0x,b1x,b0y,b1y,b0z,b1z,bgx,rx,bgy,ry,bgz,rz;
      up2(t01[k][0],b0x,b1x); up2(t01[k][1],b0y,b1y); up2(t01[k][2],b0z,b1z);
      up2(tgr[k][0],bgx,rx);  up2(tgr[k][1],bgy,ry);  up2(tgr[k][2],bgz,rz);
      float* o = g_T + n*384 + lane*12;
      *(float4*)(o  ) = make_float4(b0x,b0y,b0z,b1x);
      *(float4*)(o+4) = make_float4(b1y,b1z,bgx,bgy);
      *(float4*)(o+8) = make_float4(bgz,rx,ry,rz);
      up2(u01[k][0],b0x,b1x); up2(u01[k][1],b0y,b1y); up2(u01[k][2],b0z,b1z);
      up2(ugr[k][0],bgx,rx);  up2(ugr[k][1],bgy,ry);  up2(ugr[k][2],bgz,rz);
      o = g_U + n*384 + lane*12;
      *(float4*)(o  ) = make_float4(b0x,b0y,b0z,b1x);
      *(float4*)(o+4) = make_float4(b1y,b1z,bgx,bgy);
      *(float4*)(o+8) = make_float4(bgz,rx,ry,rz);
    }
    __syncwarp();
  }
}

// ---------------- HMMA MLP: 1250 pairs of 128-edge tiles, 16 warps ----------------
#define LD1 136
#define LD2 72
#define LDO 98
#define W1Hb 139264
#define W1Lb 156672
#define W2Hb 174080
#define W2Lb 183296
#define W3Hb 192512
#define W3Lb 206336
#define B1b  220160
#define B2b  220416
#define B3b  220672
#define MBTOT 221056

__global__ void __launch_bounds__(512) k_mlp_hmma(const float* __restrict__ ele,
   const float* __restrict__ W1, const float* __restrict__ b1,
   const float* __restrict__ W2, const float* __restrict__ b2,
   const float* __restrict__ W3, const float* __restrict__ b3){
  extern __shared__ char smc[];
  unsigned int sb = s2u_(smc);
  int tid=threadIdx.x, wid=tid>>5, lane=tid&31;
  for (int i=tid;i<64*128;i+=512){
    int n=i>>7,k=i&127; float w=W1[k*64+n];
    __nv_bfloat16 h=__float2bfloat16(w);
    *(__nv_bfloat16*)(smc+W1Hb+(n*LD1+k)*2)=h;
    *(__nv_bfloat16*)(smc+W1Lb+(n*LD1+k)*2)=__float2bfloat16(w-__bfloat162float(h));
  }
  for (int i=tid;i<64*64;i+=512){
    int n=i>>6,k=i&63; float w=W2[k*64+n];
    __nv_bfloat16 h=__float2bfloat16(w);
    *(__nv_bfloat16*)(smc+W2Hb+(n*LD2+k)*2)=h;
    *(__nv_bfloat16*)(smc+W2Lb+(n*LD2+k)*2)=__float2bfloat16(w-__bfloat162float(h));
  }
  for (int i=tid;i<96*64;i+=512){
    int n=i>>6,k=i&63; float w=W3[k*96+n];
    __nv_bfloat16 h=__float2bfloat16(w);
    *(__nv_bfloat16*)(smc+W3Hb+(n*LD2+k)*2)=h;
    *(__nv_bfloat16*)(smc+W3Lb+(n*LD2+k)*2)=__float2bfloat16(w-__bfloat162float(h));
  }
  float* b1S=(float*)(smc+B1b); float* b2S=(float*)(smc+B2b); float* b3S=(float*)(smc+B3b);
  if (tid<64){ b1S[tid]=b1[tid]; b2S[tid]=b2[tid]; }
  if (tid<96) b3S[tid]=b3[tid];
  __syncthreads();

  int tt  = wid>>3;          // tile index 0/1
  int w8  = wid&7;           // warp within tile
  int r0  = w8*16;
  int arow = r0 + (lane&15);
  int koff = (lane>>4)<<3;
  int b4r  = (lane&7) + ((lane>>4)<<3);
  int b4k  = ((lane>>3)&1)<<3;
  int er = r0+(lane>>2), ec2=(lane&3)*2;
  unsigned xb  = sb + (unsigned)tt*34816u;           // X hi base for this tile
  unsigned xlb = sb + 69632u + (unsigned)tt*34816u;  // X lo
  unsigned hb  = sb + (unsigned)tt*18432u;           // H/G hi (overlays X)
  unsigned hlb = sb + 36864u + (unsigned)tt*18432u;  // H/G lo
  char* hbc  = smc + tt*18432;
  char* hlbc = smc + 36864 + tt*18432;

  for (int tp=blockIdx.x; tp<EE/256; tp+=gridDim.x){
    // ---- stage 2 X tiles ----
    #pragma unroll
    for (int st=0;st<2;st++){
      const float4* xp=(const float4*)(ele+(long long)(2*tp+st)*16384);
      for (int i=tid;i<4096;i+=512){
        float4 v=xp[i];
        int r=(i*4)>>7, c=(i*4)&127;
        unsigned h0,l0,h1,l1;
        split2(v.x,v.y,h0,l0); split2(v.z,v.w,h1,l1);
        unsigned off=(unsigned)(r*LD1+c)*2u;
        *(uint2*)(smc+st*34816+off)=make_uint2(h0,h1);
        *(uint2*)(smc+69632+st*34816+off)=make_uint2(l0,l1);
      }
    }
    __syncthreads();

    // ---- layer 1: K=128, N=64 ----
    float acc[8][4];
    #pragma unroll
    for(int nt=0;nt<8;nt++){acc[nt][0]=0.f;acc[nt][1]=0.f;acc[nt][2]=0.f;acc[nt][3]=0.f;}
    #pragma unroll
    for(int kk=0;kk<8;kk++){
      unsigned ah[4], al[4];
      ldsm4(ah[0],ah[1],ah[2],ah[3], xb +(unsigned)(arow*LD1+kk*16+koff)*2u);
      ldsm4(al[0],al[1],al[2],al[3], xlb+(unsigned)(arow*LD1+kk*16+koff)*2u);
      #pragma unroll
      for(int p=0;p<4;p++){
        unsigned bh[4],bl[4];
        ldsm4(bh[0],bh[1],bh[2],bh[3], sb+W1Hb+(unsigned)((p*16+b4r)*LD1+kk*16+b4k)*2u);
        ldsm4(bl[0],bl[1],bl[2],bl[3], sb+W1Lb+(unsigned)((p*16+b4r)*LD1+kk*16+b4k)*2u);
        mma16816(acc[2*p],   ah, bh);
        mma16816(acc[2*p],   ah, bl);
        mma16816(acc[2*p],   al, bh);
        mma16816(acc[2*p+1], ah, bh+2);
        mma16816(acc[2*p+1], ah, bl+2);
        mma16816(acc[2*p+1], al, bh+2);
      }
    }
    __syncthreads();   // all warps done reading X; H may overlay X
    #pragma unroll
    for(int nt=0;nt<8;nt++){
      int c=nt*8+ec2;
      float f0=acc[nt][0]+b1S[c], f1=acc[nt][1]+b1S[c+1];
      float f2=acc[nt][2]+b1S[c], f3=acc[nt][3]+b1S[c+1];
      f0*=sig_(f0); f1*=sig_(f1); f2*=sig_(f2); f3*=sig_(f3);
      unsigned h,l;
      split2(f0,f1,h,l);
      *(unsigned*)(hbc +(er*LD2+c)*2)=h;
      *(unsigned*)(hlbc+(er*LD2+c)*2)=l;
      split2(f2,f3,h,l);
      *(unsigned*)(hbc +((er+8)*LD2+c)*2)=h;
      *(unsigned*)(hlbc+((er+8)*LD2+c)*2)=l;
    }
    __syncwarp();

    // ---- layer 2: K=64, N=64; G overlays H in place (rows warp-private) ----
    #pragma unroll
    for(int nt=0;nt<8;nt++){acc[nt][0]=0.f;acc[nt][1]=0.f;acc[nt][2]=0.f;acc[nt][3]=0.f;}
    #pragma unroll
    for(int kk=0;kk<4;kk++){
      unsigned ah[4], al[4];
      ldsm4(ah[0],ah[1],ah[2],ah[3], hb +(unsigned)(arow*LD2+kk*16+koff)*2u);
      ldsm4(al[0],al[1],al[2],al[3], hlb+(unsigned)(arow*LD2+kk*16+koff)*2u);
      #pragma unroll
      for(int p=0;p<4;p++){
        unsigned bh[4],bl[4];
        ldsm4(bh[0],bh[1],bh[2],bh[3], sb+W2Hb+(unsigned)((p*16+b4r)*LD2+kk*16+b4k)*2u);
        ldsm4(bl[0],bl[1],bl[2],bl[3], sb+W2Lb+(unsigned)((p*16+b4r)*LD2+kk*16+b4k)*2u);
        mma16816(acc[2*p],   ah, bh);
        mma16816(acc[2*p],   ah, bl);
        mma16816(acc[2*p],   al, bh);
        mma16816(acc[2*p+1], ah, bh+2);
        mma16816(acc[2*p+1], ah, bl+2);
        mma16816(acc[2*p+1], al, bh+2);
      }
    }
    #pragma unroll
    for(int nt=0;nt<8;nt++){
      int c=nt*8+ec2;
      float f0=acc[nt][0]+b2S[c], f1=acc[nt][1]+b2S[c+1];
      float f2=acc[nt][2]+b2S[c], f3=acc[nt][3]+b2S[c+1];
      f0*=sig_(f0); f1*=sig_(f1); f2*=sig_(f2); f3*=sig_(f3);
      unsigned h,l;
      split2(f0,f1,h,l);
      *(unsigned*)(hbc +(er*LD2+c)*2)=h;
      *(unsigned*)(hlbc+(er*LD2+c)*2)=l;
      split2(f2,f3,h,l);
      *(unsigned*)(hbc +((er+8)*LD2+c)*2)=h;
      *(unsigned*)(hlbc+((er+8)*LD2+c)*2)=l;
    }
    __syncwarp();

    // ---- layer 3: K=64, N=96 ----
    float a3[12][4];
    #pragma unroll
    for(int nt=0;nt<12;nt++){a3[nt][0]=0.f;a3[nt][1]=0.f;a3[nt][2]=0.f;a3[nt][3]=0.f;}
    #pragma unroll
    for(int kk=0;kk<4;kk++){
      unsigned ah[4], al[4];
      ldsm4(ah[0],ah[1],ah[2],ah[3], hb +(unsigned)(arow*LD2+kk*16+koff)*2u);
      ldsm4(al[0],al[1],al[2],al[3], hlb+(unsigned)(arow*LD2+kk*16+koff)*2u);
      #pragma unroll
      for(int p=0;p<6;p++){
        unsigned bh[4],bl[4];
        ldsm4(bh[0],bh[1],bh[2],bh[3], sb+W3Hb+(unsigned)((p*16+b4r)*LD2+kk*16+b4k)*2u);
        ldsm4(bl[0],bl[1],bl[2],bl[3], sb+W3Lb+(unsigned)((p*16+b4r)*LD2+kk*16+b4k)*2u);
        mma16816(a3[2*p],   ah, bh);
        mma16816(a3[2*p],   ah, bl);
        mma16816(a3[2*p],   al, bh);
        mma16816(a3[2*p+1], ah, bh+2);
        mma16816(a3[2*p+1], ah, bl+2);
        mma16816(a3[2*p+1], al, bh+2);
      }
    }
    __syncthreads();   // all warps done reading G; OUT may overlay
    {
      float* outS=(float*)(smc+tt*50176);
      #pragma unroll
      for(int nt=0;nt<12;nt++){
        int c=nt*8+ec2;
        *(float2*)(outS+er*LDO+c)     = make_float2(a3[nt][0]+b3S[c], a3[nt][1]+b3S[c+1]);
        *(float2*)(outS+(er+8)*LDO+c) = make_float2(a3[nt][2]+b3S[c], a3[nt][3]+b3S[c+1]);
      }
    }
    __syncthreads();
    #pragma unroll
    for(int st=0;st<2;st++){
      const float* outS=(const float*)(smc+st*50176);
      long long base=(long long)(2*tp+st)*12288;
      for(int i=tid;i<12288;i+=512){
        int r=i/96, c=i-r*96;
        g_wmlp[base+i]=outS[r*LDO+c];
      }
    }
    __syncthreads();
  }
}

__global__ void __launch_bounds__(512) k_e12(const int* __restrict__ eidx,
   const float* __restrict__ esh, const float* __restrict__ efea,
   const float* __restrict__ Wss0, const float* __restrict__ Wssg, const float* __restrict__ Wsv1,
   const float* __restrict__ Wvv0, const float* __restrict__ Wvvg, const float* __restrict__ Wvs1){
  extern __shared__ float sm[];
  float4* FC = (float4*)sm;
  ulonglong2* W2a = (ulonglong2*)(sm+8192);
  unsigned long long* W2b = (unsigned long long*)(sm+12288);
  float* stage = sm + 14336;
  for (int i=threadIdx.x;i<2048;i+=blockDim.x){
    int u=(i>>5)+128, l=i&31;
    FC[i]=make_float4(Wss0[u*64+2*l], Wss0[u*64+2*l+1], Wssg[u*32+l], Wsv1[u*32+l]);
  }
  for (int i=threadIdx.x;i<1024;i+=blockDim.x){
    int u=(i>>5)+64, l=i&31;
    float w0=Wvv0[u*64+2*l], w1=Wvv0[u*64+2*l+1];
    float wz=Wvvg[u*32+l],   ww=Wvs1[u*32+l];
    W2a[i] = make_ulonglong2(pkab(w0,w1), pkab(wz,ww));
    W2b[i] = pkab(ww,ww);
  }
  __syncthreads();
  int warp=threadIdx.x>>5, lane=threadIdx.x&31, wpb=blockDim.x>>5;
  float* sd0 = stage + warp*2720;
  float* vd  = sd0 + 896;
  float* shS = sd0 + 2688;
  const float inv3 = 0.57735027f, invfan = 0.058925565f;
  const int batches = (EE+6)/7;
  for (int p = blockIdx.x*wpb+warp; p<batches; p+=gridDim.x*wpb){
    int e0 = p*7;
    int nid[7], njd[7];
    #pragma unroll
    for (int k=0;k<7;k++){
      int e = e0+k;
      if (e < EE){
        nid[k]=eidx[e]; njd[k]=eidx[EE+e];
        float4 sh = *(const float4*)(esh + (long long)e*4);
        if (lane==0) *(float4*)(shS + k*4) = sh;
        const float* r = efea + (long long)e*160;
        float x0=r[lane], x1=r[32+lane];
        *(unsigned long long*)(sd0 + k*128 + 2*lane)      = pkab(x0,x0);
        *(unsigned long long*)(sd0 + k*128 + 64 + 2*lane) = pkab(x1,x1);
        float ex=r[64+3*lane], ey=r[65+3*lane], ez=r[66+3*lane];
        float dd=(ex*sh.y+ey*sh.z+ez*sh.w)*inv3;
        float* o = vd + k*256 + lane*8;
        *(float4*)o     = make_float4(dd,dd,ex,ey);
        *(float2*)(o+4) = make_float2(dd,ez);
      } else {
        nid[k]=-1; njd[k]=0;
        *(unsigned long long*)(sd0 + k*128 + 2*lane)      = 0ull;
        *(unsigned long long*)(sd0 + k*128 + 64 + 2*lane) = 0ull;
        float* o = vd + k*256 + lane*8;
        *(float4*)o     = make_float4(0.f,0.f,0.f,0.f);
        *(float2*)(o+4) = make_float2(0.f,0.f);
        if (lane==0) *(float4*)(shS + k*4) = make_float4(0.f,0.f,0.f,0.f);
      }
    }
    __syncwarp();
    unsigned long long a01[7], agt[7];
    #pragma unroll
    for (int k=0;k<7;k++){ a01[k]=0ull; agt[k]=0ull; }
    #pragma unroll 2
    for (int u=0;u<64;u+=2){
      ulonglong2 w0 = *(ulonglong2*)&FC[(u  )*32+lane];
      ulonglong2 w1 = *(ulonglong2*)&FC[(u+1)*32+lane];
      #pragma unroll
      for (int k=0;k<7;k++){
        ulonglong2 xp = *(ulonglong2*)(sd0 + k*128 + 2*u);
        fma2(a01[k], xp.x, w0.x); fma2(agt[k], xp.x, w0.y);
        fma2(a01[k], xp.y, w1.x); fma2(agt[k], xp.y, w1.y);
      }
    }
    unsigned long long b01[7], r01[7], gz2[7];
    #pragma unroll
    for (int k=0;k<7;k++){ b01[k]=0ull; r01[k]=0ull; gz2[k]=0ull; }
    #pragma unroll 4
    for (int u=0;u<32;u++){
      ulonglong2 wa = W2a[u*32+lane];
      unsigned long long wb = W2b[u*32+lane];
      #pragma unroll
      for (int k=0;k<7;k++){
        ulonglong2 t1 = *(ulonglong2*)(vd + k*256 + u*8);
        unsigned long long t2 = *(unsigned long long*)(vd + k*256 + u*8 + 4);
        fma2(b01[k], t1.x, wa.x);
        fma2(r01[k], t1.y, wb);
        fma2(gz2[k], t2,   wa.y);
      }
    }
    #pragma unroll
    for (int k=0;k<7;k++){
      if (nid[k] < 0) continue;
      long long e = e0+k;
      float a0,a1,ag,at,b0,b1,r0,r1,bg,r2;
      up2(a01[k],a0,a1); up2(agt[k],ag,at);
      up2(b01[k],b0,b1); up2(r01[k],r0,r1); up2(gz2[k],bg,r2);
      float4 P = *(const float4*)(g_P + nid[k]*128 + lane*4);
      float4 Q = *(const float4*)(g_Q + njd[k]*128 + lane*4);
      a0+=P.x+Q.x; a1+=P.y+Q.y; ag+=P.z+Q.z; at+=P.w+Q.w;
      float4 sh = *(float4*)(shS + k*4);
      const float* tp  = g_T + nid[k]*384 + lane*12;
      const float* upt = g_U + njd[k]*384 + lane*12;
      float4 t0=*(const float4*)tp,  t1=*(const float4*)(tp+4),  t2=*(const float4*)(tp+8);
      float4 u0=*(const float4*)upt, u1=*(const float4*)(upt+4), u2=*(const float4*)(upt+8);
      float s0x=t0.x+u0.x, s0y=t0.y+u0.y, s0z=t0.z+u0.z, s0w=t0.w+u0.w;
      float s1x=t1.x+u1.x, s1y=t1.y+u1.y, s1z=t1.z+u1.z, s1w=t1.w+u1.w;
      float s2x=t2.x+u2.x, s2y=t2.y+u2.y, s2z=t2.z+u2.z, s2w=t2.w+u2.w;
      b0 += inv3*(s0x*sh.y + s0y*sh.z + s0z*sh.w);
      b1 += inv3*(s0w*sh.y + s1x*sh.z + s1y*sh.w);
      bg += inv3*(s1z*sh.y + s1w*sh.z + s2x*sh.w);
      r0 += s2y; r1 += s2z; r2 += s2w;
      float zs0=(sh.x*a0+b0)*invfan, zs1=(sh.x*a1+b1)*invfan;
      float zg =(sh.x*ag+bg)*invfan;
      const float* wm = g_wmlp + e*96;
      float2 wm01 = *(const float2*)(wm+2*lane);
      float wmv = wm[64+lane];
      zs0 = zs0*sig_(zs0)*wm01.x;
      zs1 = zs1*sig_(zs1)*wm01.y;
      float gv = sig_(zg)*wmv*invfan;
      int n = nid[k];
      atomicAdd((float2*)(g_accs + n*64 + 2*lane), make_float2(zs0, zs1));
      atomicAdd(&g_accv4[n*32+lane],
                make_float4((at*sh.y + r0*sh.x)*gv, (at*sh.z + r1*sh.x)*gv,
                            (at*sh.w + r2*sh.x)*gv, 0.f));
    }
    __syncwarp();
  }
}

__global__ void __launch_bounds__(512) k_node_post(const int* __restrict__ batch,
   const float* __restrict__ ppWs, const float* __restrict__ ppbs, const float* __restrict__ ppWv){
  extern __shared__ float sm[];
  float2* WsS = (float2*)sm;
  float* WvS = sm+4096;
  float* bsS = sm+5120;
  float* stage = sm+5184;
  for (int i=threadIdx.x;i<4096;i+=blockDim.x) sm[i]=ppWs[i];
  for (int i=threadIdx.x;i<1024;i+=blockDim.x) WvS[i]=ppWv[i];
  for (int i=threadIdx.x;i<64;i+=blockDim.x) bsS[i]=ppbs[i];
  __syncthreads();
  int warp=threadIdx.x>>5, lane=threadIdx.x&31, wpb=blockDim.x>>5;
  float*  sS  = stage + warp*192;
  float4* vS  = (float4*)(sS+64);
  for (int n=blockIdx.x*wpb+warp; n<NN; n+=gridDim.x*wpb){
    sS[lane]=g_accs[n*64+lane]; sS[32+lane]=g_accs[n*64+32+lane];
    vS[lane]=g_accv4[n*32+lane];
    __syncwarp();
    float a0=0.f,a1=0.f;
    #pragma unroll 4
    for (int u=0;u<64;u++){
      float x=sS[u]; float2 w=WsS[u*32+lane];
      a0+=x*w.x; a1+=x*w.y;
    }
    float ns0 = a0*0.125f + bsS[2*lane]   + g_scs[n*64+2*lane];
    float ns1 = a1*0.125f + bsS[2*lane+1] + g_scs[n*64+2*lane+1];
    g_ns[n*64+2*lane]=ns0; g_ns[n*64+2*lane+1]=ns1;
    float vx=0.f,vy=0.f,vz=0.f;
    #pragma unroll 4
    for (int u=0;u<32;u++){
      float4 x=vS[u]; float w=WvS[u*32+lane];
      vx+=x.x*w; vy+=x.y*w; vz+=x.z*w;
    }
    float nv0 = vx*0.17677670f + g_scv[n*96+3*lane];
    float nv1 = vy*0.17677670f + g_scv[n*96+3*lane+1];
    float nv2 = vz*0.17677670f + g_scv[n*96+3*lane+2];
    g_nv[n*96+3*lane]=nv0; g_nv[n*96+3*lane+1]=nv1; g_nv[n*96+3*lane+2]=nv2;
    float m = ns0+ns1;
    float q = ns0*ns0+ns1*ns1;
    float pw = nv0*nv0+nv1*nv1+nv2*nv2;
    #pragma unroll
    for (int off=16;off>0;off>>=1){
      m += __shfl_down_sync(0xffffffffu, m, off);
      q += __shfl_down_sync(0xffffffffu, q, off);
      pw += __shfl_down_sync(0xffffffffu, pw, off);
    }
    if (lane==0){
      int g = batch[n];
      atomicAdd(&g_gstat[g],        m*(1.f/64.f));
      atomicAdd(&g_gstat[NG_+g],    q*(1.f/64.f));
      atomicAdd(&g_gstat[2*NG_+g],  pw*(1.f/96.f));
      atomicAdd(&g_gstat[3*NG_+g],  1.f);
    }
    __syncwarp();
  }
}

__global__ void k_groups(){
  int t = threadIdx.x;
  if (t < NG_){
    float c  = fmaxf(g_gstat[3*NG_+t], 1.f);
    float mu = g_gstat[t]/c;
    float vs = g_gstat[NG_+t]/c - mu*mu;
    float vv = g_gstat[2*NG_+t]/c;
    g_gout[t]       = mu;
    g_gout[NG_+t]   = rsqrtf(vs+1e-5f);
    g_gout[2*NG_+t] = rsqrtf(vv+1e-5f);
  }
}

__global__ void k_out(const float* __restrict__ nf, const int* __restrict__ batch,
   const float* __restrict__ lnws, const float* __restrict__ lnbs,
   const float* __restrict__ lnwv, float* __restrict__ out){
  int i = blockIdx.x*blockDim.x+threadIdx.x;
  if (i >= NN*160) return;
  int n = i/160, c = i - n*160;
  int g = batch[n];
  float base = nf[i];
  float o;
  if (c < 64){
    float x = (g_ns[n*64+c] - g_gout[g]) * g_gout[NG_+g];
    o = base + x*lnws[c] + lnbs[c];
  } else {
    int cc = c-64;
    o = base + g_nv[n*96+cc]*g_gout[2*NG_+g]*lnwv[cc/3];
  }
  out[i]=o;
}

extern "C" void kernel_launch(void* const* d_in, const int* in_sizes, int n_in,
                              void* d_out, int out_size){
  const float* nf   =(const float*)d_in[0];
  const float* oh   =(const float*)d_in[1];
  const float* esh  =(const float*)d_in[2];
  const float* efea =(const float*)d_in[3];
  const float* ele  =(const float*)d_in[4];
  const int*   eidx =(const int*)d_in[5];
  const int*   batch=(const int*)d_in[6];
  const float* lpWs =(const float*)d_in[7];
  const float* lpbs =(const float*)d_in[8];
  const float* lpWv =(const float*)d_in[9];
  const float* ppWs =(const float*)d_in[10];
  const float* ppbs =(const float*)d_in[11];
  const float* ppWv =(const float*)d_in[12];
  const float* scWs =(const float*)d_in[13];
  const float* scWv =(const float*)d_in[14];
  const float* Wss0 =(const float*)d_in[15];
  const float* Wvv0 =(const float*)d_in[16];
  const float* Wssg =(const float*)d_in[17];
  const float* Wvvg =(const float*)d_in[18];
  const float* Wsv1 =(const float*)d_in[19];
  const float* Wvs1 =(const float*)d_in[20];
  const float* fcW1 =(const float*)d_in[21];
  const float* fcb1 =(const float*)d_in[22];
  const float* fcW2 =(const float*)d_in[23];
  const float* fcb2 =(const float*)d_in[24];
  const float* fcW3 =(const float*)d_in[25];
  const float* fcb3 =(const float*)d_in[26];
  const float* lnws =(const float*)d_in[27];
  const float* lnbs =(const float*)d_in[28];
  const float* lnwv =(const float*)d_in[29];
  float* out = (float*)d_out;

  const int SM_PRE  = (25664 + 16*192)*4;
  const int SM_PSTV = (24576 + 16*1024)*4;
  const int SM_E12  = (14336 + 16*2720)*4;
  const int SM_POST = (5184  + 16*192)*4;
  cudaFuncSetAttribute(k_node_pre,  cudaFuncAttributeMaxDynamicSharedMemorySize, SM_PRE);
  cudaFuncSetAttribute(k_pstv,      cudaFuncAttributeMaxDynamicSharedMemorySize, SM_PSTV);
  cudaFuncSetAttribute(k_mlp_hmma,  cudaFuncAttributeMaxDynamicSharedMemorySize, MBTOT);
  cudaFuncSetAttribute(k_e12,       cudaFuncAttributeMaxDynamicSharedMemorySize, SM_E12);
  cudaFuncSetAttribute(k_node_post, cudaFuncAttributeMaxDynamicSharedMemorySize, SM_POST);

  k_zero<<<(NN*192 + 4*NG_ + 255)/256, 256>>>();
  k_node_pre<<<148, 512, SM_PRE>>>(nf, oh, lpWs, lpbs, lpWv, scWs, scWv);
  k_pstv<<<148, 512, SM_PSTV>>>(Wss0, Wssg, Wsv1, Wvv0, Wvvg, Wvs1);
  k_mlp_hmma<<<148, 512, MBTOT>>>(ele, fcW1, fcb1, fcW2, fcb2, fcW3, fcb3);
  k_e12<<<148, 512, SM_E12>>>(eidx, esh, efea, Wss0, Wssg, Wsv1, Wvv0, Wvvg, Wvs1);
  k_node_post<<<148, 512, SM_POST>>>(batch, ppWs, ppbs, ppWv);
  k_groups<<<1, 32>>>();
  k_out<<<(NN*160 + 255)/256, 256>>>(nf, batch, lnws, lnbs, lnwv, out);
}

// round 14
// speedup vs baseline: 1.3660x; 1.1363x over previous
#include <cuda_runtime.h>
#include <cuda_bf16.h>
#include <cstdint>

#define NN 10000
#define EE 320000
#define NG_ 16

__device__ float  g_s[NN*64];
__device__ float4 g_v4[NN*32];
__device__ float  g_scs[NN*64];
__device__ float  g_scv[NN*96];
__device__ float  g_accs[NN*64];
__device__ float4 g_accv4[NN*32];
__device__ float  g_ns[NN*64];
__device__ float  g_nv[NN*96];
__device__ float  g_wmlp[(long long)EE*96];
__device__ float  g_e1[(long long)EE*128];
__device__ float  g_P[NN*128];
__device__ float  g_Q[NN*128];
__device__ float  g_T[NN*384];
__device__ float  g_U[NN*384];
__device__ float  g_gstat[4*NG_];
__device__ float  g_gout[3*NG_];

__device__ __forceinline__ float sig_(float x){ return 1.f/(1.f+__expf(-x)); }
__device__ __forceinline__ unsigned long long pk2(float x){
  unsigned long long r; asm("mov.b64 %0, {%1, %1};" : "=l"(r) : "f"(x)); return r; }
__device__ __forceinline__ unsigned long long pkab(float a, float b){
  unsigned long long r; asm("mov.b64 %0, {%1, %2};" : "=l"(r) : "f"(a), "f"(b)); return r; }
__device__ __forceinline__ void up2(unsigned long long v, float &a, float &b){
  asm("mov.b64 {%0, %1}, %2;" : "=f"(a), "=f"(b) : "l"(v)); }
__device__ __forceinline__ void fma2(unsigned long long &d, unsigned long long a, unsigned long long b){
  asm("fma.rn.f32x2 %0, %1, %2, %3;" : "=l"(d) : "l"(a), "l"(b), "l"(d)); }
__device__ __forceinline__ unsigned int s2u_(const void* p){
  unsigned int a; asm("{ .reg .u64 t; cvta.to.shared.u64 t, %1; cvt.u32.u64 %0, t; }" : "=r"(a) : "l"(p)); return a; }

__device__ __forceinline__ void ldsm4(unsigned &r0,unsigned &r1,unsigned &r2,unsigned &r3, unsigned a){
  asm volatile("ldmatrix.sync.aligned.m8n8.x4.shared.b16 {%0,%1,%2,%3}, [%4];"
    : "=r"(r0),"=r"(r1),"=r"(r2),"=r"(r3) : "r"(a)); }
__device__ __forceinline__ void mma16816(float* c, const unsigned* a, const unsigned* b){
  asm volatile("mma.sync.aligned.m16n8k16.row.col.f32.bf16.bf16.f32 "
    "{%0,%1,%2,%3}, {%4,%5,%6,%7}, {%8,%9}, {%0,%1,%2,%3};"
    : "+f"(c[0]),"+f"(c[1]),"+f"(c[2]),"+f"(c[3])
    : "r"(a[0]),"r"(a[1]),"r"(a[2]),"r"(a[3]), "r"(b[0]),"r"(b[1])); }
__device__ __forceinline__ void split2(float a, float b, unsigned &h, unsigned &l){
  __nv_bfloat16 ha=__float2bfloat16(a), hb=__float2bfloat16(b);
  float la=a-__bfloat162float(ha), lb=b-__bfloat162float(hb);
  __nv_bfloat162 hh=__halves2bfloat162(ha,hb);
  __nv_bfloat162 ll=__halves2bfloat162(__float2bfloat16(la),__float2bfloat16(lb));
  h=*(unsigned*)&hh; l=*(unsigned*)&ll; }

__global__ void k_zero(){
  int i = blockIdx.x*blockDim.x + threadIdx.x;
  if (i < NN*64) g_accs[i] = 0.f;
  int j = i - NN*64;
  if (j >= 0 && j < NN*128) ((float*)g_accv4)[j] = 0.f;
  int k = i - NN*192;
  if (k >= 0 && k < 4*NG_) g_gstat[k] = 0.f;
}

__global__ void __launch_bounds__(512) k_node_pre(const float* __restrict__ nf,
   const float* __restrict__ oh, const float* __restrict__ lpWs, const float* __restrict__ lpbs,
   const float* __restrict__ lpWv, const float* __restrict__ scWs, const float* __restrict__ scWv){
  extern __shared__ float sm[];
  float2* WsS  = (float2*)sm;
  float*  WvS  = sm + 4096;
  float2* sWsS = (float2*)(sm + 5120);
  float*  sWvS = sm + 21504;
  float*  bsS  = sm + 25600;
  float*  stage= sm + 25664;
  for (int i=threadIdx.x;i<4096;i+=blockDim.x) sm[i]=lpWs[i];
  for (int i=threadIdx.x;i<1024;i+=blockDim.x) WvS[i]=lpWv[i];
  for (int i=threadIdx.x;i<16384;i+=blockDim.x) sm[5120+i]=scWs[i];
  for (int i=threadIdx.x;i<4096;i+=blockDim.x) sWvS[i]=scWv[i];
  for (int i=threadIdx.x;i<64;i+=blockDim.x) bsS[i]=lpbs[i];
  __syncthreads();
  int warp = threadIdx.x>>5, lane = threadIdx.x&31, wpb = blockDim.x>>5;
  float*  sS  = stage + warp*192;
  float4* vS  = (float4*)(sS + 64);
  for (int n = blockIdx.x*wpb + warp; n < NN; n += gridDim.x*wpb){
    const float* row = nf + n*160;
    sS[lane] = row[lane]; sS[32+lane] = row[32+lane];
    vS[lane] = make_float4(row[64+3*lane], row[65+3*lane], row[66+3*lane], 0.f);
    const float* o4 = oh + n*4;
    int sp = (o4[1]>0.5f)?1:((o4[2]>0.5f)?2:((o4[3]>0.5f)?3:0));
    __syncwarp();
    float a0=0.f,a1=0.f,c0=0.f,c1=0.f;
    #pragma unroll 4
    for (int u=0;u<64;u++){
      float x = sS[u];
      float2 w  = WsS[u*32+lane];
      float2 w2 = sWsS[(u*4+sp)*32+lane];
      a0+=x*w.x; a1+=x*w.y; c0+=x*w2.x; c1+=x*w2.y;
    }
    g_s[n*64+2*lane]   = a0*0.125f + bsS[2*lane];
    g_s[n*64+2*lane+1] = a1*0.125f + bsS[2*lane+1];
    g_scs[n*64+2*lane]   = c0*0.0625f;
    g_scs[n*64+2*lane+1] = c1*0.0625f;
    float vx=0.f,vy=0.f,vz=0.f,cx=0.f,cy=0.f,cz=0.f;
    #pragma unroll 4
    for (int u=0;u<32;u++){
      float4 x = vS[u];
      float w  = WvS[u*32+lane];
      float w2 = sWvS[(u*4+sp)*32+lane];
      vx+=x.x*w;  vy+=x.y*w;  vz+=x.z*w;
      cx+=x.x*w2; cy+=x.y*w2; cz+=x.z*w2;
    }
    g_v4[n*32+lane] = make_float4(vx*0.17677670f, vy*0.17677670f, vz*0.17677670f, 0.f);
    g_scv[n*96+3*lane]   = cx*0.08838835f;
    g_scv[n*96+3*lane+1] = cy*0.08838835f;
    g_scv[n*96+3*lane+2] = cz*0.08838835f;
    __syncwarp();
  }
}

__global__ void __launch_bounds__(512) k_pstv(const float* __restrict__ Wss0,
   const float* __restrict__ Wssg, const float* __restrict__ Wsv1,
   const float* __restrict__ Wvv0, const float* __restrict__ Wvvg, const float* __restrict__ Wvs1){
  extern __shared__ float sm[];
  float4* FA = (float4*)sm;
  float4* FB = (float4*)(sm+8192);
  float4* GA = (float4*)(sm+16384);
  float4* GB = (float4*)(sm+20480);
  float* stage = sm + 24576;
  for (int i=threadIdx.x;i<2048;i+=blockDim.x){
    int u=i>>5, l=i&31;
    FA[i]=make_float4(Wss0[u*64+2*l], Wss0[u*64+2*l+1], Wssg[u*32+l], Wsv1[u*32+l]);
    int u2=u+64;
    FB[i]=make_float4(Wss0[u2*64+2*l], Wss0[u2*64+2*l+1], Wssg[u2*32+l], Wsv1[u2*32+l]);
  }
  for (int i=threadIdx.x;i<1024;i+=blockDim.x){
    int u=i>>5, l=i&31;
    GA[i]=make_float4(Wvv0[u*64+2*l], Wvv0[u*64+2*l+1], Wvvg[u*32+l], Wvs1[u*32+l]);
    int u2=u+32;
    GB[i]=make_float4(Wvv0[u2*64+2*l], Wvv0[u2*64+2*l+1], Wvvg[u2*32+l], Wvs1[u2*32+l]);
  }
  __syncthreads();
  int warp=threadIdx.x>>5, lane=threadIdx.x&31, wpb=blockDim.x>>5;
  float* sd = stage + warp*1024;
  const int b1 = NN/8;
  for (int p = blockIdx.x*wpb+warp; p<b1; p+=gridDim.x*wpb){
    int n0 = p*8;
    #pragma unroll
    for (int k=0;k<8;k++){
      int n = n0+k;
      float x0 = g_s[n*64+lane];
      float x1 = g_s[n*64+32+lane];
      *(unsigned long long*)(sd + k*128 + 2*lane)      = pkab(x0,x0);
      *(unsigned long long*)(sd + k*128 + 64 + 2*lane) = pkab(x1,x1);
    }
    __syncwarp();
    unsigned long long pa[8], pg[8], qa[8], qg[8];
    #pragma unroll
    for (int k=0;k<8;k++){ pa[k]=0ull; pg[k]=0ull; qa[k]=0ull; qg[k]=0ull; }
    #pragma unroll 2
    for (int u=0;u<64;u+=2){
      ulonglong2 wa0 = *(ulonglong2*)&FA[(u  )*32+lane];
      ulonglong2 wa1 = *(ulonglong2*)&FA[(u+1)*32+lane];
      ulonglong2 wb0 = *(ulonglong2*)&FB[(u  )*32+lane];
      ulonglong2 wb1 = *(ulonglong2*)&FB[(u+1)*32+lane];
      #pragma unroll
      for (int k=0;k<8;k++){
        ulonglong2 xp = *(ulonglong2*)(sd + k*128 + 2*u);
        fma2(pa[k], xp.x, wa0.x); fma2(pg[k], xp.x, wa0.y);
        fma2(qa[k], xp.x, wb0.x); fma2(qg[k], xp.x, wb0.y);
        fma2(pa[k], xp.y, wa1.x); fma2(pg[k], xp.y, wa1.y);
        fma2(qa[k], xp.y, wb1.x); fma2(qg[k], xp.y, wb1.y);
      }
    }
    #pragma unroll
    for (int k=0;k<8;k++){
      int n = n0+k;
      float a0,a1,ag,at;
      up2(pa[k],a0,a1); up2(pg[k],ag,at);
      *(float4*)(g_P + n*128 + lane*4) = make_float4(a0,a1,ag,at);
      up2(qa[k],a0,a1); up2(qg[k],ag,at);
      *(float4*)(g_Q + n*128 + lane*4) = make_float4(a0,a1,ag,at);
    }
    __syncwarp();
  }
  float4* vst = (float4*)sd;
  const int b2 = NN/4;
  for (int p = blockIdx.x*wpb+warp; p<b2; p+=gridDim.x*wpb){
    int n0 = p*4;
    #pragma unroll
    for (int k=0;k<4;k++) vst[k*32+lane] = g_v4[(n0+k)*32+lane];
    __syncwarp();
    unsigned long long t01[4][3], tgr[4][3], u01[4][3], ugr[4][3];
    #pragma unroll
    for (int k=0;k<4;k++)
      #pragma unroll
      for (int c=0;c<3;c++){ t01[k][c]=0ull; tgr[k][c]=0ull; u01[k][c]=0ull; ugr[k][c]=0ull; }
    #pragma unroll 2
    for (int u=0;u<32;u++){
      ulonglong2 ga = *(ulonglong2*)&GA[u*32+lane];
      ulonglong2 gb = *(ulonglong2*)&GB[u*32+lane];
      #pragma unroll
      for (int k=0;k<4;k++){
        float4 v = vst[k*32+u];
        unsigned long long vx=pk2(v.x), vy=pk2(v.y), vz=pk2(v.z);
        fma2(t01[k][0], vx, ga.x); fma2(t01[k][1], vy, ga.x); fma2(t01[k][2], vz, ga.x);
        fma2(tgr[k][0], vx, ga.y); fma2(tgr[k][1], vy, ga.y); fma2(tgr[k][2], vz, ga.y);
        fma2(u01[k][0], vx, gb.x); fma2(u01[k][1], vy, gb.x); fma2(u01[k][2], vz, gb.x);
        fma2(ugr[k][0], vx, gb.y); fma2(ugr[k][1], vy, gb.y); fma2(ugr[k][2], vz, gb.y);
      }
    }
    #pragma unroll
    for (int k=0;k<4;k++){
      int n = n0+k;
      float b0x,b1x,b0y,b1y,b0z,b1z,bgx,rx,bgy,ry,bgz,rz;
      up2(t01[k][0],b0x,b1x); up2(t01[k][1],b0y,b1y); up2(t01[k][2],b0z,b1z);
      up2(tgr[k][0],bgx,rx);  up2(tgr[k][1],bgy,ry);  up2(tgr[k][2],bgz,rz);
      float* o = g_T + n*384 + lane*12;
      *(float4*)(o  ) = make_float4(b0x,b0y,b0z,b1x);
      *(float4*)(o+4) = make_float4(b1y,b1z,bgx,bgy);
      *(float4*)(o+8) = make_float4(bgz,rx,ry,rz);
      up2(u01[k][0],b0x,b1x); up2(u01[k][1],b0y,b1y); up2(u01[k][2],b0z,b1z);
      up2(ugr[k][0],bgx,rx);  up2(ugr[k][1],bgy,ry);  up2(ugr[k][2],bgz,rz);
      o = g_U + n*384 + lane*12;
      *(float4*)(o  ) = make_float4(b0x,b0y,b0z,b1x);
      *(float4*)(o+4) = make_float4(b1y,b1z,bgx,bgy);
      *(float4*)(o+8) = make_float4(bgz,rx,ry,rz);
    }
    __syncwarp();
  }
}

// ---------------- HMMA MLP (unchanged from R13) ----------------
#define LD1 136
#define LD2 72
#define LDO 98
#define W1Hb 139264
#define W1Lb 156672
#define W2Hb 174080
#define W2Lb 183296
#define W3Hb 192512
#define W3Lb 206336
#define B1b  220160
#define B2b  220416
#define B3b  220672
#define MBTOT 221056

__global__ void __launch_bounds__(512) k_mlp_hmma(const float* __restrict__ ele,
   const float* __restrict__ W1, const float* __restrict__ b1,
   const float* __restrict__ W2, const float* __restrict__ b2,
   const float* __restrict__ W3, const float* __restrict__ b3){
  extern __shared__ char smc[];
  unsigned int sb = s2u_(smc);
  int tid=threadIdx.x, wid=tid>>5, lane=tid&31;
  for (int i=tid;i<64*128;i+=512){
    int n=i>>7,k=i&127; float w=W1[k*64+n];
    __nv_bfloat16 h=__float2bfloat16(w);
    *(__nv_bfloat16*)(smc+W1Hb+(n*LD1+k)*2)=h;
    *(__nv_bfloat16*)(smc+W1Lb+(n*LD1+k)*2)=__float2bfloat16(w-__bfloat162float(h));
  }
  for (int i=tid;i<64*64;i+=512){
    int n=i>>6,k=i&63; float w=W2[k*64+n];
    __nv_bfloat16 h=__float2bfloat16(w);
    *(__nv_bfloat16*)(smc+W2Hb+(n*LD2+k)*2)=h;
    *(__nv_bfloat16*)(smc+W2Lb+(n*LD2+k)*2)=__float2bfloat16(w-__bfloat162float(h));
  }
  for (int i=tid;i<96*64;i+=512){
    int n=i>>6,k=i&63; float w=W3[k*96+n];
    __nv_bfloat16 h=__float2bfloat16(w);
    *(__nv_bfloat16*)(smc+W3Hb+(n*LD2+k)*2)=h;
    *(__nv_bfloat16*)(smc+W3Lb+(n*LD2+k)*2)=__float2bfloat16(w-__bfloat162float(h));
  }
  float* b1S=(float*)(smc+B1b); float* b2S=(float*)(smc+B2b); float* b3S=(float*)(smc+B3b);
  if (tid<64){ b1S[tid]=b1[tid]; b2S[tid]=b2[tid]; }
  if (tid<96) b3S[tid]=b3[tid];
  __syncthreads();

  int tt  = wid>>3;
  int w8  = wid&7;
  int r0  = w8*16;
  int arow = r0 + (lane&15);
  int koff = (lane>>4)<<3;
  int b4r  = (lane&7) + ((lane>>4)<<3);
  int b4k  = ((lane>>3)&1)<<3;
  int er = r0+(lane>>2), ec2=(lane&3)*2;
  unsigned xb  = sb + (unsigned)tt*34816u;
  unsigned xlb = sb + 69632u + (unsigned)tt*34816u;
  unsigned hb  = sb + (unsigned)tt*18432u;
  unsigned hlb = sb + 36864u + (unsigned)tt*18432u;
  char* hbc  = smc + tt*18432;
  char* hlbc = smc + 36864 + tt*18432;

  for (int tp=blockIdx.x; tp<EE/256; tp+=gridDim.x){
    #pragma unroll
    for (int st=0;st<2;st++){
      const float4* xp=(const float4*)(ele+(long long)(2*tp+st)*16384);
      for (int i=tid;i<4096;i+=512){
        float4 v=xp[i];
        int r=(i*4)>>7, c=(i*4)&127;
        unsigned h0,l0,h1,l1;
        split2(v.x,v.y,h0,l0); split2(v.z,v.w,h1,l1);
        unsigned off=(unsigned)(r*LD1+c)*2u;
        *(uint2*)(smc+st*34816+off)=make_uint2(h0,h1);
        *(uint2*)(smc+69632+st*34816+off)=make_uint2(l0,l1);
      }
    }
    __syncthreads();

    float acc[8][4];
    #pragma unroll
    for(int nt=0;nt<8;nt++){acc[nt][0]=0.f;acc[nt][1]=0.f;acc[nt][2]=0.f;acc[nt][3]=0.f;}
    #pragma unroll
    for(int kk=0;kk<8;kk++){
      unsigned ah[4], al[4];
      ldsm4(ah[0],ah[1],ah[2],ah[3], xb +(unsigned)(arow*LD1+kk*16+koff)*2u);
      ldsm4(al[0],al[1],al[2],al[3], xlb+(unsigned)(arow*LD1+kk*16+koff)*2u);
      #pragma unroll
      for(int p=0;p<4;p++){
        unsigned bh[4],bl[4];
        ldsm4(bh[0],bh[1],bh[2],bh[3], sb+W1Hb+(unsigned)((p*16+b4r)*LD1+kk*16+b4k)*2u);
        ldsm4(bl[0],bl[1],bl[2],bl[3], sb+W1Lb+(unsigned)((p*16+b4r)*LD1+kk*16+b4k)*2u);
        mma16816(acc[2*p],   ah, bh);
        mma16816(acc[2*p],   ah, bl);
        mma16816(acc[2*p],   al, bh);
        mma16816(acc[2*p+1], ah, bh+2);
        mma16816(acc[2*p+1], ah, bl+2);
        mma16816(acc[2*p+1], al, bh+2);
      }
    }
    __syncthreads();
    #pragma unroll
    for(int nt=0;nt<8;nt++){
      int c=nt*8+ec2;
      float f0=acc[nt][0]+b1S[c], f1=acc[nt][1]+b1S[c+1];
      float f2=acc[nt][2]+b1S[c], f3=acc[nt][3]+b1S[c+1];
      f0*=sig_(f0); f1*=sig_(f1); f2*=sig_(f2); f3*=sig_(f3);
      unsigned h,l;
      split2(f0,f1,h,l);
      *(unsigned*)(hbc +(er*LD2+c)*2)=h;
      *(unsigned*)(hlbc+(er*LD2+c)*2)=l;
      split2(f2,f3,h,l);
      *(unsigned*)(hbc +((er+8)*LD2+c)*2)=h;
      *(unsigned*)(hlbc+((er+8)*LD2+c)*2)=l;
    }
    __syncwarp();

    #pragma unroll
    for(int nt=0;nt<8;nt++){acc[nt][0]=0.f;acc[nt][1]=0.f;acc[nt][2]=0.f;acc[nt][3]=0.f;}
    #pragma unroll
    for(int kk=0;kk<4;kk++){
      unsigned ah[4], al[4];
      ldsm4(ah[0],ah[1],ah[2],ah[3], hb +(unsigned)(arow*LD2+kk*16+koff)*2u);
      ldsm4(al[0],al[1],al[2],al[3], hlb+(unsigned)(arow*LD2+kk*16+koff)*2u);
      #pragma unroll
      for(int p=0;p<4;p++){
        unsigned bh[4],bl[4];
        ldsm4(bh[0],bh[1],bh[2],bh[3], sb+W2Hb+(unsigned)((p*16+b4r)*LD2+kk*16+b4k)*2u);
        ldsm4(bl[0],bl[1],bl[2],bl[3], sb+W2Lb+(unsigned)((p*16+b4r)*LD2+kk*16+b4k)*2u);
        mma16816(acc[2*p],   ah, bh);
        mma16816(acc[2*p],   ah, bl);
        mma16816(acc[2*p],   al, bh);
        mma16816(acc[2*p+1], ah, bh+2);
        mma16816(acc[2*p+1], ah, bl+2);
        mma16816(acc[2*p+1], al, bh+2);
      }
    }
    #pragma unroll
    for(int nt=0;nt<8;nt++){
      int c=nt*8+ec2;
      float f0=acc[nt][0]+b2S[c], f1=acc[nt][1]+b2S[c+1];
      float f2=acc[nt][2]+b2S[c], f3=acc[nt][3]+b2S[c+1];
      f0*=sig_(f0); f1*=sig_(f1); f2*=sig_(f2); f3*=sig_(f3);
      unsigned h,l;
      split2(f0,f1,h,l);
      *(unsigned*)(hbc +(er*LD2+c)*2)=h;
      *(unsigned*)(hlbc+(er*LD2+c)*2)=l;
      split2(f2,f3,h,l);
      *(unsigned*)(hbc +((er+8)*LD2+c)*2)=h;
      *(unsigned*)(hlbc+((er+8)*LD2+c)*2)=l;
    }
    __syncwarp();

    float a3[12][4];
    #pragma unroll
    for(int nt=0;nt<12;nt++){a3[nt][0]=0.f;a3[nt][1]=0.f;a3[nt][2]=0.f;a3[nt][3]=0.f;}
    #pragma unroll
    for(int kk=0;kk<4;kk++){
      unsigned ah[4], al[4];
      ldsm4(ah[0],ah[1],ah[2],ah[3], hb +(unsigned)(arow*LD2+kk*16+koff)*2u);
      ldsm4(al[0],al[1],al[2],al[3], hlb+(unsigned)(arow*LD2+kk*16+koff)*2u);
      #pragma unroll
      for(int p=0;p<6;p++){
        unsigned bh[4],bl[4];
        ldsm4(bh[0],bh[1],bh[2],bh[3], sb+W3Hb+(unsigned)((p*16+b4r)*LD2+kk*16+b4k)*2u);
        ldsm4(bl[0],bl[1],bl[2],bl[3], sb+W3Lb+(unsigned)((p*16+b4r)*LD2+kk*16+b4k)*2u);
        mma16816(a3[2*p],   ah, bh);
        mma16816(a3[2*p],   ah, bl);
        mma16816(a3[2*p],   al, bh);
        mma16816(a3[2*p+1], ah, bh+2);
        mma16816(a3[2*p+1], ah, bl+2);
        mma16816(a3[2*p+1], al, bh+2);
      }
    }
    __syncthreads();
    {
      float* outS=(float*)(smc+tt*50176);
      #pragma unroll
      for(int nt=0;nt<12;nt++){
        int c=nt*8+ec2;
        *(float2*)(outS+er*LDO+c)     = make_float2(a3[nt][0]+b3S[c], a3[nt][1]+b3S[c+1]);
        *(float2*)(outS+(er+8)*LDO+c) = make_float2(a3[nt][2]+b3S[c], a3[nt][3]+b3S[c+1]);
      }
    }
    __syncthreads();
    #pragma unroll
    for(int st=0;st<2;st++){
      const float* outS=(const float*)(smc+st*50176);
      long long base=(long long)(2*tp+st)*12288;
      for(int i=tid;i<12288;i+=512){
        int r=i/96, c=i-r*96;
        g_wmlp[base+i]=outS[r*LDO+c];
      }
    }
    __syncthreads();
  }
}

// ---------------- HMMA es-GEMV: g_e1 = es @ F1[128:192] (K=64, N=128) ----------------
#define ESXH 0
#define ESXL 18432
#define ESWH 36864
#define ESWL 55296
#define ESTOT 73728

__global__ void __launch_bounds__(256,2) k_es(const float* __restrict__ efea,
   const float* __restrict__ Wss0, const float* __restrict__ Wssg, const float* __restrict__ Wsv1){
  extern __shared__ char smc[];
  unsigned int sb = s2u_(smc);
  int tid=threadIdx.x, wid=tid>>5, lane=tid&31;
  // stage packed weight: col n=4l+j -> {Wss0[.][2l],Wss0[.][2l+1],Wssg[.][l],Wsv1[.][l]}, rows k=0..63 (F1 rows 128+k)
  for (int i=tid;i<128*64;i+=256){
    int n=i>>6, k=i&63, l=n>>2, j=n&3;
    float w = (j==0)? Wss0[(k+128)*64+2*l] : (j==1)? Wss0[(k+128)*64+2*l+1]
            : (j==2)? Wssg[(k+128)*32+l]   : Wsv1[(k+128)*32+l];
    __nv_bfloat16 h=__float2bfloat16(w);
    *(__nv_bfloat16*)(smc+ESWH+(n*LD2+k)*2)=h;
    *(__nv_bfloat16*)(smc+ESWL+(n*LD2+k)*2)=__float2bfloat16(w-__bfloat162float(h));
  }
  __syncthreads();

  int r0  = wid*16;
  int arow = r0 + (lane&15);
  int koff = (lane>>4)<<3;
  int b4r  = (lane&7) + ((lane>>4)<<3);
  int b4k  = ((lane>>3)&1)<<3;
  int er = r0+(lane>>2), ec2=(lane&3)*2;

  for (int t=blockIdx.x; t<EE/128; t+=gridDim.x){
    for (int i=tid;i<128*32;i+=256){
      int r=i>>5, c2=i&31;
      float2 v = *(const float2*)(efea + (long long)(t*128+r)*160 + c2*2);
      unsigned h,l; split2(v.x,v.y,h,l);
      unsigned off=(unsigned)(r*LD2+c2*2)*2u;
      *(unsigned*)(smc+ESXH+off)=h;
      *(unsigned*)(smc+ESXL+off)=l;
    }
    __syncthreads();

    float acc[16][4];
    #pragma unroll
    for(int nt=0;nt<16;nt++){acc[nt][0]=0.f;acc[nt][1]=0.f;acc[nt][2]=0.f;acc[nt][3]=0.f;}
    #pragma unroll
    for(int kk=0;kk<4;kk++){
      unsigned ah[4], al[4];
      ldsm4(ah[0],ah[1],ah[2],ah[3], sb+ESXH+(unsigned)(arow*LD2+kk*16+koff)*2u);
      ldsm4(al[0],al[1],al[2],al[3], sb+ESXL+(unsigned)(arow*LD2+kk*16+koff)*2u);
      #pragma unroll
      for(int p=0;p<8;p++){
        unsigned bh[4],bl[4];
        ldsm4(bh[0],bh[1],bh[2],bh[3], sb+ESWH+(unsigned)((p*16+b4r)*LD2+kk*16+b4k)*2u);
        ldsm4(bl[0],bl[1],bl[2],bl[3], sb+ESWL+(unsigned)((p*16+b4r)*LD2+kk*16+b4k)*2u);
        mma16816(acc[2*p],   ah, bh);
        mma16816(acc[2*p],   ah, bl);
        mma16816(acc[2*p],   al, bh);
        mma16816(acc[2*p+1], ah, bh+2);
        mma16816(acc[2*p+1], ah, bl+2);
        mma16816(acc[2*p+1], al, bh+2);
      }
    }
    #pragma unroll
    for(int nt=0;nt<16;nt++){
      int c=nt*8+ec2;
      *(float2*)(g_e1 + (long long)(t*128+er)*128 + c)   = make_float2(acc[nt][0], acc[nt][1]);
      *(float2*)(g_e1 + (long long)(t*128+er+8)*128 + c) = make_float2(acc[nt][2], acc[nt][3]);
    }
    __syncthreads();
  }
}

// ---------------- e12: ev-GEMV + epilogue + scatter (F1 via g_e1), 4 edges/warp ----------------
__global__ void __launch_bounds__(256,3) k_e12(const int* __restrict__ eidx,
   const float* __restrict__ esh, const float* __restrict__ efea,
   const float* __restrict__ Wvv0, const float* __restrict__ Wvvg, const float* __restrict__ Wvs1){
  extern __shared__ float sm[];
  ulonglong2* W2a = (ulonglong2*)sm;     // 4096 f
  float* stage = sm + 4096;              // per warp 1040 f
  for (int i=threadIdx.x;i<1024;i+=blockDim.x){
    int u=(i>>5)+64, l=i&31;
    float w0=Wvv0[u*64+2*l], w1=Wvv0[u*64+2*l+1];
    float wz=Wvvg[u*32+l],   ww=Wvs1[u*32+l];
    W2a[i] = make_ulonglong2(pkab(w0,w1), pkab(wz,ww));
  }
  __syncthreads();
  int warp=threadIdx.x>>5, lane=threadIdx.x&31, wpb=blockDim.x>>5;
  float* vd  = stage + warp*1040;
  float* shS = vd + 1024;
  const float inv3 = 0.57735027f, invfan = 0.058925565f;
  const int batches = EE/4;
  for (int p = blockIdx.x*wpb+warp; p<batches; p+=gridDim.x*wpb){
    int e0 = p*4;
    int nid[4], njd[4];
    #pragma unroll
    for (int k=0;k<4;k++){
      int e = e0+k;
      nid[k]=eidx[e]; njd[k]=eidx[EE+e];
      float4 sh = *(const float4*)(esh + (long long)e*4);
      if (lane==0) *(float4*)(shS + k*4) = sh;
      const float* r = efea + (long long)e*160;
      float ex=r[64+3*lane], ey=r[65+3*lane], ez=r[66+3*lane];
      float dd=(ex*sh.y+ey*sh.z+ez*sh.w)*inv3;
      float* o = vd + k*256 + lane*8;
      *(float4*)o     = make_float4(dd,dd,ex,ey);
      *(float2*)(o+4) = make_float2(dd,ez);
    }
    __syncwarp();
    unsigned long long b01[4], r01[4], gz2[4];
    #pragma unroll
    for (int k=0;k<4;k++){ b01[k]=0ull; r01[k]=0ull; gz2[k]=0ull; }
    #pragma unroll 4
    for (int u=0;u<32;u++){
      ulonglong2 wa = W2a[u*32+lane];
      float wz,ww; up2(wa.y, wz, ww);
      unsigned long long wb = pk2(ww);
      #pragma unroll
      for (int k=0;k<4;k++){
        ulonglong2 t1 = *(ulonglong2*)(vd + k*256 + u*8);
        unsigned long long t2 = *(unsigned long long*)(vd + k*256 + u*8 + 4);
        fma2(b01[k], t1.x, wa.x);
        fma2(r01[k], t1.y, wb);
        fma2(gz2[k], t2,   wa.y);
      }
    }
    #pragma unroll
    for (int k=0;k<4;k++){
      long long e = e0+k;
      float b0,b1,r0,r1,bg,r2;
      up2(b01[k],b0,b1); up2(r01[k],r0,r1); up2(gz2[k],bg,r2);
      float4 f1v = *(const float4*)(g_e1 + e*128 + lane*4);
      float4 P = *(const float4*)(g_P + nid[k]*128 + lane*4);
      float4 Q = *(const float4*)(g_Q + njd[k]*128 + lane*4);
      float a0=f1v.x+P.x+Q.x, a1=f1v.y+P.y+Q.y, ag=f1v.z+P.z+Q.z, at=f1v.w+P.w+Q.w;
      float4 sh = *(float4*)(shS + k*4);
      const float* tp  = g_T + nid[k]*384 + lane*12;
      const float* upt = g_U + njd[k]*384 + lane*12;
      float4 t0=*(const float4*)tp,  t1=*(const float4*)(tp+4),  t2=*(const float4*)(tp+8);
      float4 u0=*(const float4*)upt, u1=*(const float4*)(upt+4), u2=*(const float4*)(upt+8);
      float s0x=t0.x+u0.x, s0y=t0.y+u0.y, s0z=t0.z+u0.z, s0w=t0.w+u0.w;
      float s1x=t1.x+u1.x, s1y=t1.y+u1.y, s1z=t1.z+u1.z, s1w=t1.w+u1.w;
      float s2x=t2.x+u2.x, s2y=t2.y+u2.y, s2z=t2.z+u2.z, s2w=t2.w+u2.w;
      b0 += inv3*(s0x*sh.y + s0y*sh.z + s0z*sh.w);
      b1 += inv3*(s0w*sh.y + s1x*sh.z + s1y*sh.w);
      bg += inv3*(s1z*sh.y + s1w*sh.z + s2x*sh.w);
      r0 += s2y; r1 += s2z; r2 += s2w;
      float zs0=(sh.x*a0+b0)*invfan, zs1=(sh.x*a1+b1)*invfan;
      float zg =(sh.x*ag+bg)*invfan;
      const float* wm = g_wmlp + e*96;
      float2 wm01 = *(const float2*)(wm+2*lane);
      float wmv = wm[64+lane];
      zs0 = zs0*sig_(zs0)*wm01.x;
      zs1 = zs1*sig_(zs1)*wm01.y;
      float gv = sig_(zg)*wmv*invfan;
      int n = nid[k];
      atomicAdd((float2*)(g_accs + n*64 + 2*lane), make_float2(zs0, zs1));
      atomicAdd(&g_accv4[n*32+lane],
                make_float4((at*sh.y + r0*sh.x)*gv, (at*sh.z + r1*sh.x)*gv,
                            (at*sh.w + r2*sh.x)*gv, 0.f));
    }
    __syncwarp();
  }
}

__global__ void __launch_bounds__(512) k_node_post(const int* __restrict__ batch,
   const float* __restrict__ ppWs, const float* __restrict__ ppbs, const float* __restrict__ ppWv){
  extern __shared__ float sm[];
  float2* WsS = (float2*)sm;
  float* WvS = sm+4096;
  float* bsS = sm+5120;
  float* stage = sm+5184;
  for (int i=threadIdx.x;i<4096;i+=blockDim.x) sm[i]=ppWs[i];
  for (int i=threadIdx.x;i<1024;i+=blockDim.x) WvS[i]=ppWv[i];
  for (int i=threadIdx.x;i<64;i+=blockDim.x) bsS[i]=ppbs[i];
  __syncthreads();
  int warp=threadIdx.x>>5, lane=threadIdx.x&31, wpb=blockDim.x>>5;
  float*  sS  = stage + warp*192;
  float4* vS  = (float4*)(sS+64);
  for (int n=blockIdx.x*wpb+warp; n<NN; n+=gridDim.x*wpb){
    sS[lane]=g_accs[n*64+lane]; sS[32+lane]=g_accs[n*64+32+lane];
    vS[lane]=g_accv4[n*32+lane];
    __syncwarp();
    float a0=0.f,a1=0.f;
    #pragma unroll 4
    for (int u=0;u<64;u++){
      float x=sS[u]; float2 w=WsS[u*32+lane];
      a0+=x*w.x; a1+=x*w.y;
    }
    float ns0 = a0*0.125f + bsS[2*lane]   + g_scs[n*64+2*lane];
    float ns1 = a1*0.125f + bsS[2*lane+1] + g_scs[n*64+2*lane+1];
    g_ns[n*64+2*lane]=ns0; g_ns[n*64+2*lane+1]=ns1;
    float vx=0.f,vy=0.f,vz=0.f;
    #pragma unroll 4
    for (int u=0;u<32;u++){
      float4 x=vS[u]; float w=WvS[u*32+lane];
      vx+=x.x*w; vy+=x.y*w; vz+=x.z*w;
    }
    float nv0 = vx*0.17677670f + g_scv[n*96+3*lane];
    float nv1 = vy*0.17677670f + g_scv[n*96+3*lane+1];
    float nv2 = vz*0.17677670f + g_scv[n*96+3*lane+2];
    g_nv[n*96+3*lane]=nv0; g_nv[n*96+3*lane+1]=nv1; g_nv[n*96+3*lane+2]=nv2;
    float m = ns0+ns1;
    float q = ns0*ns0+ns1*ns1;
    float pw = nv0*nv0+nv1*nv1+nv2*nv2;
    #pragma unroll
    for (int off=16;off>0;off>>=1){
      m += __shfl_down_sync(0xffffffffu, m, off);
      q += __shfl_down_sync(0xffffffffu, q, off);
      pw += __shfl_down_sync(0xffffffffu, pw, off);
    }
    if (lane==0){
      int g = batch[n];
      atomicAdd(&g_gstat[g],        m*(1.f/64.f));
      atomicAdd(&g_gstat[NG_+g],    q*(1.f/64.f));
      atomicAdd(&g_gstat[2*NG_+g],  pw*(1.f/96.f));
      atomicAdd(&g_gstat[3*NG_+g],  1.f);
    }
    __syncwarp();
  }
}

__global__ void k_groups(){
  int t = threadIdx.x;
  if (t < NG_){
    float c  = fmaxf(g_gstat[3*NG_+t], 1.f);
    float mu = g_gstat[t]/c;
    float vs = g_gstat[NG_+t]/c - mu*mu;
    float vv = g_gstat[2*NG_+t]/c;
    g_gout[t]       = mu;
    g_gout[NG_+t]   = rsqrtf(vs+1e-5f);
    g_gout[2*NG_+t] = rsqrtf(vv+1e-5f);
  }
}

__global__ void k_out(const float* __restrict__ nf, const int* __restrict__ batch,
   const float* __restrict__ lnws, const float* __restrict__ lnbs,
   const float* __restrict__ lnwv, float* __restrict__ out){
  int i = blockIdx.x*blockDim.x+threadIdx.x;
  if (i >= NN*160) return;
  int n = i/160, c = i - n*160;
  int g = batch[n];
  float base = nf[i];
  float o;
  if (c < 64){
    float x = (g_ns[n*64+c] - g_gout[g]) * g_gout[NG_+g];
    o = base + x*lnws[c] + lnbs[c];
  } else {
    int cc = c-64;
    o = base + g_nv[n*96+cc]*g_gout[2*NG_+g]*lnwv[cc/3];
  }
  out[i]=o;
}

extern "C" void kernel_launch(void* const* d_in, const int* in_sizes, int n_in,
                              void* d_out, int out_size){
  const float* nf   =(const float*)d_in[0];
  const float* oh   =(const float*)d_in[1];
  const float* esh  =(const float*)d_in[2];
  const float* efea =(const float*)d_in[3];
  const float* ele  =(const float*)d_in[4];
  const int*   eidx =(const int*)d_in[5];
  const int*   batch=(const int*)d_in[6];
  const float* lpWs =(const float*)d_in[7];
  const float* lpbs =(const float*)d_in[8];
  const float* lpWv =(const float*)d_in[9];
  const float* ppWs =(const float*)d_in[10];
  const float* ppbs =(const float*)d_in[11];
  const float* ppWv =(const float*)d_in[12];
  const float* scWs =(const float*)d_in[13];
  const float* scWv =(const float*)d_in[14];
  const float* Wss0 =(const float*)d_in[15];
  const float* Wvv0 =(const float*)d_in[16];
  const float* Wssg =(const float*)d_in[17];
  const float* Wvvg =(const float*)d_in[18];
  const float* Wsv1 =(const float*)d_in[19];
  const float* Wvs1 =(const float*)d_in[20];
  const float* fcW1 =(const float*)d_in[21];
  const float* fcb1 =(const float*)d_in[22];
  const float* fcW2 =(const float*)d_in[23];
  const float* fcb2 =(const float*)d_in[24];
  const float* fcW3 =(const float*)d_in[25];
  const float* fcb3 =(const float*)d_in[26];
  const float* lnws =(const float*)d_in[27];
  const float* lnbs =(const float*)d_in[28];
  const float* lnwv =(const float*)d_in[29];
  float* out = (float*)d_out;

  const int SM_PRE  = (25664 + 16*192)*4;
  const int SM_PSTV = (24576 + 16*1024)*4;
  const int SM_E12  = (4096  + 8*1040)*4;   // 49664
  const int SM_POST = (5184  + 16*192)*4;
  cudaFuncSetAttribute(k_node_pre,  cudaFuncAttributeMaxDynamicSharedMemorySize, SM_PRE);
  cudaFuncSetAttribute(k_pstv,      cudaFuncAttributeMaxDynamicSharedMemorySize, SM_PSTV);
  cudaFuncSetAttribute(k_mlp_hmma,  cudaFuncAttributeMaxDynamicSharedMemorySize, MBTOT);
  cudaFuncSetAttribute(k_es,        cudaFuncAttributeMaxDynamicSharedMemorySize, ESTOT);
  cudaFuncSetAttribute(k_e12,       cudaFuncAttributeMaxDynamicSharedMemorySize, SM_E12);
  cudaFuncSetAttribute(k_node_post, cudaFuncAttributeMaxDynamicSharedMemorySize, SM_POST);

  k_zero<<<(NN*192 + 4*NG_ + 255)/256, 256>>>();
  k_node_pre<<<148, 512, SM_PRE>>>(nf, oh, lpWs, lpbs, lpWv, scWs, scWv);
  k_pstv<<<148, 512, SM_PSTV>>>(Wss0, Wssg, Wsv1, Wvv0, Wvvg, Wvs1);
  k_mlp_hmma<<<148, 512, MBTOT>>>(ele, fcW1, fcb1, fcW2, fcb2, fcW3, fcb3);
  k_es<<<296, 256, ESTOT>>>(efea, Wss0, Wssg, Wsv1);
  k_e12<<<444, 256, SM_E12>>>(eidx, esh, efea, Wvv0, Wvvg, Wvs1);
  k_node_post<<<148, 512, SM_POST>>>(batch, ppWs, ppbs, ppWv);
  k_groups<<<1, 32>>>();
  k_out<<<(NN*160 + 255)/256, 256>>>(nf, batch, lnws, lnbs, lnwv, out);
}

// round 16
// speedup vs baseline: 1.3683x; 1.0017x over previous
#include <cuda_runtime.h>
#include <cuda_bf16.h>
#include <cstdint>

#define NN 10000
#define EE 320000
#define NG_ 16

__device__ float  g_s[NN*64];
__device__ float4 g_v4[NN*32];
__device__ float  g_scs[NN*64];
__device__ float  g_scv[NN*96];
__device__ float  g_accs[NN*64];
__device__ float4 g_accv4[NN*32];
__device__ float  g_ns[NN*64];
__device__ float  g_nv[NN*96];
__device__ float  g_wmlp[(long long)EE*96];
__device__ float  g_e1[(long long)EE*128];
__device__ float  g_P[NN*128];
__device__ float  g_Q[NN*128];
__device__ float  g_T[NN*384];
__device__ float  g_U[NN*384];
__device__ float  g_gstat[4*NG_];
__device__ float  g_gout[3*NG_];

__device__ __forceinline__ float sig_(float x){ return 1.f/(1.f+__expf(-x)); }
__device__ __forceinline__ unsigned long long pk2(float x){
  unsigned long long r; asm("mov.b64 %0, {%1, %1};" : "=l"(r) : "f"(x)); return r; }
__device__ __forceinline__ unsigned long long pkab(float a, float b){
  unsigned long long r; asm("mov.b64 %0, {%1, %2};" : "=l"(r) : "f"(a), "f"(b)); return r; }
__device__ __forceinline__ void up2(unsigned long long v, float &a, float &b){
  asm("mov.b64 {%0, %1}, %2;" : "=f"(a), "=f"(b) : "l"(v)); }
__device__ __forceinline__ void fma2(unsigned long long &d, unsigned long long a, unsigned long long b){
  asm("fma.rn.f32x2 %0, %1, %2, %3;" : "=l"(d) : "l"(a), "l"(b), "l"(d)); }
__device__ __forceinline__ unsigned int s2u_(const void* p){
  unsigned int a; asm("{ .reg .u64 t; cvta.to.shared.u64 t, %1; cvt.u32.u64 %0, t; }" : "=r"(a) : "l"(p)); return a; }

__device__ __forceinline__ void ldsm4(unsigned &r0,unsigned &r1,unsigned &r2,unsigned &r3, unsigned a){
  asm volatile("ldmatrix.sync.aligned.m8n8.x4.shared.b16 {%0,%1,%2,%3}, [%4];"
    : "=r"(r0),"=r"(r1),"=r"(r2),"=r"(r3) : "r"(a)); }
__device__ __forceinline__ void mma16816(float* c, const unsigned* a, const unsigned* b){
  asm volatile("mma.sync.aligned.m16n8k16.row.col.f32.bf16.bf16.f32 "
    "{%0,%1,%2,%3}, {%4,%5,%6,%7}, {%8,%9}, {%0,%1,%2,%3};"
    : "+f"(c[0]),"+f"(c[1]),"+f"(c[2]),"+f"(c[3])
    : "r"(a[0]),"r"(a[1]),"r"(a[2]),"r"(a[3]), "r"(b[0]),"r"(b[1])); }
__device__ __forceinline__ void split2(float a, float b, unsigned &h, unsigned &l){
  __nv_bfloat16 ha=__float2bfloat16(a), hb=__float2bfloat16(b);
  float la=a-__bfloat162float(ha), lb=b-__bfloat162float(hb);
  __nv_bfloat162 hh=__halves2bfloat162(ha,hb);
  __nv_bfloat162 ll=__halves2bfloat162(__float2bfloat16(la),__float2bfloat16(lb));
  h=*(unsigned*)&hh; l=*(unsigned*)&ll; }

__global__ void k_zero(){
  int i = blockIdx.x*blockDim.x + threadIdx.x;
  if (i < NN*64) g_accs[i] = 0.f;
  int j = i - NN*64;
  if (j >= 0 && j < NN*128) ((float*)g_accv4)[j] = 0.f;
  int k = i - NN*192;
  if (k >= 0 && k < 4*NG_) g_gstat[k] = 0.f;
}

__global__ void __launch_bounds__(512) k_node_pre(const float* __restrict__ nf,
   const float* __restrict__ oh, const float* __restrict__ lpWs, const float* __restrict__ lpbs,
   const float* __restrict__ lpWv, const float* __restrict__ scWs, const float* __restrict__ scWv){
  extern __shared__ float sm[];
  float2* WsS  = (float2*)sm;
  float*  WvS  = sm + 4096;
  float2* sWsS = (float2*)(sm + 5120);
  float*  sWvS = sm + 21504;
  float*  bsS  = sm + 25600;
  float*  stage= sm + 25664;
  for (int i=threadIdx.x;i<4096;i+=blockDim.x) sm[i]=lpWs[i];
  for (int i=threadIdx.x;i<1024;i+=blockDim.x) WvS[i]=lpWv[i];
  for (int i=threadIdx.x;i<16384;i+=blockDim.x) sm[5120+i]=scWs[i];
  for (int i=threadIdx.x;i<4096;i+=blockDim.x) sWvS[i]=scWv[i];
  for (int i=threadIdx.x;i<64;i+=blockDim.x) bsS[i]=lpbs[i];
  __syncthreads();
  int warp = threadIdx.x>>5, lane = threadIdx.x&31, wpb = blockDim.x>>5;
  float*  sS  = stage + warp*192;
  float4* vS  = (float4*)(sS + 64);
  for (int n = blockIdx.x*wpb + warp; n < NN; n += gridDim.x*wpb){
    const float* row = nf + n*160;
    sS[lane] = row[lane]; sS[32+lane] = row[32+lane];
    vS[lane] = make_float4(row[64+3*lane], row[65+3*lane], row[66+3*lane], 0.f);
    const float* o4 = oh + n*4;
    int sp = (o4[1]>0.5f)?1:((o4[2]>0.5f)?2:((o4[3]>0.5f)?3:0));
    __syncwarp();
    float a0=0.f,a1=0.f,c0=0.f,c1=0.f;
    #pragma unroll 4
    for (int u=0;u<64;u++){
      float x = sS[u];
      float2 w  = WsS[u*32+lane];
      float2 w2 = sWsS[(u*4+sp)*32+lane];
      a0+=x*w.x; a1+=x*w.y; c0+=x*w2.x; c1+=x*w2.y;
    }
    g_s[n*64+2*lane]   = a0*0.125f + bsS[2*lane];
    g_s[n*64+2*lane+1] = a1*0.125f + bsS[2*lane+1];
    g_scs[n*64+2*lane]   = c0*0.0625f;
    g_scs[n*64+2*lane+1] = c1*0.0625f;
    float vx=0.f,vy=0.f,vz=0.f,cx=0.f,cy=0.f,cz=0.f;
    #pragma unroll 4
    for (int u=0;u<32;u++){
      float4 x = vS[u];
      float w  = WvS[u*32+lane];
      float w2 = sWvS[(u*4+sp)*32+lane];
      vx+=x.x*w;  vy+=x.y*w;  vz+=x.z*w;
      cx+=x.x*w2; cy+=x.y*w2; cz+=x.z*w2;
    }
    g_v4[n*32+lane] = make_float4(vx*0.17677670f, vy*0.17677670f, vz*0.17677670f, 0.f);
    g_scv[n*96+3*lane]   = cx*0.08838835f;
    g_scv[n*96+3*lane+1] = cy*0.08838835f;
    g_scv[n*96+3*lane+2] = cz*0.08838835f;
    __syncwarp();
  }
}

__global__ void __launch_bounds__(512) k_pstv(const float* __restrict__ Wss0,
   const float* __restrict__ Wssg, const float* __restrict__ Wsv1,
   const float* __restrict__ Wvv0, const float* __restrict__ Wvvg, const float* __restrict__ Wvs1){
  extern __shared__ float sm[];
  float4* FA = (float4*)sm;
  float4* FB = (float4*)(sm+8192);
  float4* GA = (float4*)(sm+16384);
  float4* GB = (float4*)(sm+20480);
  float* stage = sm + 24576;
  for (int i=threadIdx.x;i<2048;i+=blockDim.x){
    int u=i>>5, l=i&31;
    FA[i]=make_float4(Wss0[u*64+2*l], Wss0[u*64+2*l+1], Wssg[u*32+l], Wsv1[u*32+l]);
    int u2=u+64;
    FB[i]=make_float4(Wss0[u2*64+2*l], Wss0[u2*64+2*l+1], Wssg[u2*32+l], Wsv1[u2*32+l]);
  }
  for (int i=threadIdx.x;i<1024;i+=blockDim.x){
    int u=i>>5, l=i&31;
    GA[i]=make_float4(Wvv0[u*64+2*l], Wvv0[u*64+2*l+1], Wvvg[u*32+l], Wvs1[u*32+l]);
    int u2=u+32;
    GB[i]=make_float4(Wvv0[u2*64+2*l], Wvv0[u2*64+2*l+1], Wvvg[u2*32+l], Wvs1[u2*32+l]);
  }
  __syncthreads();
  int warp=threadIdx.x>>5, lane=threadIdx.x&31, wpb=blockDim.x>>5;
  float* sd = stage + warp*1024;
  const int b1 = NN/8;
  for (int p = blockIdx.x*wpb+warp; p<b1; p+=gridDim.x*wpb){
    int n0 = p*8;
    #pragma unroll
    for (int k=0;k<8;k++){
      int n = n0+k;
      float x0 = g_s[n*64+lane];
      float x1 = g_s[n*64+32+lane];
      *(unsigned long long*)(sd + k*128 + 2*lane)      = pkab(x0,x0);
      *(unsigned long long*)(sd + k*128 + 64 + 2*lane) = pkab(x1,x1);
    }
    __syncwarp();
    unsigned long long pa[8], pg[8], qa[8], qg[8];
    #pragma unroll
    for (int k=0;k<8;k++){ pa[k]=0ull; pg[k]=0ull; qa[k]=0ull; qg[k]=0ull; }
    #pragma unroll 2
    for (int u=0;u<64;u+=2){
      ulonglong2 wa0 = *(ulonglong2*)&FA[(u  )*32+lane];
      ulonglong2 wa1 = *(ulonglong2*)&FA[(u+1)*32+lane];
      ulonglong2 wb0 = *(ulonglong2*)&FB[(u  )*32+lane];
      ulonglong2 wb1 = *(ulonglong2*)&FB[(u+1)*32+lane];
      #pragma unroll
      for (int k=0;k<8;k++){
        ulonglong2 xp = *(ulonglong2*)(sd + k*128 + 2*u);
        fma2(pa[k], xp.x, wa0.x); fma2(pg[k], xp.x, wa0.y);
        fma2(qa[k], xp.x, wb0.x); fma2(qg[k], xp.x, wb0.y);
        fma2(pa[k], xp.y, wa1.x); fma2(pg[k], xp.y, wa1.y);
        fma2(qa[k], xp.y, wb1.x); fma2(qg[k], xp.y, wb1.y);
      }
    }
    #pragma unroll
    for (int k=0;k<8;k++){
      int n = n0+k;
      float a0,a1,ag,at;
      up2(pa[k],a0,a1); up2(pg[k],ag,at);
      *(float4*)(g_P + n*128 + lane*4) = make_float4(a0,a1,ag,at);
      up2(qa[k],a0,a1); up2(qg[k],ag,at);
      *(float4*)(g_Q + n*128 + lane*4) = make_float4(a0,a1,ag,at);
    }
    __syncwarp();
  }
  float4* vst = (float4*)sd;
  const int b2 = NN/4;
  for (int p = blockIdx.x*wpb+warp; p<b2; p+=gridDim.x*wpb){
    int n0 = p*4;
    #pragma unroll
    for (int k=0;k<4;k++) vst[k*32+lane] = g_v4[(n0+k)*32+lane];
    __syncwarp();
    unsigned long long t01[4][3], tgr[4][3], u01[4][3], ugr[4][3];
    #pragma unroll
    for (int k=0;k<4;k++)
      #pragma unroll
      for (int c=0;c<3;c++){ t01[k][c]=0ull; tgr[k][c]=0ull; u01[k][c]=0ull; ugr[k][c]=0ull; }
    #pragma unroll 2
    for (int u=0;u<32;u++){
      ulonglong2 ga = *(ulonglong2*)&GA[u*32+lane];
      ulonglong2 gb = *(ulonglong2*)&GB[u*32+lane];
      #pragma unroll
      for (int k=0;k<4;k++){
        float4 v = vst[k*32+u];
        unsigned long long vx=pk2(v.x), vy=pk2(v.y), vz=pk2(v.z);
        fma2(t01[k][0], vx, ga.x); fma2(t01[k][1], vy, ga.x); fma2(t01[k][2], vz, ga.x);
        fma2(tgr[k][0], vx, ga.y); fma2(tgr[k][1], vy, ga.y); fma2(tgr[k][2], vz, ga.y);
        fma2(u01[k][0], vx, gb.x); fma2(u01[k][1], vy, gb.x); fma2(u01[k][2], vz, gb.x);
        fma2(ugr[k][0], vx, gb.y); fma2(ugr[k][1], vy, gb.y); fma2(ugr[k][2], vz, gb.y);
      }
    }
    #pragma unroll
    for (int k=0;k<4;k++){
      int n = n0+k;
      float b0x,b1x,b0y,b1y,b0z,b1z,bgx,rx,bgy,ry,bgz,rz;
      up2(t01[k][0],b0x,b1x); up2(t01[k][1],b0y,b1y); up2(t01[k][2],b0z,b1z);
      up2(tgr[k][0],bgx,rx);  up2(tgr[k][1],bgy,ry);  up2(tgr[k][2],bgz,rz);
      float* o = g_T + n*384 + lane*12;
      *(float4*)(o  ) = make_float4(b0x,b0y,b0z,b1x);
      *(float4*)(o+4) = make_float4(b1y,b1z,bgx,bgy);
      *(float4*)(o+8) = make_float4(bgz,rx,ry,rz);
      up2(u01[k][0],b0x,b1x); up2(u01[k][1],b0y,b1y); up2(u01[k][2],b0z,b1z);
      up2(ugr[k][0],bgx,rx);  up2(ugr[k][1],bgy,ry);  up2(ugr[k][2],bgz,rz);
      o = g_U + n*384 + lane*12;
      *(float4*)(o  ) = make_float4(b0x,b0y,b0z,b1x);
      *(float4*)(o+4) = make_float4(b1y,b1z,bgx,bgy);
      *(float4*)(o+8) = make_float4(bgz,rx,ry,rz);
    }
    __syncwarp();
  }
}

// ---------------- HMMA MLP: register-resident inter-layer flow ----------------
#define LD1 136
#define LD2 72
#define W1Hb 139264
#define W1Lb 156672
#define W2Hb 174080
#define W2Lb 183296
#define W3Hb 192512
#define W3Lb 206336
#define B1b  220160
#define B2b  220416
#define B3b  220672
#define MBTOT 221056

__global__ void __launch_bounds__(512) k_mlp_hmma(const float* __restrict__ ele,
   const float* __restrict__ W1, const float* __restrict__ b1,
   const float* __restrict__ W2, const float* __restrict__ b2,
   const float* __restrict__ W3, const float* __restrict__ b3){
  extern __shared__ char smc[];
  unsigned int sb = s2u_(smc);
  int tid=threadIdx.x, wid=tid>>5, lane=tid&31;
  for (int i=tid;i<64*128;i+=512){
    int n=i>>7,k=i&127; float w=W1[k*64+n];
    __nv_bfloat16 h=__float2bfloat16(w);
    *(__nv_bfloat16*)(smc+W1Hb+(n*LD1+k)*2)=h;
    *(__nv_bfloat16*)(smc+W1Lb+(n*LD1+k)*2)=__float2bfloat16(w-__bfloat162float(h));
  }
  for (int i=tid;i<64*64;i+=512){
    int n=i>>6,k=i&63; float w=W2[k*64+n];
    __nv_bfloat16 h=__float2bfloat16(w);
    *(__nv_bfloat16*)(smc+W2Hb+(n*LD2+k)*2)=h;
    *(__nv_bfloat16*)(smc+W2Lb+(n*LD2+k)*2)=__float2bfloat16(w-__bfloat162float(h));
  }
  for (int i=tid;i<96*64;i+=512){
    int n=i>>6,k=i&63; float w=W3[k*96+n];
    __nv_bfloat16 h=__float2bfloat16(w);
    *(__nv_bfloat16*)(smc+W3Hb+(n*LD2+k)*2)=h;
    *(__nv_bfloat16*)(smc+W3Lb+(n*LD2+k)*2)=__float2bfloat16(w-__bfloat162float(h));
  }
  float* b1S=(float*)(smc+B1b); float* b2S=(float*)(smc+B2b); float* b3S=(float*)(smc+B3b);
  if (tid<64){ b1S[tid]=b1[tid]; b2S[tid]=b2[tid]; }
  if (tid<96) b3S[tid]=b3[tid];
  __syncthreads();

  int tt  = wid>>3;
  int w8  = wid&7;
  int r0  = w8*16;
  int arow = r0 + (lane&15);
  int koff = (lane>>4)<<3;
  int b4r  = (lane&7) + ((lane>>4)<<3);
  int b4k  = ((lane>>3)&1)<<3;
  int er = r0+(lane>>2), ec2=(lane&3)*2;
  unsigned xb  = sb + (unsigned)tt*34816u;
  unsigned xlb = sb + 69632u + (unsigned)tt*34816u;

  for (int tp=blockIdx.x; tp<EE/256; tp+=gridDim.x){
    #pragma unroll
    for (int st=0;st<2;st++){
      const float4* xp=(const float4*)(ele+(long long)(2*tp+st)*16384);
      for (int i=tid;i<4096;i+=512){
        float4 v=xp[i];
        int r=(i*4)>>7, c=(i*4)&127;
        unsigned h0,l0,h1,l1;
        split2(v.x,v.y,h0,l0); split2(v.z,v.w,h1,l1);
        unsigned off=(unsigned)(r*LD1+c)*2u;
        *(uint2*)(smc+st*34816+off)=make_uint2(h0,h1);
        *(uint2*)(smc+69632+st*34816+off)=make_uint2(l0,l1);
      }
    }
    __syncthreads();

    // ---- layer 1: K=128, N=64 (X from smem) ----
    float acc[8][4];
    #pragma unroll
    for(int nt=0;nt<8;nt++){acc[nt][0]=0.f;acc[nt][1]=0.f;acc[nt][2]=0.f;acc[nt][3]=0.f;}
    #pragma unroll
    for(int kk=0;kk<8;kk++){
      unsigned ah[4], al[4];
      ldsm4(ah[0],ah[1],ah[2],ah[3], xb +(unsigned)(arow*LD1+kk*16+koff)*2u);
      ldsm4(al[0],al[1],al[2],al[3], xlb+(unsigned)(arow*LD1+kk*16+koff)*2u);
      #pragma unroll
      for(int p=0;p<4;p++){
        unsigned bh[4],bl[4];
        ldsm4(bh[0],bh[1],bh[2],bh[3], sb+W1Hb+(unsigned)((p*16+b4r)*LD1+kk*16+b4k)*2u);
        ldsm4(bl[0],bl[1],bl[2],bl[3], sb+W1Lb+(unsigned)((p*16+b4r)*LD1+kk*16+b4k)*2u);
        mma16816(acc[2*p],   ah, bh);
        mma16816(acc[2*p],   ah, bl);
        mma16816(acc[2*p],   al, bh);
        mma16816(acc[2*p+1], ah, bh+2);
        mma16816(acc[2*p+1], ah, bl+2);
        mma16816(acc[2*p+1], al, bh+2);
      }
    }

    // ---- epi 1 -> register A-fragments for layer 2 ----
    unsigned fh[4][4], fl[4][4];
    #pragma unroll
    for(int nt=0;nt<8;nt++){
      int c=nt*8+ec2;
      float f0=acc[nt][0]+b1S[c], f1=acc[nt][1]+b1S[c+1];
      float f2=acc[nt][2]+b1S[c], f3=acc[nt][3]+b1S[c+1];
      f0*=sig_(f0); f1*=sig_(f1); f2*=sig_(f2); f3*=sig_(f3);
      unsigned h01,l01,h23,l23;
      split2(f0,f1,h01,l01); split2(f2,f3,h23,l23);
      int kkx=nt>>1, o=(nt&1)<<1;
      fh[kkx][o]=h01; fh[kkx][o+1]=h23;
      fl[kkx][o]=l01; fl[kkx][o+1]=l23;
    }

    // ---- layer 2: K=64, N=64 (A in registers) ----
    float acc2[8][4];
    #pragma unroll
    for(int nt=0;nt<8;nt++){acc2[nt][0]=0.f;acc2[nt][1]=0.f;acc2[nt][2]=0.f;acc2[nt][3]=0.f;}
    #pragma unroll
    for(int kk=0;kk<4;kk++){
      #pragma unroll
      for(int p=0;p<4;p++){
        unsigned bh[4],bl[4];
        ldsm4(bh[0],bh[1],bh[2],bh[3], sb+W2Hb+(unsigned)((p*16+b4r)*LD2+kk*16+b4k)*2u);
        ldsm4(bl[0],bl[1],bl[2],bl[3], sb+W2Lb+(unsigned)((p*16+b4r)*LD2+kk*16+b4k)*2u);
        mma16816(acc2[2*p],   fh[kk], bh);
        mma16816(acc2[2*p],   fh[kk], bl);
        mma16816(acc2[2*p],   fl[kk], bh);
        mma16816(acc2[2*p+1], fh[kk], bh+2);
        mma16816(acc2[2*p+1], fh[kk], bl+2);
        mma16816(acc2[2*p+1], fl[kk], bh+2);
      }
    }

    // ---- epi 2 -> register A-fragments for layer 3 ----
    #pragma unroll
    for(int nt=0;nt<8;nt++){
      int c=nt*8+ec2;
      float f0=acc2[nt][0]+b2S[c], f1=acc2[nt][1]+b2S[c+1];
      float f2=acc2[nt][2]+b2S[c], f3=acc2[nt][3]+b2S[c+1];
      f0*=sig_(f0); f1*=sig_(f1); f2*=sig_(f2); f3*=sig_(f3);
      unsigned h01,l01,h23,l23;
      split2(f0,f1,h01,l01); split2(f2,f3,h23,l23);
      int kkx=nt>>1, o=(nt&1)<<1;
      fh[kkx][o]=h01; fh[kkx][o+1]=h23;
      fl[kkx][o]=l01; fl[kkx][o+1]=l23;
    }

    // ---- layer 3: K=64, N=96 (A in registers), store direct to g_wmlp ----
    float a3[12][4];
    #pragma unroll
    for(int nt=0;nt<12;nt++){a3[nt][0]=0.f;a3[nt][1]=0.f;a3[nt][2]=0.f;a3[nt][3]=0.f;}
    #pragma unroll
    for(int kk=0;kk<4;kk++){
      #pragma unroll
      for(int p=0;p<6;p++){
        unsigned bh[4],bl[4];
        ldsm4(bh[0],bh[1],bh[2],bh[3], sb+W3Hb+(unsigned)((p*16+b4r)*LD2+kk*16+b4k)*2u);
        ldsm4(bl[0],bl[1],bl[2],bl[3], sb+W3Lb+(unsigned)((p*16+b4r)*LD2+kk*16+b4k)*2u);
        mma16816(a3[2*p],   fh[kk], bh);
        mma16816(a3[2*p],   fh[kk], bl);
        mma16816(a3[2*p],   fl[kk], bh);
        mma16816(a3[2*p+1], fh[kk], bh+2);
        mma16816(a3[2*p+1], fh[kk], bl+2);
        mma16816(a3[2*p+1], fl[kk], bh+2);
      }
    }
    {
      long long row0 = (long long)(2*tp+tt)*128 + er;
      float* o0 = g_wmlp + row0*96;
      float* o8 = g_wmlp + (row0+8)*96;
      #pragma unroll
      for(int nt=0;nt<12;nt++){
        int c=nt*8+ec2;
        *(float2*)(o0+c) = make_float2(a3[nt][0]+b3S[c], a3[nt][1]+b3S[c+1]);
        *(float2*)(o8+c) = make_float2(a3[nt][2]+b3S[c], a3[nt][3]+b3S[c+1]);
      }
    }
    __syncthreads();
  }
}

// ---------------- HMMA es-GEMV: g_e1 = es @ F1[128:192] (K=64, N=128) ----------------
#define ESXH 0
#define ESXL 18432
#define ESWH 36864
#define ESWL 55296
#define ESTOT 73728

__global__ void __launch_bounds__(256,2) k_es(const float* __restrict__ efea,
   const float* __restrict__ Wss0, const float* __restrict__ Wssg, const float* __restrict__ Wsv1){
  extern __shared__ char smc[];
  unsigned int sb = s2u_(smc);
  int tid=threadIdx.x, wid=tid>>5, lane=tid&31;
  for (int i=tid;i<128*64;i+=256){
    int n=i>>6, k=i&63, l=n>>2, j=n&3;
    float w = (j==0)? Wss0[(k+128)*64+2*l] : (j==1)? Wss0[(k+128)*64+2*l+1]
            : (j==2)? Wssg[(k+128)*32+l]   : Wsv1[(k+128)*32+l];
    __nv_bfloat16 h=__float2bfloat16(w);
    *(__nv_bfloat16*)(smc+ESWH+(n*LD2+k)*2)=h;
    *(__nv_bfloat16*)(smc+ESWL+(n*LD2+k)*2)=__float2bfloat16(w-__bfloat162float(h));
  }
  __syncthreads();

  int r0  = wid*16;
  int arow = r0 + (lane&15);
  int koff = (lane>>4)<<3;
  int b4r  = (lane&7) + ((lane>>4)<<3);
  int b4k  = ((lane>>3)&1)<<3;
  int er = r0+(lane>>2), ec2=(lane&3)*2;

  for (int t=blockIdx.x; t<EE/128; t+=gridDim.x){
    for (int i=tid;i<128*32;i+=256){
      int r=i>>5, c2=i&31;
      float2 v = *(const float2*)(efea + (long long)(t*128+r)*160 + c2*2);
      unsigned h,l; split2(v.x,v.y,h,l);
      unsigned off=(unsigned)(r*LD2+c2*2)*2u;
      *(unsigned*)(smc+ESXH+off)=h;
      *(unsigned*)(smc+ESXL+off)=l;
    }
    __syncthreads();

    float acc[16][4];
    #pragma unroll
    for(int nt=0;nt<16;nt++){acc[nt][0]=0.f;acc[nt][1]=0.f;acc[nt][2]=0.f;acc[nt][3]=0.f;}
    #pragma unroll
    for(int kk=0;kk<4;kk++){
      unsigned ah[4], al[4];
      ldsm4(ah[0],ah[1],ah[2],ah[3], sb+ESXH+(unsigned)(arow*LD2+kk*16+koff)*2u);
      ldsm4(al[0],al[1],al[2],al[3], sb+ESXL+(unsigned)(arow*LD2+kk*16+koff)*2u);
      #pragma unroll
      for(int p=0;p<8;p++){
        unsigned bh[4],bl[4];
        ldsm4(bh[0],bh[1],bh[2],bh[3], sb+ESWH+(unsigned)((p*16+b4r)*LD2+kk*16+b4k)*2u);
        ldsm4(bl[0],bl[1],bl[2],bl[3], sb+ESWL+(unsigned)((p*16+b4r)*LD2+kk*16+b4k)*2u);
        mma16816(acc[2*p],   ah, bh);
        mma16816(acc[2*p],   ah, bl);
        mma16816(acc[2*p],   al, bh);
        mma16816(acc[2*p+1], ah, bh+2);
        mma16816(acc[2*p+1], ah, bl+2);
        mma16816(acc[2*p+1], al, bh+2);
      }
    }
    #pragma unroll
    for(int nt=0;nt<16;nt++){
      int c=nt*8+ec2;
      *(float2*)(g_e1 + (long long)(t*128+er)*128 + c)   = make_float2(acc[nt][0], acc[nt][1]);
      *(float2*)(g_e1 + (long long)(t*128+er+8)*128 + c) = make_float2(acc[nt][2], acc[nt][3]);
    }
    __syncthreads();
  }
}

// ---------------- e12: ev-GEMV + epilogue + scatter, 4 edges/warp ----------------
__global__ void __launch_bounds__(256,3) k_e12(const int* __restrict__ eidx,
   const float* __restrict__ esh, const float* __restrict__ efea,
   const float* __restrict__ Wvv0, const float* __restrict__ Wvvg, const float* __restrict__ Wvs1){
  extern __shared__ float sm[];
  ulonglong2* W2a = (ulonglong2*)sm;
  float* stage = sm + 4096;
  for (int i=threadIdx.x;i<1024;i+=blockDim.x){
    int u=(i>>5)+64, l=i&31;
    float w0=Wvv0[u*64+2*l], w1=Wvv0[u*64+2*l+1];
    float wz=Wvvg[u*32+l],   ww=Wvs1[u*32+l];
    W2a[i] = make_ulonglong2(pkab(w0,w1), pkab(wz,ww));
  }
  __syncthreads();
  int warp=threadIdx.x>>5, lane=threadIdx.x&31, wpb=blockDim.x>>5;
  float* vd  = stage + warp*1040;
  float* shS = vd + 1024;
  const float inv3 = 0.57735027f, invfan = 0.058925565f;
  const int batches = EE/4;
  for (int p = blockIdx.x*wpb+warp; p<batches; p+=gridDim.x*wpb){
    int e0 = p*4;
    int nid[4], njd[4];
    #pragma unroll
    for (int k=0;k<4;k++){
      int e = e0+k;
      nid[k]=eidx[e]; njd[k]=eidx[EE+e];
      float4 sh = *(const float4*)(esh + (long long)e*4);
      if (lane==0) *(float4*)(shS + k*4) = sh;
      const float* r = efea + (long long)e*160;
      float ex=r[64+3*lane], ey=r[65+3*lane], ez=r[66+3*lane];
      float dd=(ex*sh.y+ey*sh.z+ez*sh.w)*inv3;
      float* o = vd + k*256 + lane*8;
      *(float4*)o     = make_float4(dd,dd,ex,ey);
      *(float2*)(o+4) = make_float2(dd,ez);
    }
    __syncwarp();
    unsigned long long b01[4], r01[4], gz2[4];
    #pragma unroll
    for (int k=0;k<4;k++){ b01[k]=0ull; r01[k]=0ull; gz2[k]=0ull; }
    #pragma unroll 4
    for (int u=0;u<32;u++){
      ulonglong2 wa = W2a[u*32+lane];
      float wz,ww; up2(wa.y, wz, ww);
      unsigned long long wb = pk2(ww);
      #pragma unroll
      for (int k=0;k<4;k++){
        ulonglong2 t1 = *(ulonglong2*)(vd + k*256 + u*8);
        unsigned long long t2 = *(unsigned long long*)(vd + k*256 + u*8 + 4);
        fma2(b01[k], t1.x, wa.x);
        fma2(r01[k], t1.y, wb);
        fma2(gz2[k], t2,   wa.y);
      }
    }
    #pragma unroll
    for (int k=0;k<4;k++){
      long long e = e0+k;
      float b0,b1,r0,r1,bg,r2;
      up2(b01[k],b0,b1); up2(r01[k],r0,r1); up2(gz2[k],bg,r2);
      float4 f1v = *(const float4*)(g_e1 + e*128 + lane*4);
      float4 P = *(const float4*)(g_P + nid[k]*128 + lane*4);
      float4 Q = *(const float4*)(g_Q + njd[k]*128 + lane*4);
      float a0=f1v.x+P.x+Q.x, a1=f1v.y+P.y+Q.y, ag=f1v.z+P.z+Q.z, at=f1v.w+P.w+Q.w;
      float4 sh = *(float4*)(shS + k*4);
      const float* tp  = g_T + nid[k]*384 + lane*12;
      const float* upt = g_U + njd[k]*384 + lane*12;
      float4 t0=*(const float4*)tp,  t1=*(const float4*)(tp+4),  t2=*(const float4*)(tp+8);
      float4 u0=*(const float4*)upt, u1=*(const float4*)(upt+4), u2=*(const float4*)(upt+8);
      float s0x=t0.x+u0.x, s0y=t0.y+u0.y, s0z=t0.z+u0.z, s0w=t0.w+u0.w;
      float s1x=t1.x+u1.x, s1y=t1.y+u1.y, s1z=t1.z+u1.z, s1w=t1.w+u1.w;
      float s2x=t2.x+u2.x, s2y=t2.y+u2.y, s2z=t2.z+u2.z, s2w=t2.w+u2.w;
      b0 += inv3*(s0x*sh.y + s0y*sh.z + s0z*sh.w);
      b1 += inv3*(s0w*sh.y + s1x*sh.z + s1y*sh.w);
      bg += inv3*(s1z*sh.y + s1w*sh.z + s2x*sh.w);
      r0 += s2y; r1 += s2z; r2 += s2w;
      float zs0=(sh.x*a0+b0)*invfan, zs1=(sh.x*a1+b1)*invfan;
      float zg =(sh.x*ag+bg)*invfan;
      const float* wm = g_wmlp + e*96;
      float2 wm01 = *(const float2*)(wm+2*lane);
      float wmv = wm[64+lane];
      zs0 = zs0*sig_(zs0)*wm01.x;
      zs1 = zs1*sig_(zs1)*wm01.y;
      float gv = sig_(zg)*wmv*invfan;
      int n = nid[k];
      atomicAdd((float2*)(g_accs + n*64 + 2*lane), make_float2(zs0, zs1));
      atomicAdd(&g_accv4[n*32+lane],
                make_float4((at*sh.y + r0*sh.x)*gv, (at*sh.z + r1*sh.x)*gv,
                            (at*sh.w + r2*sh.x)*gv, 0.f));
    }
    __syncwarp();
  }
}

__global__ void __launch_bounds__(512) k_node_post(const int* __restrict__ batch,
   const float* __restrict__ ppWs, const float* __restrict__ ppbs, const float* __restrict__ ppWv){
  extern __shared__ float sm[];
  float2* WsS = (float2*)sm;
  float* WvS = sm+4096;
  float* bsS = sm+5120;
  float* stage = sm+5184;
  for (int i=threadIdx.x;i<4096;i+=blockDim.x) sm[i]=ppWs[i];
  for (int i=threadIdx.x;i<1024;i+=blockDim.x) WvS[i]=ppWv[i];
  for (int i=threadIdx.x;i<64;i+=blockDim.x) bsS[i]=ppbs[i];
  __syncthreads();
  int warp=threadIdx.x>>5, lane=threadIdx.x&31, wpb=blockDim.x>>5;
  float*  sS  = stage + warp*192;
  float4* vS  = (float4*)(sS+64);
  for (int n=blockIdx.x*wpb+warp; n<NN; n+=gridDim.x*wpb){
    sS[lane]=g_accs[n*64+lane]; sS[32+lane]=g_accs[n*64+32+lane];
    vS[lane]=g_accv4[n*32+lane];
    __syncwarp();
    float a0=0.f,a1=0.f;
    #pragma unroll 4
    for (int u=0;u<64;u++){
      float x=sS[u]; float2 w=WsS[u*32+lane];
      a0+=x*w.x; a1+=x*w.y;
    }
    float ns0 = a0*0.125f + bsS[2*lane]   + g_scs[n*64+2*lane];
    float ns1 = a1*0.125f + bsS[2*lane+1] + g_scs[n*64+2*lane+1];
    g_ns[n*64+2*lane]=ns0; g_ns[n*64+2*lane+1]=ns1;
    float vx=0.f,vy=0.f,vz=0.f;
    #pragma unroll 4
    for (int u=0;u<32;u++){
      float4 x=vS[u]; float w=WvS[u*32+lane];
      vx+=x.x*w; vy+=x.y*w; vz+=x.z*w;
    }
    float nv0 = vx*0.17677670f + g_scv[n*96+3*lane];
    float nv1 = vy*0.17677670f + g_scv[n*96+3*lane+1];
    float nv2 = vz*0.17677670f + g_scv[n*96+3*lane+2];
    g_nv[n*96+3*lane]=nv0; g_nv[n*96+3*lane+1]=nv1; g_nv[n*96+3*lane+2]=nv2;
    float m = ns0+ns1;
    float q = ns0*ns0+ns1*ns1;
    float pw = nv0*nv0+nv1*nv1+nv2*nv2;
    #pragma unroll
    for (int off=16;off>0;off>>=1){
      m += __shfl_down_sync(0xffffffffu, m, off);
      q += __shfl_down_sync(0xffffffffu, q, off);
      pw += __shfl_down_sync(0xffffffffu, pw, off);
    }
    if (lane==0){
      int g = batch[n];
      atomicAdd(&g_gstat[g],        m*(1.f/64.f));
      atomicAdd(&g_gstat[NG_+g],    q*(1.f/64.f));
      atomicAdd(&g_gstat[2*NG_+g],  pw*(1.f/96.f));
      atomicAdd(&g_gstat[3*NG_+g],  1.f);
    }
    __syncwarp();
  }
}

__global__ void k_groups(){
  int t = threadIdx.x;
  if (t < NG_){
    float c  = fmaxf(g_gstat[3*NG_+t], 1.f);
    float mu = g_gstat[t]/c;
    float vs = g_gstat[NG_+t]/c - mu*mu;
    float vv = g_gstat[2*NG_+t]/c;
    g_gout[t]       = mu;
    g_gout[NG_+t]   = rsqrtf(vs+1e-5f);
    g_gout[2*NG_+t] = rsqrtf(vv+1e-5f);
  }
}

__global__ void k_out(const float* __restrict__ nf, const int* __restrict__ batch,
   const float* __restrict__ lnws, const float* __restrict__ lnbs,
   const float* __restrict__ lnwv, float* __restrict__ out){
  int i = blockIdx.x*blockDim.x+threadIdx.x;
  if (i >= NN*160) return;
  int n = i/160, c = i - n*160;
  int g = batch[n];
  float base = nf[i];
  float o;
  if (c < 64){
    float x = (g_ns[n*64+c] - g_gout[g]) * g_gout[NG_+g];
    o = base + x*lnws[c] + lnbs[c];
  } else {
    int cc = c-64;
    o = base + g_nv[n*96+cc]*g_gout[2*NG_+g]*lnwv[cc/3];
  }
  out[i]=o;
}

extern "C" void kernel_launch(void* const* d_in, const int* in_sizes, int n_in,
                              void* d_out, int out_size){
  const float* nf   =(const float*)d_in[0];
  const float* oh   =(const float*)d_in[1];
  const float* esh  =(const float*)d_in[2];
  const float* efea =(const float*)d_in[3];
  const float* ele  =(const float*)d_in[4];
  const int*   eidx =(const int*)d_in[5];
  const int*   batch=(const int*)d_in[6];
  const float* lpWs =(const float*)d_in[7];
  const float* lpbs =(const float*)d_in[8];
  const float* lpWv =(const float*)d_in[9];
  const float* ppWs =(const float*)d_in[10];
  const float* ppbs =(const float*)d_in[11];
  const float* ppWv =(const float*)d_in[12];
  const float* scWs =(const float*)d_in[13];
  const float* scWv =(const float*)d_in[14];
  const float* Wss0 =(const float*)d_in[15];
  const float* Wvv0 =(const float*)d_in[16];
  const float* Wssg =(const float*)d_in[17];
  const float* Wvvg =(const float*)d_in[18];
  const float* Wsv1 =(const float*)d_in[19];
  const float* Wvs1 =(const float*)d_in[20];
  const float* fcW1 =(const float*)d_in[21];
  const float* fcb1 =(const float*)d_in[22];
  const float* fcW2 =(const float*)d_in[23];
  const float* fcb2 =(const float*)d_in[24];
  const float* fcW3 =(const float*)d_in[25];
  const float* fcb3 =(const float*)d_in[26];
  const float* lnws =(const float*)d_in[27];
  const float* lnbs =(const float*)d_in[28];
  const float* lnwv =(const float*)d_in[29];
  float* out = (float*)d_out;

  const int SM_PRE  = (25664 + 16*192)*4;
  const int SM_PSTV = (24576 + 16*1024)*4;
  const int SM_E12  = (4096  + 8*1040)*4;
  const int SM_POST = (5184  + 16*192)*4;
  cudaFuncSetAttribute(k_node_pre,  cudaFuncAttributeMaxDynamicSharedMemorySize, SM_PRE);
  cudaFuncSetAttribute(k_pstv,      cudaFuncAttributeMaxDynamicSharedMemorySize, SM_PSTV);
  cudaFuncSetAttribute(k_mlp_hmma,  cudaFuncAttributeMaxDynamicSharedMemorySize, MBTOT);
  cudaFuncSetAttribute(k_es,        cudaFuncAttributeMaxDynamicSharedMemorySize, ESTOT);
  cudaFuncSetAttribute(k_e12,       cudaFuncAttributeMaxDynamicSharedMemorySize, SM_E12);
  cudaFuncSetAttribute(k_node_post, cudaFuncAttributeMaxDynamicSharedMemorySize, SM_POST);

  k_zero<<<(NN*192 + 4*NG_ + 255)/256, 256>>>();
  k_node_pre<<<148, 512, SM_PRE>>>(nf, oh, lpWs, lpbs, lpWv, scWs, scWv);
  k_pstv<<<148, 512, SM_PSTV>>>(Wss0, Wssg, Wsv1, Wvv0, Wvvg, Wvs1);
  k_mlp_hmma<<<148, 512, MBTOT>>>(ele, fcW1, fcb1, fcW2, fcb2, fcW3, fcb3);
  k_es<<<296, 256, ESTOT>>>(efea, Wss0, Wssg, Wsv1);
  k_e12<<<444, 256, SM_E12>>>(eidx, esh, efea, Wvv0, Wvvg, Wvs1);
  k_node_post<<<148, 512, SM_POST>>>(batch, ppWs, ppbs, ppWv);
  k_groups<<<1, 32>>>();
  k_out<<<(NN*160 + 255)/256, 256>>>(nf, batch, lnws, lnbs, lnwv, out);
}

// round 17
// speedup vs baseline: 1.4941x; 1.0919x over previous
#include <cuda_runtime.h>
#include <cuda_bf16.h>
#include <cstdint>

#define NN 10000
#define EE 320000
#define NG_ 16

__device__ float  g_s[NN*64];
__device__ float4 g_v4[NN*32];
__device__ float  g_scs[NN*64];
__device__ float  g_scv[NN*96];
__device__ float  g_accs[NN*64];
__device__ float4 g_accv4[NN*32];
__device__ float  g_ns[NN*64];
__device__ float  g_nv[NN*96];
__device__ float  g_wmlp[(long long)EE*96];
__device__ float  g_e1[(long long)EE*128];
__device__ float  g_P[NN*128];
__device__ float  g_Q[NN*128];
__device__ float  g_T[NN*384];
__device__ float  g_U[NN*384];
__device__ float  g_gstat[4*NG_];
__device__ float  g_gout[3*NG_];

__device__ __forceinline__ float sig_(float x){ return 1.f/(1.f+__expf(-x)); }
__device__ __forceinline__ unsigned long long pk2(float x){
  unsigned long long r; asm("mov.b64 %0, {%1, %1};" : "=l"(r) : "f"(x)); return r; }
__device__ __forceinline__ unsigned long long pkab(float a, float b){
  unsigned long long r; asm("mov.b64 %0, {%1, %2};" : "=l"(r) : "f"(a), "f"(b)); return r; }
__device__ __forceinline__ void up2(unsigned long long v, float &a, float &b){
  asm("mov.b64 {%0, %1}, %2;" : "=f"(a), "=f"(b) : "l"(v)); }
__device__ __forceinline__ void fma2(unsigned long long &d, unsigned long long a, unsigned long long b){
  asm("fma.rn.f32x2 %0, %1, %2, %3;" : "=l"(d) : "l"(a), "l"(b), "l"(d)); }
__device__ __forceinline__ unsigned int s2u_(const void* p){
  unsigned int a; asm("{ .reg .u64 t; cvta.to.shared.u64 t, %1; cvt.u32.u64 %0, t; }" : "=r"(a) : "l"(p)); return a; }

__device__ __forceinline__ void ldsm4(unsigned &r0,unsigned &r1,unsigned &r2,unsigned &r3, unsigned a){
  asm volatile("ldmatrix.sync.aligned.m8n8.x4.shared.b16 {%0,%1,%2,%3}, [%4];"
    : "=r"(r0),"=r"(r1),"=r"(r2),"=r"(r3) : "r"(a)); }
__device__ __forceinline__ void mma16816(float* c, const unsigned* a, const unsigned* b){
  asm volatile("mma.sync.aligned.m16n8k16.row.col.f32.bf16.bf16.f32 "
    "{%0,%1,%2,%3}, {%4,%5,%6,%7}, {%8,%9}, {%0,%1,%2,%3};"
    : "+f"(c[0]),"+f"(c[1]),"+f"(c[2]),"+f"(c[3])
    : "r"(a[0]),"r"(a[1]),"r"(a[2]),"r"(a[3]), "r"(b[0]),"r"(b[1])); }
__device__ __forceinline__ void split2(float a, float b, unsigned &h, unsigned &l){
  __nv_bfloat16 ha=__float2bfloat16(a), hb=__float2bfloat16(b);
  float la=a-__bfloat162float(ha), lb=b-__bfloat162float(hb);
  __nv_bfloat162 hh=__halves2bfloat162(ha,hb);
  __nv_bfloat162 ll=__halves2bfloat162(__float2bfloat16(la),__float2bfloat16(lb));
  h=*(unsigned*)&hh; l=*(unsigned*)&ll; }

__global__ void k_zero(){
  int i = blockIdx.x*blockDim.x + threadIdx.x;
  if (i < NN*64) g_accs[i] = 0.f;
  int j = i - NN*64;
  if (j >= 0 && j < NN*128) ((float*)g_accv4)[j] = 0.f;
  int k = i - NN*192;
  if (k >= 0 && k < 4*NG_) g_gstat[k] = 0.f;
}

__global__ void __launch_bounds__(512) k_node_pre(const float* __restrict__ nf,
   const float* __restrict__ oh, const float* __restrict__ lpWs, const float* __restrict__ lpbs,
   const float* __restrict__ lpWv, const float* __restrict__ scWs, const float* __restrict__ scWv){
  extern __shared__ float sm[];
  float2* WsS  = (float2*)sm;
  float*  WvS  = sm + 4096;
  float2* sWsS = (float2*)(sm + 5120);
  float*  sWvS = sm + 21504;
  float*  bsS  = sm + 25600;
  float*  stage= sm + 25664;
  for (int i=threadIdx.x;i<4096;i+=blockDim.x) sm[i]=lpWs[i];
  for (int i=threadIdx.x;i<1024;i+=blockDim.x) WvS[i]=lpWv[i];
  for (int i=threadIdx.x;i<16384;i+=blockDim.x) sm[5120+i]=scWs[i];
  for (int i=threadIdx.x;i<4096;i+=blockDim.x) sWvS[i]=scWv[i];
  for (int i=threadIdx.x;i<64;i+=blockDim.x) bsS[i]=lpbs[i];
  __syncthreads();
  int warp = threadIdx.x>>5, lane = threadIdx.x&31, wpb = blockDim.x>>5;
  float*  sS  = stage + warp*192;
  float4* vS  = (float4*)(sS + 64);
  for (int n = blockIdx.x*wpb + warp; n < NN; n += gridDim.x*wpb){
    const float* row = nf + n*160;
    sS[lane] = row[lane]; sS[32+lane] = row[32+lane];
    vS[lane] = make_float4(row[64+3*lane], row[65+3*lane], row[66+3*lane], 0.f);
    const float* o4 = oh + n*4;
    int sp = (o4[1]>0.5f)?1:((o4[2]>0.5f)?2:((o4[3]>0.5f)?3:0));
    __syncwarp();
    float a0=0.f,a1=0.f,c0=0.f,c1=0.f;
    #pragma unroll 4
    for (int u=0;u<64;u++){
      float x = sS[u];
      float2 w  = WsS[u*32+lane];
      float2 w2 = sWsS[(u*4+sp)*32+lane];
      a0+=x*w.x; a1+=x*w.y; c0+=x*w2.x; c1+=x*w2.y;
    }
    g_s[n*64+2*lane]   = a0*0.125f + bsS[2*lane];
    g_s[n*64+2*lane+1] = a1*0.125f + bsS[2*lane+1];
    g_scs[n*64+2*lane]   = c0*0.0625f;
    g_scs[n*64+2*lane+1] = c1*0.0625f;
    float vx=0.f,vy=0.f,vz=0.f,cx=0.f,cy=0.f,cz=0.f;
    #pragma unroll 4
    for (int u=0;u<32;u++){
      float4 x = vS[u];
      float w  = WvS[u*32+lane];
      float w2 = sWvS[(u*4+sp)*32+lane];
      vx+=x.x*w;  vy+=x.y*w;  vz+=x.z*w;
      cx+=x.x*w2; cy+=x.y*w2; cz+=x.z*w2;
    }
    g_v4[n*32+lane] = make_float4(vx*0.17677670f, vy*0.17677670f, vz*0.17677670f, 0.f);
    g_scv[n*96+3*lane]   = cx*0.08838835f;
    g_scv[n*96+3*lane+1] = cy*0.08838835f;
    g_scv[n*96+3*lane+2] = cz*0.08838835f;
    __syncwarp();
  }
}

__global__ void __launch_bounds__(512) k_pstv(const float* __restrict__ Wss0,
   const float* __restrict__ Wssg, const float* __restrict__ Wsv1,
   const float* __restrict__ Wvv0, const float* __restrict__ Wvvg, const float* __restrict__ Wvs1){
  extern __shared__ float sm[];
  float4* FA = (float4*)sm;
  float4* FB = (float4*)(sm+8192);
  float4* GA = (float4*)(sm+16384);
  float4* GB = (float4*)(sm+20480);
  float* stage = sm + 24576;
  for (int i=threadIdx.x;i<2048;i+=blockDim.x){
    int u=i>>5, l=i&31;
    FA[i]=make_float4(Wss0[u*64+2*l], Wss0[u*64+2*l+1], Wssg[u*32+l], Wsv1[u*32+l]);
    int u2=u+64;
    FB[i]=make_float4(Wss0[u2*64+2*l], Wss0[u2*64+2*l+1], Wssg[u2*32+l], Wsv1[u2*32+l]);
  }
  for (int i=threadIdx.x;i<1024;i+=blockDim.x){
    int u=i>>5, l=i&31;
    GA[i]=make_float4(Wvv0[u*64+2*l], Wvv0[u*64+2*l+1], Wvvg[u*32+l], Wvs1[u*32+l]);
    int u2=u+32;
    GB[i]=make_float4(Wvv0[u2*64+2*l], Wvv0[u2*64+2*l+1], Wvvg[u2*32+l], Wvs1[u2*32+l]);
  }
  __syncthreads();
  int warp=threadIdx.x>>5, lane=threadIdx.x&31, wpb=blockDim.x>>5;
  float* sd = stage + warp*1024;
  const int b1 = NN/8;
  for (int p = blockIdx.x*wpb+warp; p<b1; p+=gridDim.x*wpb){
    int n0 = p*8;
    #pragma unroll
    for (int k=0;k<8;k++){
      int n = n0+k;
      float x0 = g_s[n*64+lane];
      float x1 = g_s[n*64+32+lane];
      *(unsigned long long*)(sd + k*128 + 2*lane)      = pkab(x0,x0);
      *(unsigned long long*)(sd + k*128 + 64 + 2*lane) = pkab(x1,x1);
    }
    __syncwarp();
    unsigned long long pa[8], pg[8], qa[8], qg[8];
    #pragma unroll
    for (int k=0;k<8;k++){ pa[k]=0ull; pg[k]=0ull; qa[k]=0ull; qg[k]=0ull; }
    #pragma unroll 2
    for (int u=0;u<64;u+=2){
      ulonglong2 wa0 = *(ulonglong2*)&FA[(u  )*32+lane];
      ulonglong2 wa1 = *(ulonglong2*)&FA[(u+1)*32+lane];
      ulonglong2 wb0 = *(ulonglong2*)&FB[(u  )*32+lane];
      ulonglong2 wb1 = *(ulonglong2*)&FB[(u+1)*32+lane];
      #pragma unroll
      for (int k=0;k<8;k++){
        ulonglong2 xp = *(ulonglong2*)(sd + k*128 + 2*u);
        fma2(pa[k], xp.x, wa0.x); fma2(pg[k], xp.x, wa0.y);
        fma2(qa[k], xp.x, wb0.x); fma2(qg[k], xp.x, wb0.y);
        fma2(pa[k], xp.y, wa1.x); fma2(pg[k], xp.y, wa1.y);
        fma2(qa[k], xp.y, wb1.x); fma2(qg[k], xp.y, wb1.y);
      }
    }
    #pragma unroll
    for (int k=0;k<8;k++){
      int n = n0+k;
      float a0,a1,ag,at;
      up2(pa[k],a0,a1); up2(pg[k],ag,at);
      *(float4*)(g_P + n*128 + lane*4) = make_float4(a0,a1,ag,at);
      up2(qa[k],a0,a1); up2(qg[k],ag,at);
      *(float4*)(g_Q + n*128 + lane*4) = make_float4(a0,a1,ag,at);
    }
    __syncwarp();
  }
  float4* vst = (float4*)sd;
  const int b2 = NN/4;
  for (int p = blockIdx.x*wpb+warp; p<b2; p+=gridDim.x*wpb){
    int n0 = p*4;
    #pragma unroll
    for (int k=0;k<4;k++) vst[k*32+lane] = g_v4[(n0+k)*32+lane];
    __syncwarp();
    unsigned long long t01[4][3], tgr[4][3], u01[4][3], ugr[4][3];
    #pragma unroll
    for (int k=0;k<4;k++)
      #pragma unroll
      for (int c=0;c<3;c++){ t01[k][c]=0ull; tgr[k][c]=0ull; u01[k][c]=0ull; ugr[k][c]=0ull; }
    #pragma unroll 2
    for (int u=0;u<32;u++){
      ulonglong2 ga = *(ulonglong2*)&GA[u*32+lane];
      ulonglong2 gb = *(ulonglong2*)&GB[u*32+lane];
      #pragma unroll
      for (int k=0;k<4;k++){
        float4 v = vst[k*32+u];
        unsigned long long vx=pk2(v.x), vy=pk2(v.y), vz=pk2(v.z);
        fma2(t01[k][0], vx, ga.x); fma2(t01[k][1], vy, ga.x); fma2(t01[k][2], vz, ga.x);
        fma2(tgr[k][0], vx, ga.y); fma2(tgr[k][1], vy, ga.y); fma2(tgr[k][2], vz, ga.y);
        fma2(u01[k][0], vx, gb.x); fma2(u01[k][1], vy, gb.x); fma2(u01[k][2], vz, gb.x);
        fma2(ugr[k][0], vx, gb.y); fma2(ugr[k][1], vy, gb.y); fma2(ugr[k][2], vz, gb.y);
      }
    }
    #pragma unroll
    for (int k=0;k<4;k++){
      int n = n0+k;
      float b0x,b1x,b0y,b1y,b0z,b1z,bgx,rx,bgy,ry,bgz,rz;
      up2(t01[k][0],b0x,b1x); up2(t01[k][1],b0y,b1y); up2(t01[k][2],b0z,b1z);
      up2(tgr[k][0],bgx,rx);  up2(tgr[k][1],bgy,ry);  up2(tgr[k][2],bgz,rz);
      float* o = g_T + n*384 + lane*12;
      *(float4*)(o  ) = make_float4(b0x,b0y,b0z,b1x);
      *(float4*)(o+4) = make_float4(b1y,b1z,bgx,bgy);
      *(float4*)(o+8) = make_float4(bgz,rx,ry,rz);
      up2(u01[k][0],b0x,b1x); up2(u01[k][1],b0y,b1y); up2(u01[k][2],b0z,b1z);
      up2(ugr[k][0],bgx,rx);  up2(ugr[k][1],bgy,ry);  up2(ugr[k][2],bgz,rz);
      o = g_U + n*384 + lane*12;
      *(float4*)(o  ) = make_float4(b0x,b0y,b0z,b1x);
      *(float4*)(o+4) = make_float4(b1y,b1z,bgx,bgy);
      *(float4*)(o+8) = make_float4(bgz,rx,ry,rz);
    }
    __syncwarp();
  }
}

// ---------------- HMMA MLP: weights-only SMEM, layer-1 A direct from gmem, 0 loop syncs ----------------
#define LD1 136
#define LD2 72
#define MW1H 0
#define MW1L 17408
#define MW2H 34816
#define MW2L 44032
#define MW3H 53248
#define MW3L 67072
#define MB1  80896
#define MB2  81152
#define MB3  81408
#define MLPTOT 81792

__global__ void __launch_bounds__(256,2) k_mlp_hmma(const float* __restrict__ ele,
   const float* __restrict__ W1, const float* __restrict__ b1,
   const float* __restrict__ W2, const float* __restrict__ b2,
   const float* __restrict__ W3, const float* __restrict__ b3){
  extern __shared__ char smc[];
  unsigned int sb = s2u_(smc);
  int tid=threadIdx.x, wid=tid>>5, lane=tid&31;
  for (int i=tid;i<64*128;i+=256){
    int n=i>>7,k=i&127; float w=W1[k*64+n];
    __nv_bfloat16 h=__float2bfloat16(w);
    *(__nv_bfloat16*)(smc+MW1H+(n*LD1+k)*2)=h;
    *(__nv_bfloat16*)(smc+MW1L+(n*LD1+k)*2)=__float2bfloat16(w-__bfloat162float(h));
  }
  for (int i=tid;i<64*64;i+=256){
    int n=i>>6,k=i&63; float w=W2[k*64+n];
    __nv_bfloat16 h=__float2bfloat16(w);
    *(__nv_bfloat16*)(smc+MW2H+(n*LD2+k)*2)=h;
    *(__nv_bfloat16*)(smc+MW2L+(n*LD2+k)*2)=__float2bfloat16(w-__bfloat162float(h));
  }
  for (int i=tid;i<96*64;i+=256){
    int n=i>>6,k=i&63; float w=W3[k*96+n];
    __nv_bfloat16 h=__float2bfloat16(w);
    *(__nv_bfloat16*)(smc+MW3H+(n*LD2+k)*2)=h;
    *(__nv_bfloat16*)(smc+MW3L+(n*LD2+k)*2)=__float2bfloat16(w-__bfloat162float(h));
  }
  float* b1S=(float*)(smc+MB1); float* b2S=(float*)(smc+MB2); float* b3S=(float*)(smc+MB3);
  if (tid<64){ b1S[tid]=b1[tid]; b2S[tid]=b2[tid]; }
  if (tid<96) b3S[tid]=b3[tid];
  __syncthreads();

  int r0  = wid*16;
  int b4r  = (lane&7) + ((lane>>4)<<3);
  int b4k  = ((lane>>3)&1)<<3;
  int er = r0+(lane>>2), ec2=(lane&3)*2;

  for (int t=blockIdx.x; t<EE/128; t+=gridDim.x){
    // ---- layer 1: K=128, N=64; A fragments direct from gmem ----
    const float* xA = ele + (long long)t*16384 + (r0+(lane>>2))*128 + 2*(lane&3);
    float acc[8][4];
    #pragma unroll
    for(int nt=0;nt<8;nt++){acc[nt][0]=0.f;acc[nt][1]=0.f;acc[nt][2]=0.f;acc[nt][3]=0.f;}
    #pragma unroll
    for(int kk=0;kk<8;kk++){
      float2 v0 = *(const float2*)(xA + kk*16);
      float2 v1 = *(const float2*)(xA + 1024 + kk*16);
      float2 v2 = *(const float2*)(xA + kk*16 + 8);
      float2 v3 = *(const float2*)(xA + 1024 + kk*16 + 8);
      unsigned ah[4], al[4];
      split2(v0.x,v0.y,ah[0],al[0]);
      split2(v1.x,v1.y,ah[1],al[1]);
      split2(v2.x,v2.y,ah[2],al[2]);
      split2(v3.x,v3.y,ah[3],al[3]);
      #pragma unroll
      for(int p=0;p<4;p++){
        unsigned bh[4],bl[4];
        ldsm4(bh[0],bh[1],bh[2],bh[3], sb+MW1H+(unsigned)((p*16+b4r)*LD1+kk*16+b4k)*2u);
        ldsm4(bl[0],bl[1],bl[2],bl[3], sb+MW1L+(unsigned)((p*16+b4r)*LD1+kk*16+b4k)*2u);
        mma16816(acc[2*p],   ah, bh);
        mma16816(acc[2*p],   ah, bl);
        mma16816(acc[2*p],   al, bh);
        mma16816(acc[2*p+1], ah, bh+2);
        mma16816(acc[2*p+1], ah, bl+2);
        mma16816(acc[2*p+1], al, bh+2);
      }
    }

    // ---- epi 1 -> register A-fragments for layer 2 ----
    unsigned fh[4][4], fl[4][4];
    #pragma unroll
    for(int nt=0;nt<8;nt++){
      int c=nt*8+ec2;
      float f0=acc[nt][0]+b1S[c], f1=acc[nt][1]+b1S[c+1];
      float f2=acc[nt][2]+b1S[c], f3=acc[nt][3]+b1S[c+1];
      f0*=sig_(f0); f1*=sig_(f1); f2*=sig_(f2); f3*=sig_(f3);
      unsigned h01,l01,h23,l23;
      split2(f0,f1,h01,l01); split2(f2,f3,h23,l23);
      int kkx=nt>>1, o=(nt&1)<<1;
      fh[kkx][o]=h01; fh[kkx][o+1]=h23;
      fl[kkx][o]=l01; fl[kkx][o+1]=l23;
    }

    // ---- layer 2: K=64, N=64 (A in registers) ----
    #pragma unroll
    for(int nt=0;nt<8;nt++){acc[nt][0]=0.f;acc[nt][1]=0.f;acc[nt][2]=0.f;acc[nt][3]=0.f;}
    #pragma unroll
    for(int kk=0;kk<4;kk++){
      #pragma unroll
      for(int p=0;p<4;p++){
        unsigned bh[4],bl[4];
        ldsm4(bh[0],bh[1],bh[2],bh[3], sb+MW2H+(unsigned)((p*16+b4r)*LD2+kk*16+b4k)*2u);
        ldsm4(bl[0],bl[1],bl[2],bl[3], sb+MW2L+(unsigned)((p*16+b4r)*LD2+kk*16+b4k)*2u);
        mma16816(acc[2*p],   fh[kk], bh);
        mma16816(acc[2*p],   fh[kk], bl);
        mma16816(acc[2*p],   fl[kk], bh);
        mma16816(acc[2*p+1], fh[kk], bh+2);
        mma16816(acc[2*p+1], fh[kk], bl+2);
        mma16816(acc[2*p+1], fl[kk], bh+2);
      }
    }

    // ---- epi 2 -> register A-fragments for layer 3 ----
    #pragma unroll
    for(int nt=0;nt<8;nt++){
      int c=nt*8+ec2;
      float f0=acc[nt][0]+b2S[c], f1=acc[nt][1]+b2S[c+1];
      float f2=acc[nt][2]+b2S[c], f3=acc[nt][3]+b2S[c+1];
      f0*=sig_(f0); f1*=sig_(f1); f2*=sig_(f2); f3*=sig_(f3);
      unsigned h01,l01,h23,l23;
      split2(f0,f1,h01,l01); split2(f2,f3,h23,l23);
      int kkx=nt>>1, o=(nt&1)<<1;
      fh[kkx][o]=h01; fh[kkx][o+1]=h23;
      fl[kkx][o]=l01; fl[kkx][o+1]=l23;
    }

    // ---- layer 3: K=64, N=96 (A in registers), store direct to g_wmlp ----
    float a3[12][4];
    #pragma unroll
    for(int nt=0;nt<12;nt++){a3[nt][0]=0.f;a3[nt][1]=0.f;a3[nt][2]=0.f;a3[nt][3]=0.f;}
    #pragma unroll
    for(int kk=0;kk<4;kk++){
      #pragma unroll
      for(int p=0;p<6;p++){
        unsigned bh[4],bl[4];
        ldsm4(bh[0],bh[1],bh[2],bh[3], sb+MW3H+(unsigned)((p*16+b4r)*LD2+kk*16+b4k)*2u);
        ldsm4(bl[0],bl[1],bl[2],bl[3], sb+MW3L+(unsigned)((p*16+b4r)*LD2+kk*16+b4k)*2u);
        mma16816(a3[2*p],   fh[kk], bh);
        mma16816(a3[2*p],   fh[kk], bl);
        mma16816(a3[2*p],   fl[kk], bh);
        mma16816(a3[2*p+1], fh[kk], bh+2);
        mma16816(a3[2*p+1], fh[kk], bl+2);
        mma16816(a3[2*p+1], fl[kk], bh+2);
      }
    }
    {
      long long row0 = (long long)t*128 + er;
      float* o0 = g_wmlp + row0*96;
      float* o8 = g_wmlp + (row0+8)*96;
      #pragma unroll
      for(int nt=0;nt<12;nt++){
        int c=nt*8+ec2;
        *(float2*)(o0+c) = make_float2(a3[nt][0]+b3S[c], a3[nt][1]+b3S[c+1]);
        *(float2*)(o8+c) = make_float2(a3[nt][2]+b3S[c], a3[nt][3]+b3S[c+1]);
      }
    }
  }
}

// ---------------- HMMA es-GEMV: g_e1 = es @ F1[128:192] (K=64, N=128) ----------------
#define ESXH 0
#define ESXL 18432
#define ESWH 36864
#define ESWL 55296
#define ESTOT 73728

__global__ void __launch_bounds__(256,2) k_es(const float* __restrict__ efea,
   const float* __restrict__ Wss0, const float* __restrict__ Wssg, const float* __restrict__ Wsv1){
  extern __shared__ char smc[];
  unsigned int sb = s2u_(smc);
  int tid=threadIdx.x, wid=tid>>5, lane=tid&31;
  for (int i=tid;i<128*64;i+=256){
    int n=i>>6, k=i&63, l=n>>2, j=n&3;
    float w = (j==0)? Wss0[(k+128)*64+2*l] : (j==1)? Wss0[(k+128)*64+2*l+1]
            : (j==2)? Wssg[(k+128)*32+l]   : Wsv1[(k+128)*32+l];
    __nv_bfloat16 h=__float2bfloat16(w);
    *(__nv_bfloat16*)(smc+ESWH+(n*LD2+k)*2)=h;
    *(__nv_bfloat16*)(smc+ESWL+(n*LD2+k)*2)=__float2bfloat16(w-__bfloat162float(h));
  }
  __syncthreads();

  int r0  = wid*16;
  int arow = r0 + (lane&15);
  int koff = (lane>>4)<<3;
  int b4r  = (lane&7) + ((lane>>4)<<3);
  int b4k  = ((lane>>3)&1)<<3;
  int er = r0+(lane>>2), ec2=(lane&3)*2;

  for (int t=blockIdx.x; t<EE/128; t+=gridDim.x){
    for (int i=tid;i<128*32;i+=256){
      int r=i>>5, c2=i&31;
      float2 v = *(const float2*)(efea + (long long)(t*128+r)*160 + c2*2);
      unsigned h,l; split2(v.x,v.y,h,l);
      unsigned off=(unsigned)(r*LD2+c2*2)*2u;
      *(unsigned*)(smc+ESXH+off)=h;
      *(unsigned*)(smc+ESXL+off)=l;
    }
    __syncthreads();

    float acc[16][4];
    #pragma unroll
    for(int nt=0;nt<16;nt++){acc[nt][0]=0.f;acc[nt][1]=0.f;acc[nt][2]=0.f;acc[nt][3]=0.f;}
    #pragma unroll
    for(int kk=0;kk<4;kk++){
      unsigned ah[4], al[4];
      ldsm4(ah[0],ah[1],ah[2],ah[3], sb+ESXH+(unsigned)(arow*LD2+kk*16+koff)*2u);
      ldsm4(al[0],al[1],al[2],al[3], sb+ESXL+(unsigned)(arow*LD2+kk*16+koff)*2u);
      #pragma unroll
      for(int p=0;p<8;p++){
        unsigned bh[4],bl[4];
        ldsm4(bh[0],bh[1],bh[2],bh[3], sb+ESWH+(unsigned)((p*16+b4r)*LD2+kk*16+b4k)*2u);
        ldsm4(bl[0],bl[1],bl[2],bl[3], sb+ESWL+(unsigned)((p*16+b4r)*LD2+kk*16+b4k)*2u);
        mma16816(acc[2*p],   ah, bh);
        mma16816(acc[2*p],   ah, bl);
        mma16816(acc[2*p],   al, bh);
        mma16816(acc[2*p+1], ah, bh+2);
        mma16816(acc[2*p+1], ah, bl+2);
        mma16816(acc[2*p+1], al, bh+2);
      }
    }
    #pragma unroll
    for(int nt=0;nt<16;nt++){
      int c=nt*8+ec2;
      *(float2*)(g_e1 + (long long)(t*128+er)*128 + c)   = make_float2(acc[nt][0], acc[nt][1]);
      *(float2*)(g_e1 + (long long)(t*128+er+8)*128 + c) = make_float2(acc[nt][2], acc[nt][3]);
    }
    __syncthreads();
  }
}

// ---------------- e12: ev-GEMV + epilogue + scatter, 4 edges/warp ----------------
__global__ void __launch_bounds__(256,3) k_e12(const int* __restrict__ eidx,
   const float* __restrict__ esh, const float* __restrict__ efea,
   const float* __restrict__ Wvv0, const float* __restrict__ Wvvg, const float* __restrict__ Wvs1){
  extern __shared__ float sm[];
  ulonglong2* W2a = (ulonglong2*)sm;
  float* stage = sm + 4096;
  for (int i=threadIdx.x;i<1024;i+=blockDim.x){
    int u=(i>>5)+64, l=i&31;
    float w0=Wvv0[u*64+2*l], w1=Wvv0[u*64+2*l+1];
    float wz=Wvvg[u*32+l],   ww=Wvs1[u*32+l];
    W2a[i] = make_ulonglong2(pkab(w0,w1), pkab(wz,ww));
  }
  __syncthreads();
  int warp=threadIdx.x>>5, lane=threadIdx.x&31, wpb=blockDim.x>>5;
  float* vd  = stage + warp*1040;
  float* shS = vd + 1024;
  const float inv3 = 0.57735027f, invfan = 0.058925565f;
  const int batches = EE/4;
  for (int p = blockIdx.x*wpb+warp; p<batches; p+=gridDim.x*wpb){
    int e0 = p*4;
    int nid[4], njd[4];
    #pragma unroll
    for (int k=0;k<4;k++){
      int e = e0+k;
      nid[k]=eidx[e]; njd[k]=eidx[EE+e];
      float4 sh = *(const float4*)(esh + (long long)e*4);
      if (lane==0) *(float4*)(shS + k*4) = sh;
      const float* r = efea + (long long)e*160;
      float ex=r[64+3*lane], ey=r[65+3*lane], ez=r[66+3*lane];
      float dd=(ex*sh.y+ey*sh.z+ez*sh.w)*inv3;
      float* o = vd + k*256 + lane*8;
      *(float4*)o     = make_float4(dd,dd,ex,ey);
      *(float2*)(o+4) = make_float2(dd,ez);
    }
    __syncwarp();
    unsigned long long b01[4], r01[4], gz2[4];
    #pragma unroll
    for (int k=0;k<4;k++){ b01[k]=0ull; r01[k]=0ull; gz2[k]=0ull; }
    #pragma unroll 4
    for (int u=0;u<32;u++){
      ulonglong2 wa = W2a[u*32+lane];
      float wz,ww; up2(wa.y, wz, ww);
      unsigned long long wb = pk2(ww);
      #pragma unroll
      for (int k=0;k<4;k++){
        ulonglong2 t1 = *(ulonglong2*)(vd + k*256 + u*8);
        unsigned long long t2 = *(unsigned long long*)(vd + k*256 + u*8 + 4);
        fma2(b01[k], t1.x, wa.x);
        fma2(r01[k], t1.y, wb);
        fma2(gz2[k], t2,   wa.y);
      }
    }
    #pragma unroll
    for (int k=0;k<4;k++){
      long long e = e0+k;
      float b0,b1,r0,r1,bg,r2;
      up2(b01[k],b0,b1); up2(r01[k],r0,r1); up2(gz2[k],bg,r2);
      float4 f1v = *(const float4*)(g_e1 + e*128 + lane*4);
      float4 P = *(const float4*)(g_P + nid[k]*128 + lane*4);
      float4 Q = *(const float4*)(g_Q + njd[k]*128 + lane*4);
      float a0=f1v.x+P.x+Q.x, a1=f1v.y+P.y+Q.y, ag=f1v.z+P.z+Q.z, at=f1v.w+P.w+Q.w;
      float4 sh = *(float4*)(shS + k*4);
      const float* tp  = g_T + nid[k]*384 + lane*12;
      const float* upt = g_U + njd[k]*384 + lane*12;
      float4 t0=*(const float4*)tp,  t1=*(const float4*)(tp+4),  t2=*(const float4*)(tp+8);
      float4 u0=*(const float4*)upt, u1=*(const float4*)(upt+4), u2=*(const float4*)(upt+8);
      float s0x=t0.x+u0.x, s0y=t0.y+u0.y, s0z=t0.z+u0.z, s0w=t0.w+u0.w;
      float s1x=t1.x+u1.x, s1y=t1.y+u1.y, s1z=t1.z+u1.z, s1w=t1.w+u1.w;
      float s2x=t2.x+u2.x, s2y=t2.y+u2.y, s2z=t2.z+u2.z, s2w=t2.w+u2.w;
      b0 += inv3*(s0x*sh.y + s0y*sh.z + s0z*sh.w);
      b1 += inv3*(s0w*sh.y + s1x*sh.z + s1y*sh.w);
      bg += inv3*(s1z*sh.y + s1w*sh.z + s2x*sh.w);
      r0 += s2y; r1 += s2z; r2 += s2w;
      float zs0=(sh.x*a0+b0)*invfan, zs1=(sh.x*a1+b1)*invfan;
      float zg =(sh.x*ag+bg)*invfan;
      const float* wm = g_wmlp + e*96;
      float2 wm01 = *(const float2*)(wm+2*lane);
      float wmv = wm[64+lane];
      zs0 = zs0*sig_(zs0)*wm01.x;
      zs1 = zs1*sig_(zs1)*wm01.y;
      float gv = sig_(zg)*wmv*invfan;
      int n = nid[k];
      atomicAdd((float2*)(g_accs + n*64 + 2*lane), make_float2(zs0, zs1));
      atomicAdd(&g_accv4[n*32+lane],
                make_float4((at*sh.y + r0*sh.x)*gv, (at*sh.z + r1*sh.x)*gv,
                            (at*sh.w + r2*sh.x)*gv, 0.f));
    }
    __syncwarp();
  }
}

__global__ void __launch_bounds__(512) k_node_post(const int* __restrict__ batch,
   const float* __restrict__ ppWs, const float* __restrict__ ppbs, const float* __restrict__ ppWv){
  extern __shared__ float sm[];
  float2* WsS = (float2*)sm;
  float* WvS = sm+4096;
  float* bsS = sm+5120;
  float* stage = sm+5184;
  for (int i=threadIdx.x;i<4096;i+=blockDim.x) sm[i]=ppWs[i];
  for (int i=threadIdx.x;i<1024;i+=blockDim.x) WvS[i]=ppWv[i];
  for (int i=threadIdx.x;i<64;i+=blockDim.x) bsS[i]=ppbs[i];
  __syncthreads();
  int warp=threadIdx.x>>5, lane=threadIdx.x&31, wpb=blockDim.x>>5;
  float*  sS  = stage + warp*192;
  float4* vS  = (float4*)(sS+64);
  for (int n=blockIdx.x*wpb+warp; n<NN; n+=gridDim.x*wpb){
    sS[lane]=g_accs[n*64+lane]; sS[32+lane]=g_accs[n*64+32+lane];
    vS[lane]=g_accv4[n*32+lane];
    __syncwarp();
    float a0=0.f,a1=0.f;
    #pragma unroll 4
    for (int u=0;u<64;u++){
      float x=sS[u]; float2 w=WsS[u*32+lane];
      a0+=x*w.x; a1+=x*w.y;
    }
    float ns0 = a0*0.125f + bsS[2*lane]   + g_scs[n*64+2*lane];
    float ns1 = a1*0.125f + bsS[2*lane+1] + g_scs[n*64+2*lane+1];
    g_ns[n*64+2*lane]=ns0; g_ns[n*64+2*lane+1]=ns1;
    float vx=0.f,vy=0.f,vz=0.f;
    #pragma unroll 4
    for (int u=0;u<32;u++){
      float4 x=vS[u]; float w=WvS[u*32+lane];
      vx+=x.x*w; vy+=x.y*w; vz+=x.z*w;
    }
    float nv0 = vx*0.17677670f + g_scv[n*96+3*lane];
    float nv1 = vy*0.17677670f + g_scv[n*96+3*lane+1];
    float nv2 = vz*0.17677670f + g_scv[n*96+3*lane+2];
    g_nv[n*96+3*lane]=nv0; g_nv[n*96+3*lane+1]=nv1; g_nv[n*96+3*lane+2]=nv2;
    float m = ns0+ns1;
    float q = ns0*ns0+ns1*ns1;
    float pw = nv0*nv0+nv1*nv1+nv2*nv2;
    #pragma unroll
    for (int off=16;off>0;off>>=1){
      m += __shfl_down_sync(0xffffffffu, m, off);
      q += __shfl_down_sync(0xffffffffu, q, off);
      pw += __shfl_down_sync(0xffffffffu, pw, off);
    }
    if (lane==0){
      int g = batch[n];
      atomicAdd(&g_gstat[g],        m*(1.f/64.f));
      atomicAdd(&g_gstat[NG_+g],    q*(1.f/64.f));
      atomicAdd(&g_gstat[2*NG_+g],  pw*(1.f/96.f));
      atomicAdd(&g_gstat[3*NG_+g],  1.f);
    }
    __syncwarp();
  }
}

__global__ void k_groups(){
  int t = threadIdx.x;
  if (t < NG_){
    float c  = fmaxf(g_gstat[3*NG_+t], 1.f);
    float mu = g_gstat[t]/c;
    float vs = g_gstat[NG_+t]/c - mu*mu;
    float vv = g_gstat[2*NG_+t]/c;
    g_gout[t]       = mu;
    g_gout[NG_+t]   = rsqrtf(vs+1e-5f);
    g_gout[2*NG_+t] = rsqrtf(vv+1e-5f);
  }
}

__global__ void k_out(const float* __restrict__ nf, const int* __restrict__ batch,
   const float* __restrict__ lnws, const float* __restrict__ lnbs,
   const float* __restrict__ lnwv, float* __restrict__ out){
  int i = blockIdx.x*blockDim.x+threadIdx.x;
  if (i >= NN*160) return;
  int n = i/160, c = i - n*160;
  int g = batch[n];
  float base = nf[i];
  float o;
  if (c < 64){
    float x = (g_ns[n*64+c] - g_gout[g]) * g_gout[NG_+g];
    o = base + x*lnws[c] + lnbs[c];
  } else {
    int cc = c-64;
    o = base + g_nv[n*96+cc]*g_gout[2*NG_+g]*lnwv[cc/3];
  }
  out[i]=o;
}

extern "C" void kernel_launch(void* const* d_in, const int* in_sizes, int n_in,
                              void* d_out, int out_size){
  const float* nf   =(const float*)d_in[0];
  const float* oh   =(const float*)d_in[1];
  const float* esh  =(const float*)d_in[2];
  const float* efea =(const float*)d_in[3];
  const float* ele  =(const float*)d_in[4];
  const int*   eidx =(const int*)d_in[5];
  const int*   batch=(const int*)d_in[6];
  const float* lpWs =(const float*)d_in[7];
  const float* lpbs =(const float*)d_in[8];
  const float* lpWv =(const float*)d_in[9];
  const float* ppWs =(const float*)d_in[10];
  const float* ppbs =(const float*)d_in[11];
  const float* ppWv =(const float*)d_in[12];
  const float* scWs =(const float*)d_in[13];
  const float* scWv =(const float*)d_in[14];
  const float* Wss0 =(const float*)d_in[15];
  const float* Wvv0 =(const float*)d_in[16];
  const float* Wssg =(const float*)d_in[17];
  const float* Wvvg =(const float*)d_in[18];
  const float* Wsv1 =(const float*)d_in[19];
  const float* Wvs1 =(const float*)d_in[20];
  const float* fcW1 =(const float*)d_in[21];
  const float* fcb1 =(const float*)d_in[22];
  const float* fcW2 =(const float*)d_in[23];
  const float* fcb2 =(const float*)d_in[24];
  const float* fcW3 =(const float*)d_in[25];
  const float* fcb3 =(const float*)d_in[26];
  const float* lnws =(const float*)d_in[27];
  const float* lnbs =(const float*)d_in[28];
  const float* lnwv =(const float*)d_in[29];
  float* out = (float*)d_out;

  const int SM_PRE  = (25664 + 16*192)*4;
  const int SM_PSTV = (24576 + 16*1024)*4;
  const int SM_E12  = (4096  + 8*1040)*4;
  const int SM_POST = (5184  + 16*192)*4;
  cudaFuncSetAttribute(k_node_pre,  cudaFuncAttributeMaxDynamicSharedMemorySize, SM_PRE);
  cudaFuncSetAttribute(k_pstv,      cudaFuncAttributeMaxDynamicSharedMemorySize, SM_PSTV);
  cudaFuncSetAttribute(k_mlp_hmma,  cudaFuncAttributeMaxDynamicSharedMemorySize, MLPTOT);
  cudaFuncSetAttribute(k_es,        cudaFuncAttributeMaxDynamicSharedMemorySize, ESTOT);
  cudaFuncSetAttribute(k_e12,       cudaFuncAttributeMaxDynamicSharedMemorySize, SM_E12);
  cudaFuncSetAttribute(k_node_post, cudaFuncAttributeMaxDynamicSharedMemorySize, SM_POST);

  k_zero<<<(NN*192 + 4*NG_ + 255)/256, 256>>>();
  k_node_pre<<<148, 512, SM_PRE>>>(nf, oh, lpWs, lpbs, lpWv, scWs, scWv);
  k_pstv<<<148, 512, SM_PSTV>>>(Wss0, Wssg, Wsv1, Wvv0, Wvvg, Wvs1);
  k_mlp_hmma<<<296, 256, MLPTOT>>>(ele, fcW1, fcb1, fcW2, fcb2, fcW3, fcb3);
  k_es<<<296, 256, ESTOT>>>(efea, Wss0, Wssg, Wsv1);
  k_e12<<<444, 256, SM_E12>>>(eidx, esh, efea, Wvv0, Wvvg, Wvs1);
  k_node_post<<<148, 512, SM_POST>>>(batch, ppWs, ppbs, ppWv);
  k_groups<<<1, 32>>>();
  k_out<<<(NN*160 + 255)/256, 256>>>(nf, batch, lnws, lnbs, lnwv, out);
}